// round 11
// baseline (speedup 1.0000x reference)
#include <cuda_runtime.h>
#include <cuda_bf16.h>
#include <cuda_fp16.h>
#include <math.h>
#include <float.h>
#include <stdint.h>

// ---------------- problem dims ----------------
#define NB   2048
#define VV   50000
#define E1   1024
#define E2   512
#define CC   2
#define KK   200
#define EMB  300

#define KP   50048
#define KPW  (KP/2)
#define G1NT (KP / 32)

#define KR   224
#define KRW  (KR/2)
#define RNT  (KR / 32)
#define BTROWS 50048

// ---------------- float scratch ----------------------------------------------
#define OFF_EN1    0LL
#define OFF_EN2    (OFF_EN1 + (long long)NB*E1)
#define OFF_PM     (OFF_EN2 + (long long)NB*E2)
#define OFF_LV     (OFF_PM + (long long)NB*CC)
#define OFF_Z      (OFF_LV + (long long)NB*CC)
#define OFF_ZX     (OFF_Z + (long long)NB*CC)
#define OFF_ZC     (OFF_ZX + (long long)NB*CC)
#define OFF_THETA  (OFF_ZC + (long long)KK*CC)
#define OFF_MU1    (OFF_THETA + (long long)NB*KK)
#define OFF_MU2    (OFF_MU1 + (long long)KK*100)
#define OFF_MUZ    (OFF_MU2 + (long long)KK*100)
#define OFF_LOGITS (OFF_MUZ + (long long)KK*EMB)
#define OFF_BETA   (OFF_LOGITS + (long long)KK*VV)
#define OFF_SPM    (OFF_BETA + (long long)KK*VV)
#define OFF_SLV    (OFF_SPM + 4)
#define OFF_SZ     (OFF_SLV + 4)
#define OFF_ST     (OFF_SZ + 4)
#define SCRATCH_FLOATS (OFF_ST + 8)

__device__ float g_scratch[SCRATCH_FLOATS];

// ---------------- fp16 planes (words) ----------------------------------------
#define WA 51249152LL
#define WB 25624576LL
#define W_AH 0LL
#define W_BH (W_AH + WA)
#define W_TH (W_BH + WB)
#define TWH  ((long long)NB * KRW)
#define W_BT (W_TH + TWH)
#define BTWH ((long long)BTROWS * KRW)

__device__ __align__(16) uint32_t g_bf[WA + WB + TWH + BTWH];

__device__ __forceinline__ float softplusf(float x) {
    return fmaxf(x, 0.0f) + log1pf(expf(-fabsf(x)));
}

__device__ __forceinline__ uint32_t pk_h2(__half lo, __half hi) {
    return ((uint32_t)__half_as_ushort(hi) << 16) | __half_as_ushort(lo);
}

__device__ __forceinline__ uint32_t pk_bf16(float lo, float hi) {
    uint32_t r;
    asm("cvt.rn.bf16x2.f32 %0, %1, %2;" : "=r"(r) : "f"(hi), "f"(lo));
    return r;
}

__device__ __forceinline__ void mma_f16(float* d,
                                        uint32_t a0, uint32_t a1, uint32_t a2, uint32_t a3,
                                        uint32_t b0, uint32_t b1)
{
    asm volatile(
        "mma.sync.aligned.m16n8k16.row.col.f32.f16.f16.f32 "
        "{%0,%1,%2,%3},{%4,%5,%6,%7},{%8,%9},{%0,%1,%2,%3};"
        : "+f"(d[0]), "+f"(d[1]), "+f"(d[2]), "+f"(d[3])
        : "r"(a0), "r"(a1), "r"(a2), "r"(a3), "r"(b0), "r"(b1));
}

__device__ __forceinline__ void mma_bf16(float* d,
                                         uint32_t a0, uint32_t a1, uint32_t a2, uint32_t a3,
                                         uint32_t b0, uint32_t b1)
{
    asm volatile(
        "mma.sync.aligned.m16n8k16.row.col.f32.bf16.bf16.f32 "
        "{%0,%1,%2,%3},{%4,%5,%6,%7},{%8,%9},{%0,%1,%2,%3};"
        : "+f"(d[0]), "+f"(d[1]), "+f"(d[2]), "+f"(d[3])
        : "r"(a0), "r"(a1), "r"(a2), "r"(a3), "r"(b0), "r"(b1));
}

__device__ __forceinline__ void ldsm_x4(uint32_t& r0, uint32_t& r1, uint32_t& r2,
                                        uint32_t& r3, uint32_t addr)
{
    asm volatile("ldmatrix.sync.aligned.m8n8.x4.shared.b16 {%0,%1,%2,%3}, [%4];"
                 : "=r"(r0), "=r"(r1), "=r"(r2), "=r"(r3) : "r"(addr));
}

// =============================================================================
// Pre-pass: A=input, B=en1_W -> fp16 planes, zero pad.
// =============================================================================
__global__ void __launch_bounds__(256)
split_fp16(const float* __restrict__ A, const float* __restrict__ B)
{
    const int b = blockIdx.x, tid = threadIdx.x;
    const float* src;
    uint32_t* h;
    if (b < NB) {
        src = A + (size_t)b * VV;
        h = g_bf + W_AH + (size_t)b * KPW;
    } else {
        int r = b - NB;
        src = B + (size_t)r * VV;
        h = g_bf + W_BH + (size_t)r * KPW;
    }
    for (int i = tid; i < VV / 4; i += 256) {
        float4 v = *reinterpret_cast<const float4*>(src + i * 4);
        h[2*i]     = pk_h2(__float2half_rn(v.x), __float2half_rn(v.y));
        h[2*i + 1] = pk_h2(__float2half_rn(v.z), __float2half_rn(v.w));
    }
    if (tid < KPW - VV/2) h[VV/2 + tid] = 0u;
}

// =============================================================================
// GEMM1: en1 = softplus(input @ en1_W^T + b), plain fp16.
// =============================================================================
#define STG    20480
#define G1_SMEM (3 * STG)

__global__ void __launch_bounds__(256, 2)
gemm1_fp16(const float* __restrict__ bias, float* __restrict__ C)
{
    extern __shared__ __align__(16) char sm[];
    const uint32_t sb32 = (uint32_t)__cvta_generic_to_shared(sm);
    const int tid = threadIdx.x;
    const int lane = tid & 31, warp = tid >> 5;
    const int gid = lane >> 2, tig = lane & 3;
    const int wm = warp >> 1, wn = warp & 1;
    const int m0 = blockIdx.y * 128, n0 = blockIdx.x * 128;

    float acc[2][8][4];
#pragma unroll
    for (int i = 0; i < 2; i++)
#pragma unroll
        for (int j = 0; j < 8; j++)
#pragma unroll
            for (int l = 0; l < 4; l++) acc[i][j][l] = 0.0f;

    const uint32_t* gsrc[4];
    uint32_t sdst[4];
#pragma unroll
    for (int i = 0; i < 2; i++) {
        int idx = tid + i * 256;
        int r = idx >> 2, part = idx & 3;
        gsrc[i] = g_bf + W_AH + (size_t)(m0 + r) * KPW + part * 4;
        sdst[i] = sb32 + (uint32_t)(r * 80 + part * 16);
    }
#pragma unroll
    for (int i = 0; i < 2; i++) {
        int idx = tid + i * 256;
        int r = idx >> 2, part = idx & 3;
        gsrc[2 + i] = g_bf + W_BH + (size_t)(n0 + r) * KPW + part * 4;
        sdst[2 + i] = sb32 + (uint32_t)(10240 + r * 80 + part * 16);
    }

    auto issue = [&](int t) {
        const uint32_t boff = (uint32_t)(t % 3) * STG;
        const size_t k = (size_t)t * 16;
#pragma unroll
        for (int i = 0; i < 4; i++)
            asm volatile("cp.async.cg.shared.global [%0], [%1], 16;"
                         :: "r"(sdst[i] + boff), "l"(gsrc[i] + k) : "memory");
        asm volatile("cp.async.commit_group;" ::: "memory");
    };

    const int lr = (lane & 7) + ((lane >> 3) & 1) * 8;
    const int kb = ((lane >> 4) & 1) * 16;
    const uint32_t aoff = (uint32_t)((wm * 32 + lr) * 80 + kb);
    const uint32_t boff2 = (uint32_t)(10240 + (wn * 64 + lr) * 80 + kb);

    issue(0);
    issue(1);

    for (int t = 0; t < G1NT; t++) {
        if (t == G1NT - 1) asm volatile("cp.async.wait_group 0;" ::: "memory");
        else               asm volatile("cp.async.wait_group 1;" ::: "memory");
        __syncthreads();
        if (t + 2 < G1NT) issue(t + 2);

        const uint32_t st = sb32 + (uint32_t)(t % 3) * STG;
#pragma unroll
        for (int kkw = 0; kkw < 2; kkw++) {
            const uint32_t ka = st + kkw * 32;
            uint32_t ah[2][4], bq[4][4];
#pragma unroll
            for (int ms = 0; ms < 2; ms++)
                ldsm_x4(ah[ms][0], ah[ms][1], ah[ms][2], ah[ms][3],
                        ka + aoff + ms * 1280);
#pragma unroll
            for (int pr = 0; pr < 4; pr++)
                ldsm_x4(bq[pr][0], bq[pr][1], bq[pr][2], bq[pr][3],
                        ka + boff2 + pr * 1280);
#pragma unroll
            for (int ms = 0; ms < 2; ms++)
#pragma unroll
                for (int pr = 0; pr < 4; pr++)
#pragma unroll
                    for (int j = 0; j < 2; j++) {
                        int ns = pr * 2 + j;
                        mma_f16(acc[ms][ns], ah[ms][0], ah[ms][1], ah[ms][2], ah[ms][3],
                                bq[pr][j], bq[pr][j + 2]);
                    }
        }
    }

#pragma unroll
    for (int ms = 0; ms < 2; ms++) {
        const int r0 = m0 + wm * 32 + ms * 16 + gid;
#pragma unroll
        for (int ns = 0; ns < 8; ns++) {
            const int c0 = n0 + wn * 64 + ns * 8 + 2 * tig;
            const float bv0 = bias[c0], bv1 = bias[c0 + 1];
            C[(size_t)r0 * E1 + c0]           = softplusf(acc[ms][ns][0] + bv0);
            C[(size_t)r0 * E1 + c0 + 1]       = softplusf(acc[ms][ns][1] + bv1);
            C[(size_t)(r0 + 8) * E1 + c0]     = softplusf(acc[ms][ns][2] + bv0);
            C[(size_t)(r0 + 8) * E1 + c0 + 1] = softplusf(acc[ms][ns][3] + bv1);
        }
    }
}

// =============================================================================
// recon = theta @ beta via NT fp16 from theta/beta^T planes.
// =============================================================================
__global__ void __launch_bounds__(256, 2)
recon_f16(float* __restrict__ C)
{
    extern __shared__ __align__(16) char sm[];
    const uint32_t sb32 = (uint32_t)__cvta_generic_to_shared(sm);
    const int tid = threadIdx.x;
    const int lane = tid & 31, warp = tid >> 5;
    const int gid = lane >> 2, tig = lane & 3;
    const int wm = warp >> 1, wn = warp & 1;
    const int m0 = blockIdx.y * 128, n0 = blockIdx.x * 128;

    float acc[2][8][4];
#pragma unroll
    for (int i = 0; i < 2; i++)
#pragma unroll
        for (int j = 0; j < 8; j++)
#pragma unroll
            for (int l = 0; l < 4; l++) acc[i][j][l] = 0.0f;

    const uint32_t* gsrc[4];
    uint32_t sdst[4];
#pragma unroll
    for (int i = 0; i < 2; i++) {
        int idx = tid + i * 256;
        int r = idx >> 2, part = idx & 3;
        gsrc[i] = g_bf + W_TH + (size_t)(m0 + r) * KRW + part * 4;
        sdst[i] = sb32 + (uint32_t)(r * 80 + part * 16);
    }
#pragma unroll
    for (int i = 0; i < 2; i++) {
        int idx = tid + i * 256;
        int r = idx >> 2, part = idx & 3;
        gsrc[2 + i] = g_bf + W_BT + (size_t)(n0 + r) * KRW + part * 4;
        sdst[2 + i] = sb32 + (uint32_t)(10240 + r * 80 + part * 16);
    }

    auto issue = [&](int t) {
        const uint32_t boff = (uint32_t)(t % 3) * STG;
        const size_t k = (size_t)t * 16;
#pragma unroll
        for (int i = 0; i < 4; i++)
            asm volatile("cp.async.cg.shared.global [%0], [%1], 16;"
                         :: "r"(sdst[i] + boff), "l"(gsrc[i] + k) : "memory");
        asm volatile("cp.async.commit_group;" ::: "memory");
    };

    const int lr = (lane & 7) + ((lane >> 3) & 1) * 8;
    const int kb = ((lane >> 4) & 1) * 16;
    const uint32_t aoff = (uint32_t)((wm * 32 + lr) * 80 + kb);
    const uint32_t boff2 = (uint32_t)(10240 + (wn * 64 + lr) * 80 + kb);

    issue(0);
    issue(1);

    for (int t = 0; t < RNT; t++) {
        if (t == RNT - 1) asm volatile("cp.async.wait_group 0;" ::: "memory");
        else              asm volatile("cp.async.wait_group 1;" ::: "memory");
        __syncthreads();
        if (t + 2 < RNT) issue(t + 2);

        const uint32_t st = sb32 + (uint32_t)(t % 3) * STG;
#pragma unroll
        for (int kkw = 0; kkw < 2; kkw++) {
            const uint32_t ka = st + kkw * 32;
            uint32_t ah[2][4], bq[4][4];
#pragma unroll
            for (int ms = 0; ms < 2; ms++)
                ldsm_x4(ah[ms][0], ah[ms][1], ah[ms][2], ah[ms][3],
                        ka + aoff + ms * 1280);
#pragma unroll
            for (int pr = 0; pr < 4; pr++)
                ldsm_x4(bq[pr][0], bq[pr][1], bq[pr][2], bq[pr][3],
                        ka + boff2 + pr * 1280);
#pragma unroll
            for (int ms = 0; ms < 2; ms++)
#pragma unroll
                for (int pr = 0; pr < 4; pr++)
#pragma unroll
                    for (int j = 0; j < 2; j++) {
                        int ns = pr * 2 + j;
                        mma_f16(acc[ms][ns], ah[ms][0], ah[ms][1], ah[ms][2], ah[ms][3],
                                bq[pr][j], bq[pr][j + 2]);
                    }
        }
    }

#pragma unroll
    for (int ms = 0; ms < 2; ms++) {
        const int r0 = m0 + wm * 32 + ms * 16 + gid;
#pragma unroll
        for (int ns = 0; ns < 8; ns++) {
            const int c0 = n0 + wn * 64 + ns * 8 + 2 * tig;
            if (c0 < VV) {
                C[(size_t)r0 * VV + c0]       = acc[ms][ns][0];
                C[(size_t)(r0 + 8) * VV + c0] = acc[ms][ns][2];
            }
            if (c0 + 1 < VV) {
                C[(size_t)r0 * VV + c0 + 1]       = acc[ms][ns][1];
                C[(size_t)(r0 + 8) * VV + c0 + 1] = acc[ms][ns][3];
            }
        }
    }
}

// =============================================================================
// beta^T fp16
// =============================================================================
__global__ void __launch_bounds__(256)
transpose_beta(const float* __restrict__ beta)
{
    __shared__ float s[32][33];
    const int tid = threadIdx.x;
    const int tx = tid & 31, ty = tid >> 5;
    const int v0 = blockIdx.x * 32, k0 = blockIdx.y * 32;

#pragma unroll
    for (int i = 0; i < 4; i++) {
        int k = ty + i * 8;
        int gk = k0 + k, gv = v0 + tx;
        float val = 0.f;
        if (gk < KK && gv < VV) val = beta[(size_t)gk * VV + gv];
        s[k][tx] = val;
    }
    __syncthreads();

#pragma unroll
    for (int i = 0; i < 2; i++) {
        int w = tid + i * 256;
        int v = w >> 4, kw = w & 15;
        uint32_t word = pk_h2(__float2half_rn(s[2 * kw][v]),
                              __float2half_rn(s[2 * kw + 1][v]));
        g_bf[W_BT + (size_t)(v0 + v) * KRW + (k0 >> 1) + kw] = word;
    }
}

// ============================ bf16x3 NT GEMM (en2 + logits) ==================
#define NTB_SMEM (2 * 10240 * 4)

template<bool SP, bool HB, bool CHKMN>
__global__ void __launch_bounds__(512, 1)
gemm_nt_bf16x3(const float* __restrict__ A, const float* __restrict__ B,
               const float* __restrict__ bias, float* __restrict__ C,
               int M, int N, int K)
{
    extern __shared__ __align__(16) uint32_t sw[];
    const int tid = threadIdx.x;
    const int lane = tid & 31, warp = tid >> 5;
    const int gid = lane >> 2, tig = lane & 3;
    const int wm = warp >> 2, wn = warp & 3;
    const int m0 = blockIdx.y * 128, n0 = blockIdx.x * 128;
    const int nt = (K + 31) / 32;

    float acc[2][4][4];
#pragma unroll
    for (int i = 0; i < 2; i++)
#pragma unroll
        for (int j = 0; j < 4; j++)
#pragma unroll
            for (int l = 0; l < 4; l++) acc[i][j][l] = 0.0f;

    const int srow = tid >> 3;
    const int sq   = tid & 7;
    float4 stA[2], stB[2];

    auto load_tile = [&](int t) {
        const int gk = t * 32 + sq * 4;
#pragma unroll
        for (int l = 0; l < 2; l++) {
            int r = srow + l * 64;
            {
                int gm = m0 + r;
                float4 v = make_float4(0.f, 0.f, 0.f, 0.f);
                if (((!CHKMN) || gm < M)) {
                    if (gk + 3 < K) v = *reinterpret_cast<const float4*>(A + (size_t)gm * K + gk);
                    else if (gk < K) {
                        const float* p = A + (size_t)gm * K;
                        v.x = p[gk];
                        if (gk + 1 < K) v.y = p[gk + 1];
                        if (gk + 2 < K) v.z = p[gk + 2];
                    }
                }
                stA[l] = v;
            }
            {
                int gn = n0 + r;
                float4 v = make_float4(0.f, 0.f, 0.f, 0.f);
                if (((!CHKMN) || gn < N)) {
                    if (gk + 3 < K) v = *reinterpret_cast<const float4*>(B + (size_t)gn * K + gk);
                    else if (gk < K) {
                        const float* p = B + (size_t)gn * K;
                        v.x = p[gk];
                        if (gk + 1 < K) v.y = p[gk + 1];
                        if (gk + 2 < K) v.z = p[gk + 2];
                    }
                }
                stB[l] = v;
            }
        }
    };

    auto store_tile = [&](uint32_t* buf) {
#pragma unroll
        for (int l = 0; l < 2; l++) {
            int r = srow + l * 64;
            uint32_t w = (uint32_t)(r * 20 + sq * 2);
            {
                float4 v = stA[l];
                __nv_bfloat16 hx = __float2bfloat16_rn(v.x), hy = __float2bfloat16_rn(v.y);
                __nv_bfloat16 hz = __float2bfloat16_rn(v.z), hw = __float2bfloat16_rn(v.w);
                buf[w]     = ((uint32_t)__bfloat16_as_ushort(hy) << 16) | __bfloat16_as_ushort(hx);
                buf[w + 1] = ((uint32_t)__bfloat16_as_ushort(hw) << 16) | __bfloat16_as_ushort(hz);
                buf[w + 2560]     = pk_bf16(v.x - __bfloat162float(hx), v.y - __bfloat162float(hy));
                buf[w + 2560 + 1] = pk_bf16(v.z - __bfloat162float(hz), v.w - __bfloat162float(hw));
            }
            {
                float4 v = stB[l];
                __nv_bfloat16 hx = __float2bfloat16_rn(v.x), hy = __float2bfloat16_rn(v.y);
                __nv_bfloat16 hz = __float2bfloat16_rn(v.z), hw = __float2bfloat16_rn(v.w);
                buf[w + 5120]     = ((uint32_t)__bfloat16_as_ushort(hy) << 16) | __bfloat16_as_ushort(hx);
                buf[w + 5120 + 1] = ((uint32_t)__bfloat16_as_ushort(hw) << 16) | __bfloat16_as_ushort(hz);
                buf[w + 7680]     = pk_bf16(v.x - __bfloat162float(hx), v.y - __bfloat162float(hy));
                buf[w + 7680 + 1] = pk_bf16(v.z - __bfloat162float(hz), v.w - __bfloat162float(hw));
            }
        }
    };

    load_tile(0);
    store_tile(sw);
    __syncthreads();

    for (int t = 0; t < nt; t++) {
        const int b = t & 1;
        uint32_t* bb = sw + b * 10240;
        if (t + 1 < nt) load_tile(t + 1);

#pragma unroll
        for (int kkw = 0; kkw < 16; kkw += 8) {
            uint32_t ah[2][4], al[2][4], bh[4][2], bl[4][2];
#pragma unroll
            for (int ms = 0; ms < 2; ms++) {
                int base = (wm * 32 + ms * 16 + gid) * 20 + kkw + tig;
                ah[ms][0] = bb[base];       ah[ms][1] = bb[base + 160];
                ah[ms][2] = bb[base + 4];   ah[ms][3] = bb[base + 164];
                al[ms][0] = bb[base + 2560];       al[ms][1] = bb[base + 2560 + 160];
                al[ms][2] = bb[base + 2560 + 4];   al[ms][3] = bb[base + 2560 + 164];
            }
#pragma unroll
            for (int ns = 0; ns < 4; ns++) {
                int base = 5120 + (wn * 32 + ns * 8 + gid) * 20 + kkw + tig;
                bh[ns][0] = bb[base];       bh[ns][1] = bb[base + 4];
                bl[ns][0] = bb[base + 2560]; bl[ns][1] = bb[base + 2560 + 4];
            }
#pragma unroll
            for (int ms = 0; ms < 2; ms++)
#pragma unroll
                for (int ns = 0; ns < 4; ns++) {
                    mma_bf16(acc[ms][ns], ah[ms][0], ah[ms][1], ah[ms][2], ah[ms][3],
                             bh[ns][0], bh[ns][1]);
                    mma_bf16(acc[ms][ns], ah[ms][0], ah[ms][1], ah[ms][2], ah[ms][3],
                             bl[ns][0], bl[ns][1]);
                    mma_bf16(acc[ms][ns], al[ms][0], al[ms][1], al[ms][2], al[ms][3],
                             bh[ns][0], bh[ns][1]);
                }
        }

        if (t + 1 < nt) store_tile(sw + (b ^ 1) * 10240);
        __syncthreads();
    }

#pragma unroll
    for (int ms = 0; ms < 2; ms++) {
        int r0 = m0 + wm * 32 + ms * 16 + gid;
#pragma unroll
        for (int ns = 0; ns < 4; ns++) {
            int c0 = n0 + wn * 32 + ns * 8 + 2 * tig;
            float bv0 = 0.f, bv1 = 0.f;
            if (HB) { bv0 = bias[c0]; bv1 = bias[c0 + 1]; }
            float v00 = acc[ms][ns][0] + bv0;
            float v01 = acc[ms][ns][1] + bv1;
            float v10 = acc[ms][ns][2] + bv0;
            float v11 = acc[ms][ns][3] + bv1;
            if (SP) { v00 = softplusf(v00); v01 = softplusf(v01);
                      v10 = softplusf(v10); v11 = softplusf(v11); }
            if (!CHKMN) {
                C[(size_t)r0 * N + c0]           = v00;
                C[(size_t)r0 * N + c0 + 1]       = v01;
                C[(size_t)(r0 + 8) * N + c0]     = v10;
                C[(size_t)(r0 + 8) * N + c0 + 1] = v11;
            } else {
                if (r0 < M) {
                    if (c0 < N)     C[(size_t)r0 * N + c0]     = v00;
                    if (c0 + 1 < N) C[(size_t)r0 * N + c0 + 1] = v01;
                }
                if (r0 + 8 < M) {
                    if (c0 < N)     C[(size_t)(r0 + 8) * N + c0]     = v10;
                    if (c0 + 1 < N) C[(size_t)(r0 + 8) * N + c0 + 1] = v11;
                }
            }
        }
    }
}

// ---------------- mean / logvar heads ---------------------------------------
__global__ void meanlogvar_kernel(const float* __restrict__ en2,
                                  const float* __restrict__ mW, const float* __restrict__ mb,
                                  const float* __restrict__ lW, const float* __restrict__ lb,
                                  float* __restrict__ pm, float* __restrict__ lv)
{
    int t = blockIdx.x * blockDim.x + threadIdx.x;
    if (t >= NB * 4) return;
    int n = t >> 2, j = t & 3;
    const float* w = (j < 2) ? (mW + j * E2) : (lW + (j - 2) * E2);
    const float* x = en2 + (size_t)n * E2;
    float s = 0.f;
    for (int i = 0; i < E2; i += 4) {
        float4 xa = *reinterpret_cast<const float4*>(x + i);
        float4 wa = *reinterpret_cast<const float4*>(w + i);
        s += xa.x * wa.x + xa.y * wa.y + xa.z * wa.z + xa.w * wa.w;
    }
    if (j < 2) pm[n * 2 + j] = s + mb[j];
    else       lv[n * 2 + (j - 2)] = s + lb[j - 2];
}

// ---------------- column stats of (R x 2) -----------------------------------
__global__ void colstats_kernel(const float* __restrict__ X, int R, float* __restrict__ out)
{
    __shared__ float ss[256], s2[256];
    int c = blockIdx.x, tid = threadIdx.x;
    float s = 0.f, q = 0.f;
    for (int r = tid; r < R; r += 256) {
        float x = X[r * 2 + c];
        s += x; q += x * x;
    }
    ss[tid] = s; s2[tid] = q;
    __syncthreads();
    for (int st = 128; st > 0; st >>= 1) {
        if (tid < st) { ss[tid] += ss[tid + st]; s2[tid] += s2[tid + st]; }
        __syncthreads();
    }
    if (tid == 0) {
        float m = ss[0] / R;
        out[c] = m;
        out[2 + c] = s2[0] / R - m * m;
    }
}

// ---------------- z ----------------------------------------------------------
__global__ void z_kernel(const float* __restrict__ pm, const float* __restrict__ lv,
                         const float* __restrict__ spm, const float* __restrict__ slv,
                         const float* __restrict__ gm, const float* __restrict__ bm,
                         const float* __restrict__ gl, const float* __restrict__ bl,
                         const float* __restrict__ eps,
                         float* __restrict__ gz, float* __restrict__ outz)
{
    int idx = blockIdx.x * 256 + threadIdx.x;
    if (idx >= NB * CC) return;
    int c = idx & 1;
    float pmb = gm[c] * (pm[idx] - spm[c]) * rsqrtf(spm[2 + c] + 1e-5f) + bm[c];
    float lvb = gl[c] * (lv[idx] - slv[c]) * rsqrtf(slv[2 + c] + 1e-5f) + bl[c];
    float z = pmb + sqrtf(expf(lvb)) * eps[idx];
    gz[idx] = z;
    outz[idx] = z;
}

// ---------------- BN apply ---------------------------------------------------
__global__ void bn_apply_kernel(const float* __restrict__ X, const float* __restrict__ stats,
                                const float* __restrict__ g, const float* __restrict__ b,
                                int total, float* __restrict__ o1, float* __restrict__ o2)
{
    int idx = blockIdx.x * 256 + threadIdx.x;
    if (idx >= total) return;
    int c = idx & 1;
    float y = g[c] * (X[idx] - stats[c]) * rsqrtf(stats[2 + c] + 1e-5f) + b[c];
    o1[idx] = y;
    o2[idx] = y;
}

// ---------------- theta (fp32 outputs + fp16 plane) --------------------------
__global__ void theta_kernel(const float* __restrict__ zx, const float* __restrict__ zc,
                             float* __restrict__ gtheta, float* __restrict__ otheta)
{
    __shared__ float sz[KK * 2];
    __shared__ float red[256];
    __shared__ float sth[KR];
    int n = blockIdx.x, tid = threadIdx.x;
    for (int i = tid; i < KK * 2; i += 256) sz[i] = zc[i];
    __syncthreads();
    float x0 = zx[n * 2], x1 = zx[n * 2 + 1];
    float l = -FLT_MAX;
    if (tid < KK) {
        float dx = x0 - sz[tid * 2];
        float dy = x1 - sz[tid * 2 + 1];
        l = -0.5f * (dx * dx + dy * dy);
    }
    red[tid] = l;
    __syncthreads();
    for (int st = 128; st > 0; st >>= 1) {
        if (tid < st) red[tid] = fmaxf(red[tid], red[tid + st]);
        __syncthreads();
    }
    float mx = red[0];
    __syncthreads();
    float e = (tid < KK) ? expf(l - mx) : 0.f;
    red[tid] = e;
    __syncthreads();
    for (int st = 128; st > 0; st >>= 1) {
        if (tid < st) red[tid] += red[tid + st];
        __syncthreads();
    }
    float inv = 1.f / red[0];
    float th = e * inv;
    if (tid < KK) {
        gtheta[(size_t)n * KK + tid] = th;
        otheta[(size_t)n * KK + tid] = th;
    }
    if (tid < KR) sth[tid] = (tid < KK) ? th : 0.f;
    __syncthreads();
    if (tid < KRW) {
        g_bf[W_TH + (size_t)n * KRW + tid] =
            pk_h2(__float2half_rn(sth[2 * tid]), __float2half_rn(sth[2 * tid + 1]));
    }
}

// ---------------- decoder MLP ------------------------------------------------
__global__ void mu1_kernel(const float* __restrict__ zc, const float* __restrict__ W,
                           const float* __restrict__ b, float* __restrict__ out)
{
    int t = blockIdx.x * 256 + threadIdx.x;
    if (t >= KK * 100) return;
    int k = t / 100, j = t % 100;
    float v = zc[k * 2] * W[j * 2] + zc[k * 2 + 1] * W[j * 2 + 1] + b[j];
    out[t] = softplusf(v);
}

__global__ void mu2_kernel(const float* __restrict__ mu1, const float* __restrict__ W,
                           const float* __restrict__ b, float* __restrict__ out)
{
    __shared__ float row[100];
    int k = blockIdx.x, tid = threadIdx.x;
    if (tid < 100) row[tid] = mu1[k * 100 + tid];
    __syncthreads();
    if (tid < 100) {
        const float* w = W + tid * 100;
        float s = b[tid];
        for (int i = 0; i < 100; i++) s += row[i] * w[i];
        out[k * 100 + tid] = softplusf(s);
    }
}

__global__ void muz_kernel(const float* __restrict__ mu2, const float* __restrict__ W,
                           const float* __restrict__ b, float* __restrict__ out)
{
    __shared__ float row[100];
    int k = blockIdx.x, tid = threadIdx.x;
    if (tid < 100) row[tid] = mu2[k * 100 + tid];
    __syncthreads();
    for (int j = tid; j < EMB; j += 128) {
        const float* w = W + j * 100;
        float s = b[j];
        for (int i = 0; i < 100; i++) s += row[i] * w[i];
        out[k * EMB + j] = s;
    }
}

// ---------------- beta -------------------------------------------------------
__global__ void __launch_bounds__(1024)
beta_kernel(const float* __restrict__ logits, const float* __restrict__ bbias,
            const float* __restrict__ gdec, const float* __restrict__ bdec,
            float* __restrict__ beta)
{
    __shared__ float red[1024];
    __shared__ float red2[1024];
    const int k = blockIdx.x, tid = threadIdx.x;
    const float* row = logits + (size_t)k * VV;
    const float* bb  = bbias + (size_t)k * VV;

    float s = 0.f, q = 0.f;
    for (int v = tid; v < VV; v += 1024) { float x = row[v]; s += x; q += x * x; }
    red[tid] = s; red2[tid] = q;
    __syncthreads();
    for (int st = 512; st > 0; st >>= 1) {
        if (tid < st) { red[tid] += red[tid + st]; red2[tid] += red2[tid + st]; }
        __syncthreads();
    }
    float mean = red[0] / VV;
    float var  = red2[0] / VV - mean * mean;
    float scale = gdec[k] * rsqrtf(var + 1e-5f);
    float shift = bdec[k] - mean * scale;
    __syncthreads();

    float mx = -FLT_MAX;
    for (int v = tid; v < VV; v += 1024) {
        float y = row[v] * scale + shift + bb[v];
        mx = fmaxf(mx, y);
    }
    red[tid] = mx;
    __syncthreads();
    for (int st = 512; st > 0; st >>= 1) {
        if (tid < st) red[tid] = fmaxf(red[tid], red[tid + st]);
        __syncthreads();
    }
    mx = red[0];
    __syncthreads();

    float se = 0.f;
    for (int v = tid; v < VV; v += 1024) {
        float y = row[v] * scale + shift + bb[v];
        se += expf(y - mx);
    }
    red[tid] = se;
    __syncthreads();
    for (int st = 512; st > 0; st >>= 1) {
        if (tid < st) red[tid] += red[tid + st];
        __syncthreads();
    }
    float inv = 1.f / red[0];

    for (int v = tid; v < VV; v += 1024) {
        float y = row[v] * scale + shift + bb[v];
        beta[(size_t)k * VV + v] = expf(y - mx) * inv;
    }
}

// ---------------- launch -----------------------------------------------------
extern "C" void kernel_launch(void* const* d_in, const int* in_sizes, int n_in,
                              void* d_out, int out_size)
{
    const float* input_   = (const float*)d_in[0];
    const float* eps      = (const float*)d_in[2];
    const float* en1_W    = (const float*)d_in[3];
    const float* en1_b    = (const float*)d_in[4];
    const float* en2_W    = (const float*)d_in[5];
    const float* en2_b    = (const float*)d_in[6];
    const float* mean_W   = (const float*)d_in[7];
    const float* mean_b   = (const float*)d_in[8];
    const float* logvar_W = (const float*)d_in[9];
    const float* logvar_b = (const float*)d_in[10];
    const float* mu1_W    = (const float*)d_in[11];
    const float* mu1_b    = (const float*)d_in[12];
    const float* mu2_W    = (const float*)d_in[13];
    const float* mu2_b    = (const float*)d_in[14];
    const float* mu_W     = (const float*)d_in[15];
    const float* mu_b     = (const float*)d_in[16];
    const float* topics   = (const float*)d_in[17];
    const float* bbias    = (const float*)d_in[18];
    const float* emb      = (const float*)d_in[19];
    const float* g_mean   = (const float*)d_in[20];
    const float* b_mean   = (const float*)d_in[21];
    const float* g_logvar = (const float*)d_in[22];
    const float* b_logvar = (const float*)d_in[23];
    const float* g_x      = (const float*)d_in[24];
    const float* b_x      = (const float*)d_in[25];
    const float* g_phi    = (const float*)d_in[26];
    const float* b_phi    = (const float*)d_in[27];
    const float* g_dec    = (const float*)d_in[28];
    const float* b_dec    = (const float*)d_in[29];

    float* out = (float*)d_out;
    float* out_z     = out;
    float* out_recon = out + (long long)NB * CC;
    float* out_zx    = out_recon + (long long)NB * VV;
    float* out_zc    = out_zx + (long long)NB * CC;
    float* out_theta = out_zc + (long long)KK * CC;

    void* sp = nullptr;
    cudaGetSymbolAddress(&sp, g_scratch);
    float* S = (float*)sp;
    float* s_en1    = S + OFF_EN1;
    float* s_en2    = S + OFF_EN2;
    float* s_pm     = S + OFF_PM;
    float* s_lv     = S + OFF_LV;
    float* s_z      = S + OFF_Z;
    float* s_zx     = S + OFF_ZX;
    float* s_zc     = S + OFF_ZC;
    float* s_theta  = S + OFF_THETA;
    float* s_mu1    = S + OFF_MU1;
    float* s_mu2    = S + OFF_MU2;
    float* s_muz    = S + OFF_MUZ;
    float* s_logits = S + OFF_LOGITS;
    float* s_beta   = S + OFF_BETA;
    float* st_pm    = S + OFF_SPM;
    float* st_lv    = S + OFF_SLV;
    float* st_z     = S + OFF_SZ;
    float* st_t     = S + OFF_ST;

    // lazily created resources (host objects only; work per call is identical)
    static cudaStream_t s_dec = nullptr;
    static cudaEvent_t ev_fork = nullptr, ev_zc = nullptr, ev_join = nullptr;
    if (s_dec == nullptr) {
        cudaStreamCreateWithFlags(&s_dec, cudaStreamNonBlocking);
        cudaEventCreateWithFlags(&ev_fork, cudaEventDisableTiming);
        cudaEventCreateWithFlags(&ev_zc, cudaEventDisableTiming);
        cudaEventCreateWithFlags(&ev_join, cudaEventDisableTiming);
        cudaFuncSetAttribute(gemm1_fp16, cudaFuncAttributeMaxDynamicSharedMemorySize, G1_SMEM);
        cudaFuncSetAttribute(recon_f16, cudaFuncAttributeMaxDynamicSharedMemorySize, G1_SMEM);
        cudaFuncSetAttribute(gemm_nt_bf16x3<true, true, false>,
                             cudaFuncAttributeMaxDynamicSharedMemorySize, NTB_SMEM);
        cudaFuncSetAttribute(gemm_nt_bf16x3<false, false, true>,
                             cudaFuncAttributeMaxDynamicSharedMemorySize, NTB_SMEM);
    }

    // ---- fork decoder chain onto s_dec ----
    cudaEventRecord(ev_fork, 0);
    cudaStreamWaitEvent(s_dec, ev_fork, 0);

    // decoder chain (independent of encoder): zc -> mu MLP -> logits -> beta -> beta^T
    colstats_kernel<<<2, 256, 0, s_dec>>>(topics, KK, st_t);
    bn_apply_kernel<<<(KK * CC + 255) / 256, 256, 0, s_dec>>>(
        topics, st_t, g_phi, b_phi, KK * CC, s_zc, out_zc);
    cudaEventRecord(ev_zc, s_dec);          // zc ready (theta on stream 0 needs it)
    mu1_kernel<<<(KK * 100 + 255) / 256, 256, 0, s_dec>>>(s_zc, mu1_W, mu1_b, s_mu1);
    mu2_kernel<<<KK, 128, 0, s_dec>>>(s_mu1, mu2_W, mu2_b, s_mu2);
    muz_kernel<<<KK, 128, 0, s_dec>>>(s_mu2, mu_W, mu_b, s_muz);
    gemm_nt_bf16x3<false, false, true><<<dim3((VV + 127) / 128, (KK + 127) / 128), 512, NTB_SMEM, s_dec>>>(
        s_muz, emb, nullptr, s_logits, KK, VV, EMB);
    beta_kernel<<<KK, 1024, 0, s_dec>>>(s_logits, bbias, g_dec, b_dec, s_beta);
    transpose_beta<<<dim3(BTROWS / 32, KR / 32), 256, 0, s_dec>>>(s_beta);
    cudaEventRecord(ev_join, s_dec);

    // encoder chain on stream 0
    split_fp16<<<NB + E1, 256>>>(input_, en1_W);
    gemm1_fp16<<<dim3(E1 / 128, NB / 128), 256, G1_SMEM>>>(en1_b, s_en1);
    gemm_nt_bf16x3<true, true, false><<<dim3(E2 / 128, NB / 128), 512, NTB_SMEM>>>(
        s_en1, en2_W, en2_b, s_en2, NB, E2, E1);
    meanlogvar_kernel<<<(NB * 4 + 255) / 256, 256>>>(
        s_en2, mean_W, mean_b, logvar_W, logvar_b, s_pm, s_lv);
    colstats_kernel<<<2, 256>>>(s_pm, NB, st_pm);
    colstats_kernel<<<2, 256>>>(s_lv, NB, st_lv);
    z_kernel<<<(NB * CC + 255) / 256, 256>>>(
        s_pm, s_lv, st_pm, st_lv, g_mean, b_mean, g_logvar, b_logvar, eps, s_z, out_z);
    colstats_kernel<<<2, 256>>>(s_z, NB, st_z);
    bn_apply_kernel<<<(NB * CC + 255) / 256, 256>>>(s_z, st_z, g_x, b_x, NB * CC, s_zx, out_zx);

    // theta needs zc from decoder chain
    cudaStreamWaitEvent(0, ev_zc, 0);
    theta_kernel<<<NB, 256>>>(s_zx, s_zc, s_theta, out_theta);

    // join: recon needs theta (stream 0) + beta^T (s_dec)
    cudaStreamWaitEvent(0, ev_join, 0);
    recon_f16<<<dim3(BTROWS / 128, NB / 128), 256, G1_SMEM>>>(out_recon);

    (void)in_sizes; (void)n_in; (void)out_size;
}

// round 12
// speedup vs baseline: 1.3072x; 1.3072x over previous
#include <cuda_runtime.h>
#include <cuda_bf16.h>
#include <cuda_fp16.h>
#include <math.h>
#include <float.h>
#include <stdint.h>

// ---------------- problem dims ----------------
#define NB   2048
#define VV   50000
#define E1   1024
#define E2   512
#define CC   2
#define KK   200
#define EMB  300

#define KP   50048
#define KPW  (KP/2)
#define G1NT (KP / 32)

#define KR   224
#define KRW  (KR/2)
#define RNT  (KR / 32)
#define BTROWS 50048

// ---------------- float scratch ----------------------------------------------
#define OFF_EN1    0LL
#define OFF_EN2    (OFF_EN1 + (long long)NB*E1)
#define OFF_PM     (OFF_EN2 + (long long)NB*E2)
#define OFF_LV     (OFF_PM + (long long)NB*CC)
#define OFF_Z      (OFF_LV + (long long)NB*CC)
#define OFF_ZX     (OFF_Z + (long long)NB*CC)
#define OFF_ZC     (OFF_ZX + (long long)NB*CC)
#define OFF_THETA  (OFF_ZC + (long long)KK*CC)
#define OFF_MU1    (OFF_THETA + (long long)NB*KK)
#define OFF_MU2    (OFF_MU1 + (long long)KK*100)
#define OFF_MUZ    (OFF_MU2 + (long long)KK*100)
#define OFF_LOGITS (OFF_MUZ + (long long)KK*EMB)
#define OFF_BETA   (OFF_LOGITS + (long long)KK*VV)
#define OFF_SPM    (OFF_BETA + (long long)KK*VV)
#define OFF_SLV    (OFF_SPM + 4)
#define OFF_SZ     (OFF_SLV + 4)
#define OFF_ST     (OFF_SZ + 4)
#define SCRATCH_FLOATS (OFF_ST + 8)

__device__ float g_scratch[SCRATCH_FLOATS];

// ---------------- fp16 planes (words) ----------------------------------------
#define WA 51249152LL
#define WB 25624576LL
#define W_AH 0LL
#define W_BH (W_AH + WA)
#define W_TH (W_BH + WB)
#define TWH  ((long long)NB * KRW)
#define W_BT (W_TH + TWH)
#define BTWH ((long long)BTROWS * KRW)

__device__ __align__(16) uint32_t g_bf[WA + WB + TWH + BTWH];

__device__ __forceinline__ float softplusf(float x) {
    return fmaxf(x, 0.0f) + log1pf(expf(-fabsf(x)));
}

__device__ __forceinline__ uint32_t pk_h2(__half lo, __half hi) {
    return ((uint32_t)__half_as_ushort(hi) << 16) | __half_as_ushort(lo);
}

__device__ __forceinline__ uint32_t pk_bf16(float lo, float hi) {
    uint32_t r;
    asm("cvt.rn.bf16x2.f32 %0, %1, %2;" : "=r"(r) : "f"(hi), "f"(lo));
    return r;
}

__device__ __forceinline__ unsigned tf32_rna(float x) {
    unsigned r;
    asm("cvt.rna.tf32.f32 %0, %1;" : "=r"(r) : "f"(x));
    return r;
}

__device__ __forceinline__ void mma_f16(float* d,
                                        uint32_t a0, uint32_t a1, uint32_t a2, uint32_t a3,
                                        uint32_t b0, uint32_t b1)
{
    asm volatile(
        "mma.sync.aligned.m16n8k16.row.col.f32.f16.f16.f32 "
        "{%0,%1,%2,%3},{%4,%5,%6,%7},{%8,%9},{%0,%1,%2,%3};"
        : "+f"(d[0]), "+f"(d[1]), "+f"(d[2]), "+f"(d[3])
        : "r"(a0), "r"(a1), "r"(a2), "r"(a3), "r"(b0), "r"(b1));
}

__device__ __forceinline__ void mma_bf16(float* d,
                                         uint32_t a0, uint32_t a1, uint32_t a2, uint32_t a3,
                                         uint32_t b0, uint32_t b1)
{
    asm volatile(
        "mma.sync.aligned.m16n8k16.row.col.f32.bf16.bf16.f32 "
        "{%0,%1,%2,%3},{%4,%5,%6,%7},{%8,%9},{%0,%1,%2,%3};"
        : "+f"(d[0]), "+f"(d[1]), "+f"(d[2]), "+f"(d[3])
        : "r"(a0), "r"(a1), "r"(a2), "r"(a3), "r"(b0), "r"(b1));
}

__device__ __forceinline__ void mma_tf32(float* d,
                                         unsigned a0, unsigned a1, unsigned a2, unsigned a3,
                                         unsigned b0, unsigned b1)
{
    asm volatile(
        "mma.sync.aligned.m16n8k8.row.col.f32.tf32.tf32.f32 "
        "{%0,%1,%2,%3},{%4,%5,%6,%7},{%8,%9},{%0,%1,%2,%3};"
        : "+f"(d[0]), "+f"(d[1]), "+f"(d[2]), "+f"(d[3])
        : "r"(a0), "r"(a1), "r"(a2), "r"(a3), "r"(b0), "r"(b1));
}

__device__ __forceinline__ void ldsm_x4(uint32_t& r0, uint32_t& r1, uint32_t& r2,
                                        uint32_t& r3, uint32_t addr)
{
    asm volatile("ldmatrix.sync.aligned.m8n8.x4.shared.b16 {%0,%1,%2,%3}, [%4];"
                 : "=r"(r0), "=r"(r1), "=r"(r2), "=r"(r3) : "r"(addr));
}

// =============================================================================
// Pre-pass: A=input, B=en1_W -> fp16 planes, zero pad.
// =============================================================================
__global__ void __launch_bounds__(256)
split_fp16(const float* __restrict__ A, const float* __restrict__ B)
{
    const int b = blockIdx.x, tid = threadIdx.x;
    const float* src;
    uint32_t* h;
    if (b < NB) {
        src = A + (size_t)b * VV;
        h = g_bf + W_AH + (size_t)b * KPW;
    } else {
        int r = b - NB;
        src = B + (size_t)r * VV;
        h = g_bf + W_BH + (size_t)r * KPW;
    }
    for (int i = tid; i < VV / 4; i += 256) {
        float4 v = *reinterpret_cast<const float4*>(src + i * 4);
        h[2*i]     = pk_h2(__float2half_rn(v.x), __float2half_rn(v.y));
        h[2*i + 1] = pk_h2(__float2half_rn(v.z), __float2half_rn(v.w));
    }
    if (tid < KPW - VV/2) h[VV/2 + tid] = 0u;
}

// =============================================================================
// GEMM1: en1 = softplus(input @ en1_W^T + b), plain fp16.
// =============================================================================
#define STG    20480
#define G1_SMEM (3 * STG)

__global__ void __launch_bounds__(256, 2)
gemm1_fp16(const float* __restrict__ bias, float* __restrict__ C)
{
    extern __shared__ __align__(16) char sm[];
    const uint32_t sb32 = (uint32_t)__cvta_generic_to_shared(sm);
    const int tid = threadIdx.x;
    const int lane = tid & 31, warp = tid >> 5;
    const int gid = lane >> 2, tig = lane & 3;
    const int wm = warp >> 1, wn = warp & 1;
    const int m0 = blockIdx.y * 128, n0 = blockIdx.x * 128;

    float acc[2][8][4];
#pragma unroll
    for (int i = 0; i < 2; i++)
#pragma unroll
        for (int j = 0; j < 8; j++)
#pragma unroll
            for (int l = 0; l < 4; l++) acc[i][j][l] = 0.0f;

    const uint32_t* gsrc[4];
    uint32_t sdst[4];
#pragma unroll
    for (int i = 0; i < 2; i++) {
        int idx = tid + i * 256;
        int r = idx >> 2, part = idx & 3;
        gsrc[i] = g_bf + W_AH + (size_t)(m0 + r) * KPW + part * 4;
        sdst[i] = sb32 + (uint32_t)(r * 80 + part * 16);
    }
#pragma unroll
    for (int i = 0; i < 2; i++) {
        int idx = tid + i * 256;
        int r = idx >> 2, part = idx & 3;
        gsrc[2 + i] = g_bf + W_BH + (size_t)(n0 + r) * KPW + part * 4;
        sdst[2 + i] = sb32 + (uint32_t)(10240 + r * 80 + part * 16);
    }

    auto issue = [&](int t) {
        const uint32_t boff = (uint32_t)(t % 3) * STG;
        const size_t k = (size_t)t * 16;
#pragma unroll
        for (int i = 0; i < 4; i++)
            asm volatile("cp.async.cg.shared.global [%0], [%1], 16;"
                         :: "r"(sdst[i] + boff), "l"(gsrc[i] + k) : "memory");
        asm volatile("cp.async.commit_group;" ::: "memory");
    };

    const int lr = (lane & 7) + ((lane >> 3) & 1) * 8;
    const int kb = ((lane >> 4) & 1) * 16;
    const uint32_t aoff = (uint32_t)((wm * 32 + lr) * 80 + kb);
    const uint32_t boff2 = (uint32_t)(10240 + (wn * 64 + lr) * 80 + kb);

    issue(0);
    issue(1);

    for (int t = 0; t < G1NT; t++) {
        if (t == G1NT - 1) asm volatile("cp.async.wait_group 0;" ::: "memory");
        else               asm volatile("cp.async.wait_group 1;" ::: "memory");
        __syncthreads();
        if (t + 2 < G1NT) issue(t + 2);

        const uint32_t st = sb32 + (uint32_t)(t % 3) * STG;
#pragma unroll
        for (int kkw = 0; kkw < 2; kkw++) {
            const uint32_t ka = st + kkw * 32;
            uint32_t ah[2][4], bq[4][4];
#pragma unroll
            for (int ms = 0; ms < 2; ms++)
                ldsm_x4(ah[ms][0], ah[ms][1], ah[ms][2], ah[ms][3],
                        ka + aoff + ms * 1280);
#pragma unroll
            for (int pr = 0; pr < 4; pr++)
                ldsm_x4(bq[pr][0], bq[pr][1], bq[pr][2], bq[pr][3],
                        ka + boff2 + pr * 1280);
#pragma unroll
            for (int ms = 0; ms < 2; ms++)
#pragma unroll
                for (int pr = 0; pr < 4; pr++)
#pragma unroll
                    for (int j = 0; j < 2; j++) {
                        int ns = pr * 2 + j;
                        mma_f16(acc[ms][ns], ah[ms][0], ah[ms][1], ah[ms][2], ah[ms][3],
                                bq[pr][j], bq[pr][j + 2]);
                    }
        }
    }

#pragma unroll
    for (int ms = 0; ms < 2; ms++) {
        const int r0 = m0 + wm * 32 + ms * 16 + gid;
#pragma unroll
        for (int ns = 0; ns < 8; ns++) {
            const int c0 = n0 + wn * 64 + ns * 8 + 2 * tig;
            const float bv0 = bias[c0], bv1 = bias[c0 + 1];
            C[(size_t)r0 * E1 + c0]           = softplusf(acc[ms][ns][0] + bv0);
            C[(size_t)r0 * E1 + c0 + 1]       = softplusf(acc[ms][ns][1] + bv1);
            C[(size_t)(r0 + 8) * E1 + c0]     = softplusf(acc[ms][ns][2] + bv0);
            C[(size_t)(r0 + 8) * E1 + c0 + 1] = softplusf(acc[ms][ns][3] + bv1);
        }
    }
}

// =============================================================================
// recon = theta @ beta via NT fp16 planes.
// =============================================================================
__global__ void __launch_bounds__(256, 2)
recon_f16(float* __restrict__ C)
{
    extern __shared__ __align__(16) char sm[];
    const uint32_t sb32 = (uint32_t)__cvta_generic_to_shared(sm);
    const int tid = threadIdx.x;
    const int lane = tid & 31, warp = tid >> 5;
    const int gid = lane >> 2, tig = lane & 3;
    const int wm = warp >> 1, wn = warp & 1;
    const int m0 = blockIdx.y * 128, n0 = blockIdx.x * 128;

    float acc[2][8][4];
#pragma unroll
    for (int i = 0; i < 2; i++)
#pragma unroll
        for (int j = 0; j < 8; j++)
#pragma unroll
            for (int l = 0; l < 4; l++) acc[i][j][l] = 0.0f;

    const uint32_t* gsrc[4];
    uint32_t sdst[4];
#pragma unroll
    for (int i = 0; i < 2; i++) {
        int idx = tid + i * 256;
        int r = idx >> 2, part = idx & 3;
        gsrc[i] = g_bf + W_TH + (size_t)(m0 + r) * KRW + part * 4;
        sdst[i] = sb32 + (uint32_t)(r * 80 + part * 16);
    }
#pragma unroll
    for (int i = 0; i < 2; i++) {
        int idx = tid + i * 256;
        int r = idx >> 2, part = idx & 3;
        gsrc[2 + i] = g_bf + W_BT + (size_t)(n0 + r) * KRW + part * 4;
        sdst[2 + i] = sb32 + (uint32_t)(10240 + r * 80 + part * 16);
    }

    auto issue = [&](int t) {
        const uint32_t boff = (uint32_t)(t % 3) * STG;
        const size_t k = (size_t)t * 16;
#pragma unroll
        for (int i = 0; i < 4; i++)
            asm volatile("cp.async.cg.shared.global [%0], [%1], 16;"
                         :: "r"(sdst[i] + boff), "l"(gsrc[i] + k) : "memory");
        asm volatile("cp.async.commit_group;" ::: "memory");
    };

    const int lr = (lane & 7) + ((lane >> 3) & 1) * 8;
    const int kb = ((lane >> 4) & 1) * 16;
    const uint32_t aoff = (uint32_t)((wm * 32 + lr) * 80 + kb);
    const uint32_t boff2 = (uint32_t)(10240 + (wn * 64 + lr) * 80 + kb);

    issue(0);
    issue(1);

    for (int t = 0; t < RNT; t++) {
        if (t == RNT - 1) asm volatile("cp.async.wait_group 0;" ::: "memory");
        else              asm volatile("cp.async.wait_group 1;" ::: "memory");
        __syncthreads();
        if (t + 2 < RNT) issue(t + 2);

        const uint32_t st = sb32 + (uint32_t)(t % 3) * STG;
#pragma unroll
        for (int kkw = 0; kkw < 2; kkw++) {
            const uint32_t ka = st + kkw * 32;
            uint32_t ah[2][4], bq[4][4];
#pragma unroll
            for (int ms = 0; ms < 2; ms++)
                ldsm_x4(ah[ms][0], ah[ms][1], ah[ms][2], ah[ms][3],
                        ka + aoff + ms * 1280);
#pragma unroll
            for (int pr = 0; pr < 4; pr++)
                ldsm_x4(bq[pr][0], bq[pr][1], bq[pr][2], bq[pr][3],
                        ka + boff2 + pr * 1280);
#pragma unroll
            for (int ms = 0; ms < 2; ms++)
#pragma unroll
                for (int pr = 0; pr < 4; pr++)
#pragma unroll
                    for (int j = 0; j < 2; j++) {
                        int ns = pr * 2 + j;
                        mma_f16(acc[ms][ns], ah[ms][0], ah[ms][1], ah[ms][2], ah[ms][3],
                                bq[pr][j], bq[pr][j + 2]);
                    }
        }
    }

#pragma unroll
    for (int ms = 0; ms < 2; ms++) {
        const int r0 = m0 + wm * 32 + ms * 16 + gid;
#pragma unroll
        for (int ns = 0; ns < 8; ns++) {
            const int c0 = n0 + wn * 64 + ns * 8 + 2 * tig;
            if (c0 < VV) {
                C[(size_t)r0 * VV + c0]       = acc[ms][ns][0];
                C[(size_t)(r0 + 8) * VV + c0] = acc[ms][ns][2];
            }
            if (c0 + 1 < VV) {
                C[(size_t)r0 * VV + c0 + 1]       = acc[ms][ns][1];
                C[(size_t)(r0 + 8) * VV + c0 + 1] = acc[ms][ns][3];
            }
        }
    }
}

// =============================================================================
// beta^T fp16
// =============================================================================
__global__ void __launch_bounds__(256)
transpose_beta(const float* __restrict__ beta)
{
    __shared__ float s[32][33];
    const int tid = threadIdx.x;
    const int tx = tid & 31, ty = tid >> 5;
    const int v0 = blockIdx.x * 32, k0 = blockIdx.y * 32;

#pragma unroll
    for (int i = 0; i < 4; i++) {
        int k = ty + i * 8;
        int gk = k0 + k, gv = v0 + tx;
        float val = 0.f;
        if (gk < KK && gv < VV) val = beta[(size_t)gk * VV + gv];
        s[k][tx] = val;
    }
    __syncthreads();

#pragma unroll
    for (int i = 0; i < 2; i++) {
        int w = tid + i * 256;
        int v = w >> 4, kw = w & 15;
        uint32_t word = pk_h2(__float2half_rn(s[2 * kw][v]),
                              __float2half_rn(s[2 * kw + 1][v]));
        g_bf[W_BT + (size_t)(v0 + v) * KRW + (k0 >> 1) + kw] = word;
    }
}

// =============================================================================
// logits = mu_z[200,300] @ emb[50000,300]^T — single-pass tf32.
// BM=64, BN=64, BK=16, 256 threads (8 warps, 16x32 warp tiles).
// =============================================================================
__global__ void __launch_bounds__(256)
logits_tf32(const float* __restrict__ A, const float* __restrict__ B,
            float* __restrict__ C)
{
    __shared__ float As[64][20];
    __shared__ float Bs[64][20];
    const int tid = threadIdx.x;
    const int lane = tid & 31, warp = tid >> 5;
    const int gid = lane >> 2, tig = lane & 3;
    const int wm = warp >> 1, wn = warp & 1;   // 4 x 2 warps, 16x32 tiles
    const int m0 = blockIdx.y * 64, n0 = blockIdx.x * 64;

    float acc[4][4];
#pragma unroll
    for (int j = 0; j < 4; j++)
#pragma unroll
        for (int l = 0; l < 4; l++) acc[j][l] = 0.0f;

    const int row = tid >> 2, q = (tid & 3) * 4;

    for (int k0 = 0; k0 < EMB; k0 += 16) {
        const int gk = k0 + q;
        // A tile
        {
            int gm = m0 + row;
            float4 v = make_float4(0.f, 0.f, 0.f, 0.f);
            if (gm < KK) {
                const float* p = A + (size_t)gm * EMB;
                if (gk + 3 < EMB) v = *reinterpret_cast<const float4*>(p + gk);
                else {
                    if (gk + 0 < EMB) v.x = p[gk + 0];
                    if (gk + 1 < EMB) v.y = p[gk + 1];
                    if (gk + 2 < EMB) v.z = p[gk + 2];
                    if (gk + 3 < EMB) v.w = p[gk + 3];
                }
            }
            As[row][q + 0] = __uint_as_float(tf32_rna(v.x));
            As[row][q + 1] = __uint_as_float(tf32_rna(v.y));
            As[row][q + 2] = __uint_as_float(tf32_rna(v.z));
            As[row][q + 3] = __uint_as_float(tf32_rna(v.w));
        }
        // B tile
        {
            int gn = n0 + row;
            float4 v = make_float4(0.f, 0.f, 0.f, 0.f);
            if (gn < VV) {
                const float* p = B + (size_t)gn * EMB;
                if (gk + 3 < EMB) v = *reinterpret_cast<const float4*>(p + gk);
                else {
                    if (gk + 0 < EMB) v.x = p[gk + 0];
                    if (gk + 1 < EMB) v.y = p[gk + 1];
                    if (gk + 2 < EMB) v.z = p[gk + 2];
                    if (gk + 3 < EMB) v.w = p[gk + 3];
                }
            }
            Bs[row][q + 0] = __uint_as_float(tf32_rna(v.x));
            Bs[row][q + 1] = __uint_as_float(tf32_rna(v.y));
            Bs[row][q + 2] = __uint_as_float(tf32_rna(v.z));
            Bs[row][q + 3] = __uint_as_float(tf32_rna(v.w));
        }
        __syncthreads();

#pragma unroll
        for (int kk = 0; kk < 16; kk += 8) {
            unsigned a[4], b[4][2];
            int r = wm * 16 + gid;
            a[0] = __float_as_uint(As[r][kk + tig]);
            a[1] = __float_as_uint(As[r + 8][kk + tig]);
            a[2] = __float_as_uint(As[r][kk + tig + 4]);
            a[3] = __float_as_uint(As[r + 8][kk + tig + 4]);
#pragma unroll
            for (int ns = 0; ns < 4; ns++) {
                int n = wn * 32 + ns * 8 + gid;
                b[ns][0] = __float_as_uint(Bs[n][kk + tig]);
                b[ns][1] = __float_as_uint(Bs[n][kk + tig + 4]);
            }
#pragma unroll
            for (int ns = 0; ns < 4; ns++)
                mma_tf32(acc[ns], a[0], a[1], a[2], a[3], b[ns][0], b[ns][1]);
        }
        __syncthreads();
    }

    const int r0 = m0 + wm * 16 + gid;
#pragma unroll
    for (int ns = 0; ns < 4; ns++) {
        const int c0 = n0 + wn * 32 + ns * 8 + 2 * tig;
        if (r0 < KK) {
            if (c0 < VV)     C[(size_t)r0 * VV + c0]     = acc[ns][0];
            if (c0 + 1 < VV) C[(size_t)r0 * VV + c0 + 1] = acc[ns][1];
        }
        if (r0 + 8 < KK) {
            if (c0 < VV)     C[(size_t)(r0 + 8) * VV + c0]     = acc[ns][2];
            if (c0 + 1 < VV) C[(size_t)(r0 + 8) * VV + c0 + 1] = acc[ns][3];
        }
    }
}

// ============================ bf16x3 NT GEMM (en2) ===========================
#define NTB_SMEM (2 * 10240 * 4)

template<bool SP, bool HB, bool CHKMN>
__global__ void __launch_bounds__(512, 1)
gemm_nt_bf16x3(const float* __restrict__ A, const float* __restrict__ B,
               const float* __restrict__ bias, float* __restrict__ C,
               int M, int N, int K)
{
    extern __shared__ __align__(16) uint32_t sw[];
    const int tid = threadIdx.x;
    const int lane = tid & 31, warp = tid >> 5;
    const int gid = lane >> 2, tig = lane & 3;
    const int wm = warp >> 2, wn = warp & 3;
    const int m0 = blockIdx.y * 128, n0 = blockIdx.x * 128;
    const int nt = (K + 31) / 32;

    float acc[2][4][4];
#pragma unroll
    for (int i = 0; i < 2; i++)
#pragma unroll
        for (int j = 0; j < 4; j++)
#pragma unroll
            for (int l = 0; l < 4; l++) acc[i][j][l] = 0.0f;

    const int srow = tid >> 3;
    const int sq   = tid & 7;
    float4 stA[2], stB[2];

    auto load_tile = [&](int t) {
        const int gk = t * 32 + sq * 4;
#pragma unroll
        for (int l = 0; l < 2; l++) {
            int r = srow + l * 64;
            {
                int gm = m0 + r;
                float4 v = make_float4(0.f, 0.f, 0.f, 0.f);
                if (((!CHKMN) || gm < M)) {
                    if (gk + 3 < K) v = *reinterpret_cast<const float4*>(A + (size_t)gm * K + gk);
                    else if (gk < K) {
                        const float* p = A + (size_t)gm * K;
                        v.x = p[gk];
                        if (gk + 1 < K) v.y = p[gk + 1];
                        if (gk + 2 < K) v.z = p[gk + 2];
                    }
                }
                stA[l] = v;
            }
            {
                int gn = n0 + r;
                float4 v = make_float4(0.f, 0.f, 0.f, 0.f);
                if (((!CHKMN) || gn < N)) {
                    if (gk + 3 < K) v = *reinterpret_cast<const float4*>(B + (size_t)gn * K + gk);
                    else if (gk < K) {
                        const float* p = B + (size_t)gn * K;
                        v.x = p[gk];
                        if (gk + 1 < K) v.y = p[gk + 1];
                        if (gk + 2 < K) v.z = p[gk + 2];
                    }
                }
                stB[l] = v;
            }
        }
    };

    auto store_tile = [&](uint32_t* buf) {
#pragma unroll
        for (int l = 0; l < 2; l++) {
            int r = srow + l * 64;
            uint32_t w = (uint32_t)(r * 20 + sq * 2);
            {
                float4 v = stA[l];
                __nv_bfloat16 hx = __float2bfloat16_rn(v.x), hy = __float2bfloat16_rn(v.y);
                __nv_bfloat16 hz = __float2bfloat16_rn(v.z), hw = __float2bfloat16_rn(v.w);
                buf[w]     = ((uint32_t)__bfloat16_as_ushort(hy) << 16) | __bfloat16_as_ushort(hx);
                buf[w + 1] = ((uint32_t)__bfloat16_as_ushort(hw) << 16) | __bfloat16_as_ushort(hz);
                buf[w + 2560]     = pk_bf16(v.x - __bfloat162float(hx), v.y - __bfloat162float(hy));
                buf[w + 2560 + 1] = pk_bf16(v.z - __bfloat162float(hz), v.w - __bfloat162float(hw));
            }
            {
                float4 v = stB[l];
                __nv_bfloat16 hx = __float2bfloat16_rn(v.x), hy = __float2bfloat16_rn(v.y);
                __nv_bfloat16 hz = __float2bfloat16_rn(v.z), hw = __float2bfloat16_rn(v.w);
                buf[w + 5120]     = ((uint32_t)__bfloat16_as_ushort(hy) << 16) | __bfloat16_as_ushort(hx);
                buf[w + 5120 + 1] = ((uint32_t)__bfloat16_as_ushort(hw) << 16) | __bfloat16_as_ushort(hz);
                buf[w + 7680]     = pk_bf16(v.x - __bfloat162float(hx), v.y - __bfloat162float(hy));
                buf[w + 7680 + 1] = pk_bf16(v.z - __bfloat162float(hz), v.w - __bfloat162float(hw));
            }
        }
    };

    load_tile(0);
    store_tile(sw);
    __syncthreads();

    for (int t = 0; t < nt; t++) {
        const int b = t & 1;
        uint32_t* bb = sw + b * 10240;
        if (t + 1 < nt) load_tile(t + 1);

#pragma unroll
        for (int kkw = 0; kkw < 16; kkw += 8) {
            uint32_t ah[2][4], al[2][4], bh[4][2], bl[4][2];
#pragma unroll
            for (int ms = 0; ms < 2; ms++) {
                int base = (wm * 32 + ms * 16 + gid) * 20 + kkw + tig;
                ah[ms][0] = bb[base];       ah[ms][1] = bb[base + 160];
                ah[ms][2] = bb[base + 4];   ah[ms][3] = bb[base + 164];
                al[ms][0] = bb[base + 2560];       al[ms][1] = bb[base + 2560 + 160];
                al[ms][2] = bb[base + 2560 + 4];   al[ms][3] = bb[base + 2560 + 164];
            }
#pragma unroll
            for (int ns = 0; ns < 4; ns++) {
                int base = 5120 + (wn * 32 + ns * 8 + gid) * 20 + kkw + tig;
                bh[ns][0] = bb[base];       bh[ns][1] = bb[base + 4];
                bl[ns][0] = bb[base + 2560]; bl[ns][1] = bb[base + 2560 + 4];
            }
#pragma unroll
            for (int ms = 0; ms < 2; ms++)
#pragma unroll
                for (int ns = 0; ns < 4; ns++) {
                    mma_bf16(acc[ms][ns], ah[ms][0], ah[ms][1], ah[ms][2], ah[ms][3],
                             bh[ns][0], bh[ns][1]);
                    mma_bf16(acc[ms][ns], ah[ms][0], ah[ms][1], ah[ms][2], ah[ms][3],
                             bl[ns][0], bl[ns][1]);
                    mma_bf16(acc[ms][ns], al[ms][0], al[ms][1], al[ms][2], al[ms][3],
                             bh[ns][0], bh[ns][1]);
                }
        }

        if (t + 1 < nt) store_tile(sw + (b ^ 1) * 10240);
        __syncthreads();
    }

#pragma unroll
    for (int ms = 0; ms < 2; ms++) {
        int r0 = m0 + wm * 32 + ms * 16 + gid;
#pragma unroll
        for (int ns = 0; ns < 4; ns++) {
            int c0 = n0 + wn * 32 + ns * 8 + 2 * tig;
            float bv0 = 0.f, bv1 = 0.f;
            if (HB) { bv0 = bias[c0]; bv1 = bias[c0 + 1]; }
            float v00 = acc[ms][ns][0] + bv0;
            float v01 = acc[ms][ns][1] + bv1;
            float v10 = acc[ms][ns][2] + bv0;
            float v11 = acc[ms][ns][3] + bv1;
            if (SP) { v00 = softplusf(v00); v01 = softplusf(v01);
                      v10 = softplusf(v10); v11 = softplusf(v11); }
            if (!CHKMN) {
                C[(size_t)r0 * N + c0]           = v00;
                C[(size_t)r0 * N + c0 + 1]       = v01;
                C[(size_t)(r0 + 8) * N + c0]     = v10;
                C[(size_t)(r0 + 8) * N + c0 + 1] = v11;
            } else {
                if (r0 < M) {
                    if (c0 < N)     C[(size_t)r0 * N + c0]     = v00;
                    if (c0 + 1 < N) C[(size_t)r0 * N + c0 + 1] = v01;
                }
                if (r0 + 8 < M) {
                    if (c0 < N)     C[(size_t)(r0 + 8) * N + c0]     = v10;
                    if (c0 + 1 < N) C[(size_t)(r0 + 8) * N + c0 + 1] = v11;
                }
            }
        }
    }
}

// ---------------- mean / logvar heads ---------------------------------------
__global__ void meanlogvar_kernel(const float* __restrict__ en2,
                                  const float* __restrict__ mW, const float* __restrict__ mb,
                                  const float* __restrict__ lW, const float* __restrict__ lb,
                                  float* __restrict__ pm, float* __restrict__ lv)
{
    int t = blockIdx.x * blockDim.x + threadIdx.x;
    if (t >= NB * 4) return;
    int n = t >> 2, j = t & 3;
    const float* w = (j < 2) ? (mW + j * E2) : (lW + (j - 2) * E2);
    const float* x = en2 + (size_t)n * E2;
    float s = 0.f;
    for (int i = 0; i < E2; i += 4) {
        float4 xa = *reinterpret_cast<const float4*>(x + i);
        float4 wa = *reinterpret_cast<const float4*>(w + i);
        s += xa.x * wa.x + xa.y * wa.y + xa.z * wa.z + xa.w * wa.w;
    }
    if (j < 2) pm[n * 2 + j] = s + mb[j];
    else       lv[n * 2 + (j - 2)] = s + lb[j - 2];
}

// ---------------- column stats (topics) --------------------------------------
__global__ void colstats_kernel(const float* __restrict__ X, int R, float* __restrict__ out)
{
    __shared__ float ss[256], s2[256];
    int c = blockIdx.x, tid = threadIdx.x;
    float s = 0.f, q = 0.f;
    for (int r = tid; r < R; r += 256) {
        float x = X[r * 2 + c];
        s += x; q += x * x;
    }
    ss[tid] = s; s2[tid] = q;
    __syncthreads();
    for (int st = 128; st > 0; st >>= 1) {
        if (tid < st) { ss[tid] += ss[tid + st]; s2[tid] += s2[tid + st]; }
        __syncthreads();
    }
    if (tid == 0) {
        float m = ss[0] / R;
        out[c] = m;
        out[2 + c] = s2[0] / R - m * m;
    }
}

// ---------------- BN apply (zc) ----------------------------------------------
__global__ void bn_apply_kernel(const float* __restrict__ X, const float* __restrict__ stats,
                                const float* __restrict__ g, const float* __restrict__ b,
                                int total, float* __restrict__ o1, float* __restrict__ o2)
{
    int idx = blockIdx.x * 256 + threadIdx.x;
    if (idx >= total) return;
    int c = idx & 1;
    float y = g[c] * (X[idx] - stats[c]) * rsqrtf(stats[2 + c] + 1e-5f) + b[c];
    o1[idx] = y;
    o2[idx] = y;
}

// =============================================================================
// Fused mid-section: pm/lv stats -> z -> z stats -> zx. One block, 1024 thr.
// =============================================================================
__global__ void __launch_bounds__(1024)
mid_fused(const float* __restrict__ pm, const float* __restrict__ lv,
          const float* __restrict__ epsin,
          const float* __restrict__ gm, const float* __restrict__ bm,
          const float* __restrict__ gl, const float* __restrict__ bl,
          const float* __restrict__ gx, const float* __restrict__ bxx,
          float* __restrict__ out_z, float* __restrict__ s_zx,
          float* __restrict__ out_zx)
{
    __shared__ float4 red[1024];
    __shared__ float st[12];    // pm: m0,m1,v0,v1 | lv: ... | z: ...
    const int tid = threadIdx.x;

    auto reduce4 = [&](float s0, float q0, float s1, float q1, int base) {
        red[tid] = make_float4(s0, q0, s1, q1);
        __syncthreads();
        for (int s = 512; s > 0; s >>= 1) {
            if (tid < s) {
                float4 a = red[tid], b2 = red[tid + s];
                red[tid] = make_float4(a.x + b2.x, a.y + b2.y, a.z + b2.z, a.w + b2.w);
            }
            __syncthreads();
        }
        if (tid == 0) {
            float4 r = red[0];
            float m0 = r.x / NB, m1 = r.z / NB;
            st[base + 0] = m0;
            st[base + 1] = m1;
            st[base + 2] = r.y / NB - m0 * m0;
            st[base + 3] = r.w / NB - m1 * m1;
        }
        __syncthreads();
    };

    // pm stats
    {
        float s0 = 0, q0 = 0, s1 = 0, q1 = 0;
#pragma unroll
        for (int i = 0; i < 2; i++) {
            int r = tid + i * 1024;
            float x0 = pm[r * 2], x1 = pm[r * 2 + 1];
            s0 += x0; q0 += x0 * x0; s1 += x1; q1 += x1 * x1;
        }
        reduce4(s0, q0, s1, q1, 0);
    }
    // lv stats
    {
        float s0 = 0, q0 = 0, s1 = 0, q1 = 0;
#pragma unroll
        for (int i = 0; i < 2; i++) {
            int r = tid + i * 1024;
            float x0 = lv[r * 2], x1 = lv[r * 2 + 1];
            s0 += x0; q0 += x0 * x0; s1 += x1; q1 += x1 * x1;
        }
        reduce4(s0, q0, s1, q1, 4);
    }
    // z + z stats
    float zr[2][2];
    {
        const float pmi0 = rsqrtf(st[2] + 1e-5f), pmi1 = rsqrtf(st[3] + 1e-5f);
        const float lvi0 = rsqrtf(st[6] + 1e-5f), lvi1 = rsqrtf(st[7] + 1e-5f);
        const float gm0 = gm[0], gm1 = gm[1], bm0 = bm[0], bm1 = bm[1];
        const float gl0 = gl[0], gl1 = gl[1], bl0 = bl[0], bl1 = bl[1];
        float s0 = 0, q0 = 0, s1 = 0, q1 = 0;
#pragma unroll
        for (int i = 0; i < 2; i++) {
            int r = tid + i * 1024;
            float p0 = gm0 * (pm[r * 2] - st[0]) * pmi0 + bm0;
            float p1 = gm1 * (pm[r * 2 + 1] - st[1]) * pmi1 + bm1;
            float l0 = gl0 * (lv[r * 2] - st[4]) * lvi0 + bl0;
            float l1 = gl1 * (lv[r * 2 + 1] - st[5]) * lvi1 + bl1;
            float z0 = p0 + sqrtf(expf(l0)) * epsin[r * 2];
            float z1 = p1 + sqrtf(expf(l1)) * epsin[r * 2 + 1];
            out_z[r * 2] = z0;
            out_z[r * 2 + 1] = z1;
            zr[i][0] = z0; zr[i][1] = z1;
            s0 += z0; q0 += z0 * z0; s1 += z1; q1 += z1 * z1;
        }
        reduce4(s0, q0, s1, q1, 8);
    }
    // zx
    {
        const float zi0 = rsqrtf(st[10] + 1e-5f), zi1 = rsqrtf(st[11] + 1e-5f);
        const float gx0 = gx[0], gx1 = gx[1], bx0 = bxx[0], bx1 = bxx[1];
#pragma unroll
        for (int i = 0; i < 2; i++) {
            int r = tid + i * 1024;
            float y0 = gx0 * (zr[i][0] - st[8]) * zi0 + bx0;
            float y1 = gx1 * (zr[i][1] - st[9]) * zi1 + bx1;
            s_zx[r * 2] = y0;    s_zx[r * 2 + 1] = y1;
            out_zx[r * 2] = y0;  out_zx[r * 2 + 1] = y1;
        }
    }
}

// ---------------- theta (fp32 outputs + fp16 plane) --------------------------
__global__ void theta_kernel(const float* __restrict__ zx, const float* __restrict__ zc,
                             float* __restrict__ gtheta, float* __restrict__ otheta)
{
    __shared__ float sz[KK * 2];
    __shared__ float red[256];
    __shared__ float sth[KR];
    int n = blockIdx.x, tid = threadIdx.x;
    for (int i = tid; i < KK * 2; i += 256) sz[i] = zc[i];
    __syncthreads();
    float x0 = zx[n * 2], x1 = zx[n * 2 + 1];
    float l = -FLT_MAX;
    if (tid < KK) {
        float dx = x0 - sz[tid * 2];
        float dy = x1 - sz[tid * 2 + 1];
        l = -0.5f * (dx * dx + dy * dy);
    }
    red[tid] = l;
    __syncthreads();
    for (int st = 128; st > 0; st >>= 1) {
        if (tid < st) red[tid] = fmaxf(red[tid], red[tid + st]);
        __syncthreads();
    }
    float mx = red[0];
    __syncthreads();
    float e = (tid < KK) ? expf(l - mx) : 0.f;
    red[tid] = e;
    __syncthreads();
    for (int st = 128; st > 0; st >>= 1) {
        if (tid < st) red[tid] += red[tid + st];
        __syncthreads();
    }
    float inv = 1.f / red[0];
    float th = e * inv;
    if (tid < KK) {
        gtheta[(size_t)n * KK + tid] = th;
        otheta[(size_t)n * KK + tid] = th;
    }
    if (tid < KR) sth[tid] = (tid < KK) ? th : 0.f;
    __syncthreads();
    if (tid < KRW) {
        g_bf[W_TH + (size_t)n * KRW + tid] =
            pk_h2(__float2half_rn(sth[2 * tid]), __float2half_rn(sth[2 * tid + 1]));
    }
}

// ---------------- decoder MLP ------------------------------------------------
__global__ void mu1_kernel(const float* __restrict__ zc, const float* __restrict__ W,
                           const float* __restrict__ b, float* __restrict__ out)
{
    int t = blockIdx.x * 256 + threadIdx.x;
    if (t >= KK * 100) return;
    int k = t / 100, j = t % 100;
    float v = zc[k * 2] * W[j * 2] + zc[k * 2 + 1] * W[j * 2 + 1] + b[j];
    out[t] = softplusf(v);
}

__global__ void mu2_kernel(const float* __restrict__ mu1, const float* __restrict__ W,
                           const float* __restrict__ b, float* __restrict__ out)
{
    __shared__ float row[100];
    int k = blockIdx.x, tid = threadIdx.x;
    if (tid < 100) row[tid] = mu1[k * 100 + tid];
    __syncthreads();
    if (tid < 100) {
        const float* w = W + tid * 100;
        float s = b[tid];
        for (int i = 0; i < 100; i++) s += row[i] * w[i];
        out[k * 100 + tid] = softplusf(s);
    }
}

__global__ void muz_kernel(const float* __restrict__ mu2, const float* __restrict__ W,
                           const float* __restrict__ b, float* __restrict__ out)
{
    __shared__ float row[100];
    int k = blockIdx.x, tid = threadIdx.x;
    if (tid < 100) row[tid] = mu2[k * 100 + tid];
    __syncthreads();
    for (int j = tid; j < EMB; j += 128) {
        const float* w = W + j * 100;
        float s = b[j];
        for (int i = 0; i < 100; i++) s += row[i] * w[i];
        out[k * EMB + j] = s;
    }
}

// ---------------- beta -------------------------------------------------------
__global__ void __launch_bounds__(1024)
beta_kernel(const float* __restrict__ logits, const float* __restrict__ bbias,
            const float* __restrict__ gdec, const float* __restrict__ bdec,
            float* __restrict__ beta)
{
    __shared__ float red[1024];
    __shared__ float red2[1024];
    const int k = blockIdx.x, tid = threadIdx.x;
    const float* row = logits + (size_t)k * VV;
    const float* bb  = bbias + (size_t)k * VV;

    float s = 0.f, q = 0.f;
    for (int v = tid; v < VV; v += 1024) { float x = row[v]; s += x; q += x * x; }
    red[tid] = s; red2[tid] = q;
    __syncthreads();
    for (int st = 512; st > 0; st >>= 1) {
        if (tid < st) { red[tid] += red[tid + st]; red2[tid] += red2[tid + st]; }
        __syncthreads();
    }
    float mean = red[0] / VV;
    float var  = red2[0] / VV - mean * mean;
    float scale = gdec[k] * rsqrtf(var + 1e-5f);
    float shift = bdec[k] - mean * scale;
    __syncthreads();

    float mx = -FLT_MAX;
    for (int v = tid; v < VV; v += 1024) {
        float y = row[v] * scale + shift + bb[v];
        mx = fmaxf(mx, y);
    }
    red[tid] = mx;
    __syncthreads();
    for (int st = 512; st > 0; st >>= 1) {
        if (tid < st) red[tid] = fmaxf(red[tid], red[tid + st]);
        __syncthreads();
    }
    mx = red[0];
    __syncthreads();

    float se = 0.f;
    for (int v = tid; v < VV; v += 1024) {
        float y = row[v] * scale + shift + bb[v];
        se += expf(y - mx);
    }
    red[tid] = se;
    __syncthreads();
    for (int st = 512; st > 0; st >>= 1) {
        if (tid < st) red[tid] += red[tid + st];
        __syncthreads();
    }
    float inv = 1.f / red[0];

    for (int v = tid; v < VV; v += 1024) {
        float y = row[v] * scale + shift + bb[v];
        beta[(size_t)k * VV + v] = expf(y - mx) * inv;
    }
}

// ---------------- launch -----------------------------------------------------
extern "C" void kernel_launch(void* const* d_in, const int* in_sizes, int n_in,
                              void* d_out, int out_size)
{
    const float* input_   = (const float*)d_in[0];
    const float* eps      = (const float*)d_in[2];
    const float* en1_W    = (const float*)d_in[3];
    const float* en1_b    = (const float*)d_in[4];
    const float* en2_W    = (const float*)d_in[5];
    const float* en2_b    = (const float*)d_in[6];
    const float* mean_W   = (const float*)d_in[7];
    const float* mean_b   = (const float*)d_in[8];
    const float* logvar_W = (const float*)d_in[9];
    const float* logvar_b = (const float*)d_in[10];
    const float* mu1_W    = (const float*)d_in[11];
    const float* mu1_b    = (const float*)d_in[12];
    const float* mu2_W    = (const float*)d_in[13];
    const float* mu2_b    = (const float*)d_in[14];
    const float* mu_W     = (const float*)d_in[15];
    const float* mu_b     = (const float*)d_in[16];
    const float* topics   = (const float*)d_in[17];
    const float* bbias    = (const float*)d_in[18];
    const float* emb      = (const float*)d_in[19];
    const float* g_mean   = (const float*)d_in[20];
    const float* b_mean   = (const float*)d_in[21];
    const float* g_logvar = (const float*)d_in[22];
    const float* b_logvar = (const float*)d_in[23];
    const float* g_x      = (const float*)d_in[24];
    const float* b_x      = (const float*)d_in[25];
    const float* g_phi    = (const float*)d_in[26];
    const float* b_phi    = (const float*)d_in[27];
    const float* g_dec    = (const float*)d_in[28];
    const float* b_dec    = (const float*)d_in[29];

    float* out = (float*)d_out;
    float* out_z     = out;
    float* out_recon = out + (long long)NB * CC;
    float* out_zx    = out_recon + (long long)NB * VV;
    float* out_zc    = out_zx + (long long)NB * CC;
    float* out_theta = out_zc + (long long)KK * CC;

    void* sp = nullptr;
    cudaGetSymbolAddress(&sp, g_scratch);
    float* S = (float*)sp;
    float* s_en1    = S + OFF_EN1;
    float* s_en2    = S + OFF_EN2;
    float* s_pm     = S + OFF_PM;
    float* s_lv     = S + OFF_LV;
    float* s_zx     = S + OFF_ZX;
    float* s_zc     = S + OFF_ZC;
    float* s_theta  = S + OFF_THETA;
    float* s_mu1    = S + OFF_MU1;
    float* s_mu2    = S + OFF_MU2;
    float* s_muz    = S + OFF_MUZ;
    float* s_logits = S + OFF_LOGITS;
    float* s_beta   = S + OFF_BETA;
    float* st_t     = S + OFF_ST;

    cudaFuncSetAttribute(gemm1_fp16, cudaFuncAttributeMaxDynamicSharedMemorySize, G1_SMEM);
    cudaFuncSetAttribute(recon_f16, cudaFuncAttributeMaxDynamicSharedMemorySize, G1_SMEM);
    cudaFuncSetAttribute(gemm_nt_bf16x3<true, true, false>,
                         cudaFuncAttributeMaxDynamicSharedMemorySize, NTB_SMEM);

    // 0) pre-split: A -> 1 fp16 plane, B -> 1 fp16 plane
    split_fp16<<<NB + E1, 256>>>(input_, en1_W);

    // 1-4) decoder-side small kernels
    colstats_kernel<<<2, 256>>>(topics, KK, st_t);
    bn_apply_kernel<<<(KK * CC + 255) / 256, 256>>>(topics, st_t, g_phi, b_phi, KK * CC, s_zc, out_zc);
    mu1_kernel<<<(KK * 100 + 255) / 256, 256>>>(s_zc, mu1_W, mu1_b, s_mu1);
    mu2_kernel<<<KK, 128>>>(s_mu1, mu2_W, mu2_b, s_mu2);

    // 5) en1 = softplus(input @ en1_W^T + b) — plain fp16
    gemm1_fp16<<<dim3(E1 / 128, NB / 128), 256, G1_SMEM>>>(en1_b, s_en1);

    // 6) muz
    muz_kernel<<<KK, 128>>>(s_mu2, mu_W, mu_b, s_muz);

    // 7) en2 — bf16x3
    gemm_nt_bf16x3<true, true, false><<<dim3(E2 / 128, NB / 128), 512, NTB_SMEM>>>(
        s_en1, en2_W, en2_b, s_en2, NB, E2, E1);

    // 8) heads
    meanlogvar_kernel<<<(NB * 4 + 255) / 256, 256>>>(
        s_en2, mean_W, mean_b, logvar_W, logvar_b, s_pm, s_lv);

    // 9) fused mid-section: pm/lv stats -> z -> z stats -> zx
    mid_fused<<<1, 1024>>>(s_pm, s_lv, eps, g_mean, b_mean, g_logvar, b_logvar,
                           g_x, b_x, out_z, s_zx, out_zx);

    // 10) theta
    theta_kernel<<<NB, 256>>>(s_zx, s_zc, s_theta, out_theta);

    // 11) logits = mu_z @ emb^T — tf32 single pass
    logits_tf32<<<dim3((VV + 63) / 64, (KK + 63) / 64), 256>>>(s_muz, emb, s_logits);

    // 12) beta
    beta_kernel<<<KK, 1024>>>(s_logits, bbias, g_dec, b_dec, s_beta);

    // 13) beta^T fp16
    transpose_beta<<<dim3(BTROWS / 32, KR / 32), 256>>>(s_beta);

    // 14) recon = theta @ beta — fp16 NT
    recon_f16<<<dim3(BTROWS / 128, NB / 128), 256, G1_SMEM>>>(out_recon);

    (void)in_sizes; (void)n_in; (void)out_size;
}

// round 13
// speedup vs baseline: 1.3083x; 1.0009x over previous
#include <cuda_runtime.h>
#include <cuda_bf16.h>
#include <cuda_fp16.h>
#include <math.h>
#include <float.h>
#include <stdint.h>

// ---------------- problem dims ----------------
#define NB   2048
#define VV   50000
#define E1   1024
#define E2   512
#define CC   2
#define KK   200
#define EMB  300

#define KP   50048
#define KPW  (KP/2)
#define G1NT (KP / 32)

#define KR   224
#define KRW  (KR/2)
#define RNT  (KR / 32)
#define BTROWS 50048

// ---------------- float scratch ----------------------------------------------
#define OFF_EN1    0LL
#define OFF_EN2    (OFF_EN1 + (long long)NB*E1)
#define OFF_PM     (OFF_EN2 + (long long)NB*E2)
#define OFF_LV     (OFF_PM + (long long)NB*CC)
#define OFF_Z      (OFF_LV + (long long)NB*CC)
#define OFF_ZX     (OFF_Z + (long long)NB*CC)
#define OFF_ZC     (OFF_ZX + (long long)NB*CC)
#define OFF_THETA  (OFF_ZC + (long long)KK*CC)
#define OFF_MU1    (OFF_THETA + (long long)NB*KK)
#define OFF_MU2    (OFF_MU1 + (long long)KK*100)
#define OFF_MUZ    (OFF_MU2 + (long long)KK*100)
#define OFF_LOGITS (OFF_MUZ + (long long)KK*EMB)
#define OFF_BETA   (OFF_LOGITS + (long long)KK*VV)
#define OFF_SPM    (OFF_BETA + (long long)KK*VV)
#define OFF_SLV    (OFF_SPM + 4)
#define OFF_SZ     (OFF_SLV + 4)
#define OFF_ST     (OFF_SZ + 4)
#define SCRATCH_FLOATS (OFF_ST + 8)

__device__ float g_scratch[SCRATCH_FLOATS];

// ---------------- fp16 planes (words) ----------------------------------------
#define WA 51249152LL
#define WB 25624576LL
#define W_AH 0LL
#define W_BH (W_AH + WA)
#define W_TH (W_BH + WB)
#define TWH  ((long long)NB * KRW)
#define W_BT (W_TH + TWH)
#define BTWH ((long long)BTROWS * KRW)

__device__ __align__(16) uint32_t g_bf[WA + WB + TWH + BTWH];

__device__ __forceinline__ float softplusf(float x) {
    return fmaxf(x, 0.0f) + log1pf(expf(-fabsf(x)));
}

__device__ __forceinline__ uint32_t pk_h2(__half lo, __half hi) {
    return ((uint32_t)__half_as_ushort(hi) << 16) | __half_as_ushort(lo);
}

__device__ __forceinline__ uint32_t pk_bf16(float lo, float hi) {
    uint32_t r;
    asm("cvt.rn.bf16x2.f32 %0, %1, %2;" : "=r"(r) : "f"(hi), "f"(lo));
    return r;
}

__device__ __forceinline__ unsigned tf32_rna(float x) {
    unsigned r;
    asm("cvt.rna.tf32.f32 %0, %1;" : "=r"(r) : "f"(x));
    return r;
}

__device__ __forceinline__ void mma_f16(float* d,
                                        uint32_t a0, uint32_t a1, uint32_t a2, uint32_t a3,
                                        uint32_t b0, uint32_t b1)
{
    asm volatile(
        "mma.sync.aligned.m16n8k16.row.col.f32.f16.f16.f32 "
        "{%0,%1,%2,%3},{%4,%5,%6,%7},{%8,%9},{%0,%1,%2,%3};"
        : "+f"(d[0]), "+f"(d[1]), "+f"(d[2]), "+f"(d[3])
        : "r"(a0), "r"(a1), "r"(a2), "r"(a3), "r"(b0), "r"(b1));
}

__device__ __forceinline__ void mma_bf16(float* d,
                                         uint32_t a0, uint32_t a1, uint32_t a2, uint32_t a3,
                                         uint32_t b0, uint32_t b1)
{
    asm volatile(
        "mma.sync.aligned.m16n8k16.row.col.f32.bf16.bf16.f32 "
        "{%0,%1,%2,%3},{%4,%5,%6,%7},{%8,%9},{%0,%1,%2,%3};"
        : "+f"(d[0]), "+f"(d[1]), "+f"(d[2]), "+f"(d[3])
        : "r"(a0), "r"(a1), "r"(a2), "r"(a3), "r"(b0), "r"(b1));
}

__device__ __forceinline__ void mma_tf32(float* d,
                                         unsigned a0, unsigned a1, unsigned a2, unsigned a3,
                                         unsigned b0, unsigned b1)
{
    asm volatile(
        "mma.sync.aligned.m16n8k8.row.col.f32.tf32.tf32.f32 "
        "{%0,%1,%2,%3},{%4,%5,%6,%7},{%8,%9},{%0,%1,%2,%3};"
        : "+f"(d[0]), "+f"(d[1]), "+f"(d[2]), "+f"(d[3])
        : "r"(a0), "r"(a1), "r"(a2), "r"(a3), "r"(b0), "r"(b1));
}

__device__ __forceinline__ void ldsm_x4(uint32_t& r0, uint32_t& r1, uint32_t& r2,
                                        uint32_t& r3, uint32_t addr)
{
    asm volatile("ldmatrix.sync.aligned.m8n8.x4.shared.b16 {%0,%1,%2,%3}, [%4];"
                 : "=r"(r0), "=r"(r1), "=r"(r2), "=r"(r3) : "r"(addr));
}

// =============================================================================
// Pre-pass: A=input, B=en1_W -> fp16 planes, zero pad.
// =============================================================================
__global__ void __launch_bounds__(256)
split_fp16(const float* __restrict__ A, const float* __restrict__ B)
{
    const int b = blockIdx.x, tid = threadIdx.x;
    const float* src;
    uint32_t* h;
    if (b < NB) {
        src = A + (size_t)b * VV;
        h = g_bf + W_AH + (size_t)b * KPW;
    } else {
        int r = b - NB;
        src = B + (size_t)r * VV;
        h = g_bf + W_BH + (size_t)r * KPW;
    }
    for (int i = tid; i < VV / 4; i += 256) {
        float4 v = *reinterpret_cast<const float4*>(src + i * 4);
        h[2*i]     = pk_h2(__float2half_rn(v.x), __float2half_rn(v.y));
        h[2*i + 1] = pk_h2(__float2half_rn(v.z), __float2half_rn(v.w));
    }
    if (tid < KPW - VV/2) h[VV/2 + tid] = 0u;
}

// =============================================================================
// GEMM1: en1 = softplus(input @ en1_W^T + b), plain fp16.
// =============================================================================
#define STG    20480
#define G1_SMEM (3 * STG)

__global__ void __launch_bounds__(256, 2)
gemm1_fp16(const float* __restrict__ bias, float* __restrict__ C)
{
    extern __shared__ __align__(16) char sm[];
    const uint32_t sb32 = (uint32_t)__cvta_generic_to_shared(sm);
    const int tid = threadIdx.x;
    const int lane = tid & 31, warp = tid >> 5;
    const int gid = lane >> 2, tig = lane & 3;
    const int wm = warp >> 1, wn = warp & 1;
    const int m0 = blockIdx.y * 128, n0 = blockIdx.x * 128;

    float acc[2][8][4];
#pragma unroll
    for (int i = 0; i < 2; i++)
#pragma unroll
        for (int j = 0; j < 8; j++)
#pragma unroll
            for (int l = 0; l < 4; l++) acc[i][j][l] = 0.0f;

    const uint32_t* gsrc[4];
    uint32_t sdst[4];
#pragma unroll
    for (int i = 0; i < 2; i++) {
        int idx = tid + i * 256;
        int r = idx >> 2, part = idx & 3;
        gsrc[i] = g_bf + W_AH + (size_t)(m0 + r) * KPW + part * 4;
        sdst[i] = sb32 + (uint32_t)(r * 80 + part * 16);
    }
#pragma unroll
    for (int i = 0; i < 2; i++) {
        int idx = tid + i * 256;
        int r = idx >> 2, part = idx & 3;
        gsrc[2 + i] = g_bf + W_BH + (size_t)(n0 + r) * KPW + part * 4;
        sdst[2 + i] = sb32 + (uint32_t)(10240 + r * 80 + part * 16);
    }

    auto issue = [&](int t) {
        const uint32_t boff = (uint32_t)(t % 3) * STG;
        const size_t k = (size_t)t * 16;
#pragma unroll
        for (int i = 0; i < 4; i++)
            asm volatile("cp.async.cg.shared.global [%0], [%1], 16;"
                         :: "r"(sdst[i] + boff), "l"(gsrc[i] + k) : "memory");
        asm volatile("cp.async.commit_group;" ::: "memory");
    };

    const int lr = (lane & 7) + ((lane >> 3) & 1) * 8;
    const int kb = ((lane >> 4) & 1) * 16;
    const uint32_t aoff = (uint32_t)((wm * 32 + lr) * 80 + kb);
    const uint32_t boff2 = (uint32_t)(10240 + (wn * 64 + lr) * 80 + kb);

    issue(0);
    issue(1);

    for (int t = 0; t < G1NT; t++) {
        if (t == G1NT - 1) asm volatile("cp.async.wait_group 0;" ::: "memory");
        else               asm volatile("cp.async.wait_group 1;" ::: "memory");
        __syncthreads();
        if (t + 2 < G1NT) issue(t + 2);

        const uint32_t st = sb32 + (uint32_t)(t % 3) * STG;
#pragma unroll
        for (int kkw = 0; kkw < 2; kkw++) {
            const uint32_t ka = st + kkw * 32;
            uint32_t ah[2][4], bq[4][4];
#pragma unroll
            for (int ms = 0; ms < 2; ms++)
                ldsm_x4(ah[ms][0], ah[ms][1], ah[ms][2], ah[ms][3],
                        ka + aoff + ms * 1280);
#pragma unroll
            for (int pr = 0; pr < 4; pr++)
                ldsm_x4(bq[pr][0], bq[pr][1], bq[pr][2], bq[pr][3],
                        ka + boff2 + pr * 1280);
#pragma unroll
            for (int ms = 0; ms < 2; ms++)
#pragma unroll
                for (int pr = 0; pr < 4; pr++)
#pragma unroll
                    for (int j = 0; j < 2; j++) {
                        int ns = pr * 2 + j;
                        mma_f16(acc[ms][ns], ah[ms][0], ah[ms][1], ah[ms][2], ah[ms][3],
                                bq[pr][j], bq[pr][j + 2]);
                    }
        }
    }

#pragma unroll
    for (int ms = 0; ms < 2; ms++) {
        const int r0 = m0 + wm * 32 + ms * 16 + gid;
#pragma unroll
        for (int ns = 0; ns < 8; ns++) {
            const int c0 = n0 + wn * 64 + ns * 8 + 2 * tig;
            const float bv0 = bias[c0], bv1 = bias[c0 + 1];
            C[(size_t)r0 * E1 + c0]           = softplusf(acc[ms][ns][0] + bv0);
            C[(size_t)r0 * E1 + c0 + 1]       = softplusf(acc[ms][ns][1] + bv1);
            C[(size_t)(r0 + 8) * E1 + c0]     = softplusf(acc[ms][ns][2] + bv0);
            C[(size_t)(r0 + 8) * E1 + c0 + 1] = softplusf(acc[ms][ns][3] + bv1);
        }
    }
}

// =============================================================================
// recon = theta @ beta via NT fp16 planes.
// =============================================================================
__global__ void __launch_bounds__(256, 2)
recon_f16(float* __restrict__ C)
{
    extern __shared__ __align__(16) char sm[];
    const uint32_t sb32 = (uint32_t)__cvta_generic_to_shared(sm);
    const int tid = threadIdx.x;
    const int lane = tid & 31, warp = tid >> 5;
    const int gid = lane >> 2, tig = lane & 3;
    const int wm = warp >> 1, wn = warp & 1;
    const int m0 = blockIdx.y * 128, n0 = blockIdx.x * 128;

    float acc[2][8][4];
#pragma unroll
    for (int i = 0; i < 2; i++)
#pragma unroll
        for (int j = 0; j < 8; j++)
#pragma unroll
            for (int l = 0; l < 4; l++) acc[i][j][l] = 0.0f;

    const uint32_t* gsrc[4];
    uint32_t sdst[4];
#pragma unroll
    for (int i = 0; i < 2; i++) {
        int idx = tid + i * 256;
        int r = idx >> 2, part = idx & 3;
        gsrc[i] = g_bf + W_TH + (size_t)(m0 + r) * KRW + part * 4;
        sdst[i] = sb32 + (uint32_t)(r * 80 + part * 16);
    }
#pragma unroll
    for (int i = 0; i < 2; i++) {
        int idx = tid + i * 256;
        int r = idx >> 2, part = idx & 3;
        gsrc[2 + i] = g_bf + W_BT + (size_t)(n0 + r) * KRW + part * 4;
        sdst[2 + i] = sb32 + (uint32_t)(10240 + r * 80 + part * 16);
    }

    auto issue = [&](int t) {
        const uint32_t boff = (uint32_t)(t % 3) * STG;
        const size_t k = (size_t)t * 16;
#pragma unroll
        for (int i = 0; i < 4; i++)
            asm volatile("cp.async.cg.shared.global [%0], [%1], 16;"
                         :: "r"(sdst[i] + boff), "l"(gsrc[i] + k) : "memory");
        asm volatile("cp.async.commit_group;" ::: "memory");
    };

    const int lr = (lane & 7) + ((lane >> 3) & 1) * 8;
    const int kb = ((lane >> 4) & 1) * 16;
    const uint32_t aoff = (uint32_t)((wm * 32 + lr) * 80 + kb);
    const uint32_t boff2 = (uint32_t)(10240 + (wn * 64 + lr) * 80 + kb);

    issue(0);
    issue(1);

    for (int t = 0; t < RNT; t++) {
        if (t == RNT - 1) asm volatile("cp.async.wait_group 0;" ::: "memory");
        else              asm volatile("cp.async.wait_group 1;" ::: "memory");
        __syncthreads();
        if (t + 2 < RNT) issue(t + 2);

        const uint32_t st = sb32 + (uint32_t)(t % 3) * STG;
#pragma unroll
        for (int kkw = 0; kkw < 2; kkw++) {
            const uint32_t ka = st + kkw * 32;
            uint32_t ah[2][4], bq[4][4];
#pragma unroll
            for (int ms = 0; ms < 2; ms++)
                ldsm_x4(ah[ms][0], ah[ms][1], ah[ms][2], ah[ms][3],
                        ka + aoff + ms * 1280);
#pragma unroll
            for (int pr = 0; pr < 4; pr++)
                ldsm_x4(bq[pr][0], bq[pr][1], bq[pr][2], bq[pr][3],
                        ka + boff2 + pr * 1280);
#pragma unroll
            for (int ms = 0; ms < 2; ms++)
#pragma unroll
                for (int pr = 0; pr < 4; pr++)
#pragma unroll
                    for (int j = 0; j < 2; j++) {
                        int ns = pr * 2 + j;
                        mma_f16(acc[ms][ns], ah[ms][0], ah[ms][1], ah[ms][2], ah[ms][3],
                                bq[pr][j], bq[pr][j + 2]);
                    }
        }
    }

#pragma unroll
    for (int ms = 0; ms < 2; ms++) {
        const int r0 = m0 + wm * 32 + ms * 16 + gid;
#pragma unroll
        for (int ns = 0; ns < 8; ns++) {
            const int c0 = n0 + wn * 64 + ns * 8 + 2 * tig;
            if (c0 < VV) {
                C[(size_t)r0 * VV + c0]       = acc[ms][ns][0];
                C[(size_t)(r0 + 8) * VV + c0] = acc[ms][ns][2];
            }
            if (c0 + 1 < VV) {
                C[(size_t)r0 * VV + c0 + 1]       = acc[ms][ns][1];
                C[(size_t)(r0 + 8) * VV + c0 + 1] = acc[ms][ns][3];
            }
        }
    }
}

// =============================================================================
// beta^T fp16
// =============================================================================
__global__ void __launch_bounds__(256)
transpose_beta(const float* __restrict__ beta)
{
    __shared__ float s[32][33];
    const int tid = threadIdx.x;
    const int tx = tid & 31, ty = tid >> 5;
    const int v0 = blockIdx.x * 32, k0 = blockIdx.y * 32;

#pragma unroll
    for (int i = 0; i < 4; i++) {
        int k = ty + i * 8;
        int gk = k0 + k, gv = v0 + tx;
        float val = 0.f;
        if (gk < KK && gv < VV) val = beta[(size_t)gk * VV + gv];
        s[k][tx] = val;
    }
    __syncthreads();

#pragma unroll
    for (int i = 0; i < 2; i++) {
        int w = tid + i * 256;
        int v = w >> 4, kw = w & 15;
        uint32_t word = pk_h2(__float2half_rn(s[2 * kw][v]),
                              __float2half_rn(s[2 * kw + 1][v]));
        g_bf[W_BT + (size_t)(v0 + v) * KRW + (k0 >> 1) + kw] = word;
    }
}

// =============================================================================
// logits = mu_z[200,300] @ emb[50000,300]^T — single-pass tf32.
// =============================================================================
__global__ void __launch_bounds__(256)
logits_tf32(const float* __restrict__ A, const float* __restrict__ B,
            float* __restrict__ C)
{
    __shared__ float As[64][20];
    __shared__ float Bs[64][20];
    const int tid = threadIdx.x;
    const int lane = tid & 31, warp = tid >> 5;
    const int gid = lane >> 2, tig = lane & 3;
    const int wm = warp >> 1, wn = warp & 1;
    const int m0 = blockIdx.y * 64, n0 = blockIdx.x * 64;

    float acc[4][4];
#pragma unroll
    for (int j = 0; j < 4; j++)
#pragma unroll
        for (int l = 0; l < 4; l++) acc[j][l] = 0.0f;

    const int row = tid >> 2, q = (tid & 3) * 4;

    for (int k0 = 0; k0 < EMB; k0 += 16) {
        const int gk = k0 + q;
        {
            int gm = m0 + row;
            float4 v = make_float4(0.f, 0.f, 0.f, 0.f);
            if (gm < KK) {
                const float* p = A + (size_t)gm * EMB;
                if (gk + 3 < EMB) v = *reinterpret_cast<const float4*>(p + gk);
                else {
                    if (gk + 0 < EMB) v.x = p[gk + 0];
                    if (gk + 1 < EMB) v.y = p[gk + 1];
                    if (gk + 2 < EMB) v.z = p[gk + 2];
                    if (gk + 3 < EMB) v.w = p[gk + 3];
                }
            }
            As[row][q + 0] = __uint_as_float(tf32_rna(v.x));
            As[row][q + 1] = __uint_as_float(tf32_rna(v.y));
            As[row][q + 2] = __uint_as_float(tf32_rna(v.z));
            As[row][q + 3] = __uint_as_float(tf32_rna(v.w));
        }
        {
            int gn = n0 + row;
            float4 v = make_float4(0.f, 0.f, 0.f, 0.f);
            if (gn < VV) {
                const float* p = B + (size_t)gn * EMB;
                if (gk + 3 < EMB) v = *reinterpret_cast<const float4*>(p + gk);
                else {
                    if (gk + 0 < EMB) v.x = p[gk + 0];
                    if (gk + 1 < EMB) v.y = p[gk + 1];
                    if (gk + 2 < EMB) v.z = p[gk + 2];
                    if (gk + 3 < EMB) v.w = p[gk + 3];
                }
            }
            Bs[row][q + 0] = __uint_as_float(tf32_rna(v.x));
            Bs[row][q + 1] = __uint_as_float(tf32_rna(v.y));
            Bs[row][q + 2] = __uint_as_float(tf32_rna(v.z));
            Bs[row][q + 3] = __uint_as_float(tf32_rna(v.w));
        }
        __syncthreads();

#pragma unroll
        for (int kk = 0; kk < 16; kk += 8) {
            unsigned a[4], b[4][2];
            int r = wm * 16 + gid;
            a[0] = __float_as_uint(As[r][kk + tig]);
            a[1] = __float_as_uint(As[r + 8][kk + tig]);
            a[2] = __float_as_uint(As[r][kk + tig + 4]);
            a[3] = __float_as_uint(As[r + 8][kk + tig + 4]);
#pragma unroll
            for (int ns = 0; ns < 4; ns++) {
                int n = wn * 32 + ns * 8 + gid;
                b[ns][0] = __float_as_uint(Bs[n][kk + tig]);
                b[ns][1] = __float_as_uint(Bs[n][kk + tig + 4]);
            }
#pragma unroll
            for (int ns = 0; ns < 4; ns++)
                mma_tf32(acc[ns], a[0], a[1], a[2], a[3], b[ns][0], b[ns][1]);
        }
        __syncthreads();
    }

    const int r0 = m0 + wm * 16 + gid;
#pragma unroll
    for (int ns = 0; ns < 4; ns++) {
        const int c0 = n0 + wn * 32 + ns * 8 + 2 * tig;
        if (r0 < KK) {
            if (c0 < VV)     C[(size_t)r0 * VV + c0]     = acc[ns][0];
            if (c0 + 1 < VV) C[(size_t)r0 * VV + c0 + 1] = acc[ns][1];
        }
        if (r0 + 8 < KK) {
            if (c0 < VV)     C[(size_t)(r0 + 8) * VV + c0]     = acc[ns][2];
            if (c0 + 1 < VV) C[(size_t)(r0 + 8) * VV + c0 + 1] = acc[ns][3];
        }
    }
}

// ============================ bf16x3 NT GEMM (en2) ===========================
#define NTB_SMEM (2 * 10240 * 4)

template<bool SP, bool HB, bool CHKMN>
__global__ void __launch_bounds__(512, 1)
gemm_nt_bf16x3(const float* __restrict__ A, const float* __restrict__ B,
               const float* __restrict__ bias, float* __restrict__ C,
               int M, int N, int K)
{
    extern __shared__ __align__(16) uint32_t sw[];
    const int tid = threadIdx.x;
    const int lane = tid & 31, warp = tid >> 5;
    const int gid = lane >> 2, tig = lane & 3;
    const int wm = warp >> 2, wn = warp & 3;
    const int m0 = blockIdx.y * 128, n0 = blockIdx.x * 128;
    const int nt = (K + 31) / 32;

    float acc[2][4][4];
#pragma unroll
    for (int i = 0; i < 2; i++)
#pragma unroll
        for (int j = 0; j < 4; j++)
#pragma unroll
            for (int l = 0; l < 4; l++) acc[i][j][l] = 0.0f;

    const int srow = tid >> 3;
    const int sq   = tid & 7;
    float4 stA[2], stB[2];

    auto load_tile = [&](int t) {
        const int gk = t * 32 + sq * 4;
#pragma unroll
        for (int l = 0; l < 2; l++) {
            int r = srow + l * 64;
            {
                int gm = m0 + r;
                float4 v = make_float4(0.f, 0.f, 0.f, 0.f);
                if (((!CHKMN) || gm < M)) {
                    if (gk + 3 < K) v = *reinterpret_cast<const float4*>(A + (size_t)gm * K + gk);
                    else if (gk < K) {
                        const float* p = A + (size_t)gm * K;
                        v.x = p[gk];
                        if (gk + 1 < K) v.y = p[gk + 1];
                        if (gk + 2 < K) v.z = p[gk + 2];
                    }
                }
                stA[l] = v;
            }
            {
                int gn = n0 + r;
                float4 v = make_float4(0.f, 0.f, 0.f, 0.f);
                if (((!CHKMN) || gn < N)) {
                    if (gk + 3 < K) v = *reinterpret_cast<const float4*>(B + (size_t)gn * K + gk);
                    else if (gk < K) {
                        const float* p = B + (size_t)gn * K;
                        v.x = p[gk];
                        if (gk + 1 < K) v.y = p[gk + 1];
                        if (gk + 2 < K) v.z = p[gk + 2];
                    }
                }
                stB[l] = v;
            }
        }
    };

    auto store_tile = [&](uint32_t* buf) {
#pragma unroll
        for (int l = 0; l < 2; l++) {
            int r = srow + l * 64;
            uint32_t w = (uint32_t)(r * 20 + sq * 2);
            {
                float4 v = stA[l];
                __nv_bfloat16 hx = __float2bfloat16_rn(v.x), hy = __float2bfloat16_rn(v.y);
                __nv_bfloat16 hz = __float2bfloat16_rn(v.z), hw = __float2bfloat16_rn(v.w);
                buf[w]     = ((uint32_t)__bfloat16_as_ushort(hy) << 16) | __bfloat16_as_ushort(hx);
                buf[w + 1] = ((uint32_t)__bfloat16_as_ushort(hw) << 16) | __bfloat16_as_ushort(hz);
                buf[w + 2560]     = pk_bf16(v.x - __bfloat162float(hx), v.y - __bfloat162float(hy));
                buf[w + 2560 + 1] = pk_bf16(v.z - __bfloat162float(hz), v.w - __bfloat162float(hw));
            }
            {
                float4 v = stB[l];
                __nv_bfloat16 hx = __float2bfloat16_rn(v.x), hy = __float2bfloat16_rn(v.y);
                __nv_bfloat16 hz = __float2bfloat16_rn(v.z), hw = __float2bfloat16_rn(v.w);
                buf[w + 5120]     = ((uint32_t)__bfloat16_as_ushort(hy) << 16) | __bfloat16_as_ushort(hx);
                buf[w + 5120 + 1] = ((uint32_t)__bfloat16_as_ushort(hw) << 16) | __bfloat16_as_ushort(hz);
                buf[w + 7680]     = pk_bf16(v.x - __bfloat162float(hx), v.y - __bfloat162float(hy));
                buf[w + 7680 + 1] = pk_bf16(v.z - __bfloat162float(hz), v.w - __bfloat162float(hw));
            }
        }
    };

    load_tile(0);
    store_tile(sw);
    __syncthreads();

    for (int t = 0; t < nt; t++) {
        const int b = t & 1;
        uint32_t* bb = sw + b * 10240;
        if (t + 1 < nt) load_tile(t + 1);

#pragma unroll
        for (int kkw = 0; kkw < 16; kkw += 8) {
            uint32_t ah[2][4], al[2][4], bh[4][2], bl[4][2];
#pragma unroll
            for (int ms = 0; ms < 2; ms++) {
                int base = (wm * 32 + ms * 16 + gid) * 20 + kkw + tig;
                ah[ms][0] = bb[base];       ah[ms][1] = bb[base + 160];
                ah[ms][2] = bb[base + 4];   ah[ms][3] = bb[base + 164];
                al[ms][0] = bb[base + 2560];       al[ms][1] = bb[base + 2560 + 160];
                al[ms][2] = bb[base + 2560 + 4];   al[ms][3] = bb[base + 2560 + 164];
            }
#pragma unroll
            for (int ns = 0; ns < 4; ns++) {
                int base = 5120 + (wn * 32 + ns * 8 + gid) * 20 + kkw + tig;
                bh[ns][0] = bb[base];       bh[ns][1] = bb[base + 4];
                bl[ns][0] = bb[base + 2560]; bl[ns][1] = bb[base + 2560 + 4];
            }
#pragma unroll
            for (int ms = 0; ms < 2; ms++)
#pragma unroll
                for (int ns = 0; ns < 4; ns++) {
                    mma_bf16(acc[ms][ns], ah[ms][0], ah[ms][1], ah[ms][2], ah[ms][3],
                             bh[ns][0], bh[ns][1]);
                    mma_bf16(acc[ms][ns], ah[ms][0], ah[ms][1], ah[ms][2], ah[ms][3],
                             bl[ns][0], bl[ns][1]);
                    mma_bf16(acc[ms][ns], al[ms][0], al[ms][1], al[ms][2], al[ms][3],
                             bh[ns][0], bh[ns][1]);
                }
        }

        if (t + 1 < nt) store_tile(sw + (b ^ 1) * 10240);
        __syncthreads();
    }

#pragma unroll
    for (int ms = 0; ms < 2; ms++) {
        int r0 = m0 + wm * 32 + ms * 16 + gid;
#pragma unroll
        for (int ns = 0; ns < 4; ns++) {
            int c0 = n0 + wn * 32 + ns * 8 + 2 * tig;
            float bv0 = 0.f, bv1 = 0.f;
            if (HB) { bv0 = bias[c0]; bv1 = bias[c0 + 1]; }
            float v00 = acc[ms][ns][0] + bv0;
            float v01 = acc[ms][ns][1] + bv1;
            float v10 = acc[ms][ns][2] + bv0;
            float v11 = acc[ms][ns][3] + bv1;
            if (SP) { v00 = softplusf(v00); v01 = softplusf(v01);
                      v10 = softplusf(v10); v11 = softplusf(v11); }
            if (!CHKMN) {
                C[(size_t)r0 * N + c0]           = v00;
                C[(size_t)r0 * N + c0 + 1]       = v01;
                C[(size_t)(r0 + 8) * N + c0]     = v10;
                C[(size_t)(r0 + 8) * N + c0 + 1] = v11;
            } else {
                if (r0 < M) {
                    if (c0 < N)     C[(size_t)r0 * N + c0]     = v00;
                    if (c0 + 1 < N) C[(size_t)r0 * N + c0 + 1] = v01;
                }
                if (r0 + 8 < M) {
                    if (c0 < N)     C[(size_t)(r0 + 8) * N + c0]     = v10;
                    if (c0 + 1 < N) C[(size_t)(r0 + 8) * N + c0 + 1] = v11;
                }
            }
        }
    }
}

// ---------------- mean / logvar heads ---------------------------------------
__global__ void meanlogvar_kernel(const float* __restrict__ en2,
                                  const float* __restrict__ mW, const float* __restrict__ mb,
                                  const float* __restrict__ lW, const float* __restrict__ lb,
                                  float* __restrict__ pm, float* __restrict__ lv)
{
    int t = blockIdx.x * blockDim.x + threadIdx.x;
    if (t >= NB * 4) return;
    int n = t >> 2, j = t & 3;
    const float* w = (j < 2) ? (mW + j * E2) : (lW + (j - 2) * E2);
    const float* x = en2 + (size_t)n * E2;
    float s = 0.f;
    for (int i = 0; i < E2; i += 4) {
        float4 xa = *reinterpret_cast<const float4*>(x + i);
        float4 wa = *reinterpret_cast<const float4*>(w + i);
        s += xa.x * wa.x + xa.y * wa.y + xa.z * wa.z + xa.w * wa.w;
    }
    if (j < 2) pm[n * 2 + j] = s + mb[j];
    else       lv[n * 2 + (j - 2)] = s + lb[j - 2];
}

// ---------------- column stats (topics) --------------------------------------
__global__ void colstats_kernel(const float* __restrict__ X, int R, float* __restrict__ out)
{
    __shared__ float ss[256], s2[256];
    int c = blockIdx.x, tid = threadIdx.x;
    float s = 0.f, q = 0.f;
    for (int r = tid; r < R; r += 256) {
        float x = X[r * 2 + c];
        s += x; q += x * x;
    }
    ss[tid] = s; s2[tid] = q;
    __syncthreads();
    for (int st = 128; st > 0; st >>= 1) {
        if (tid < st) { ss[tid] += ss[tid + st]; s2[tid] += s2[tid + st]; }
        __syncthreads();
    }
    if (tid == 0) {
        float m = ss[0] / R;
        out[c] = m;
        out[2 + c] = s2[0] / R - m * m;
    }
}

// ---------------- BN apply (zc) ----------------------------------------------
__global__ void bn_apply_kernel(const float* __restrict__ X, const float* __restrict__ stats,
                                const float* __restrict__ g, const float* __restrict__ b,
                                int total, float* __restrict__ o1, float* __restrict__ o2)
{
    int idx = blockIdx.x * 256 + threadIdx.x;
    if (idx >= total) return;
    int c = idx & 1;
    float y = g[c] * (X[idx] - stats[c]) * rsqrtf(stats[2 + c] + 1e-5f) + b[c];
    o1[idx] = y;
    o2[idx] = y;
}

// =============================================================================
// Fused mid-section: pm/lv stats -> z -> z stats -> zx.
// =============================================================================
__global__ void __launch_bounds__(1024)
mid_fused(const float* __restrict__ pm, const float* __restrict__ lv,
          const float* __restrict__ epsin,
          const float* __restrict__ gm, const float* __restrict__ bm,
          const float* __restrict__ gl, const float* __restrict__ bl,
          const float* __restrict__ gx, const float* __restrict__ bxx,
          float* __restrict__ out_z, float* __restrict__ s_zx,
          float* __restrict__ out_zx)
{
    __shared__ float4 red[1024];
    __shared__ float st[12];
    const int tid = threadIdx.x;

    auto reduce4 = [&](float s0, float q0, float s1, float q1, int base) {
        red[tid] = make_float4(s0, q0, s1, q1);
        __syncthreads();
        for (int s = 512; s > 0; s >>= 1) {
            if (tid < s) {
                float4 a = red[tid], b2 = red[tid + s];
                red[tid] = make_float4(a.x + b2.x, a.y + b2.y, a.z + b2.z, a.w + b2.w);
            }
            __syncthreads();
        }
        if (tid == 0) {
            float4 r = red[0];
            float m0 = r.x / NB, m1 = r.z / NB;
            st[base + 0] = m0;
            st[base + 1] = m1;
            st[base + 2] = r.y / NB - m0 * m0;
            st[base + 3] = r.w / NB - m1 * m1;
        }
        __syncthreads();
    };

    {
        float s0 = 0, q0 = 0, s1 = 0, q1 = 0;
#pragma unroll
        for (int i = 0; i < 2; i++) {
            int r = tid + i * 1024;
            float x0 = pm[r * 2], x1 = pm[r * 2 + 1];
            s0 += x0; q0 += x0 * x0; s1 += x1; q1 += x1 * x1;
        }
        reduce4(s0, q0, s1, q1, 0);
    }
    {
        float s0 = 0, q0 = 0, s1 = 0, q1 = 0;
#pragma unroll
        for (int i = 0; i < 2; i++) {
            int r = tid + i * 1024;
            float x0 = lv[r * 2], x1 = lv[r * 2 + 1];
            s0 += x0; q0 += x0 * x0; s1 += x1; q1 += x1 * x1;
        }
        reduce4(s0, q0, s1, q1, 4);
    }
    float zr[2][2];
    {
        const float pmi0 = rsqrtf(st[2] + 1e-5f), pmi1 = rsqrtf(st[3] + 1e-5f);
        const float lvi0 = rsqrtf(st[6] + 1e-5f), lvi1 = rsqrtf(st[7] + 1e-5f);
        const float gm0 = gm[0], gm1 = gm[1], bm0 = bm[0], bm1 = bm[1];
        const float gl0 = gl[0], gl1 = gl[1], bl0 = bl[0], bl1 = bl[1];
        float s0 = 0, q0 = 0, s1 = 0, q1 = 0;
#pragma unroll
        for (int i = 0; i < 2; i++) {
            int r = tid + i * 1024;
            float p0 = gm0 * (pm[r * 2] - st[0]) * pmi0 + bm0;
            float p1 = gm1 * (pm[r * 2 + 1] - st[1]) * pmi1 + bm1;
            float l0 = gl0 * (lv[r * 2] - st[4]) * lvi0 + bl0;
            float l1 = gl1 * (lv[r * 2 + 1] - st[5]) * lvi1 + bl1;
            float z0 = p0 + sqrtf(expf(l0)) * epsin[r * 2];
            float z1 = p1 + sqrtf(expf(l1)) * epsin[r * 2 + 1];
            out_z[r * 2] = z0;
            out_z[r * 2 + 1] = z1;
            zr[i][0] = z0; zr[i][1] = z1;
            s0 += z0; q0 += z0 * z0; s1 += z1; q1 += z1 * z1;
        }
        reduce4(s0, q0, s1, q1, 8);
    }
    {
        const float zi0 = rsqrtf(st[10] + 1e-5f), zi1 = rsqrtf(st[11] + 1e-5f);
        const float gx0 = gx[0], gx1 = gx[1], bx0 = bxx[0], bx1 = bxx[1];
#pragma unroll
        for (int i = 0; i < 2; i++) {
            int r = tid + i * 1024;
            float y0 = gx0 * (zr[i][0] - st[8]) * zi0 + bx0;
            float y1 = gx1 * (zr[i][1] - st[9]) * zi1 + bx1;
            s_zx[r * 2] = y0;    s_zx[r * 2 + 1] = y1;
            out_zx[r * 2] = y0;  out_zx[r * 2 + 1] = y1;
        }
    }
}

// ---------------- theta (fp32 outputs + fp16 plane) --------------------------
__global__ void theta_kernel(const float* __restrict__ zx, const float* __restrict__ zc,
                             float* __restrict__ gtheta, float* __restrict__ otheta)
{
    __shared__ float sz[KK * 2];
    __shared__ float red[256];
    __shared__ float sth[KR];
    int n = blockIdx.x, tid = threadIdx.x;
    for (int i = tid; i < KK * 2; i += 256) sz[i] = zc[i];
    __syncthreads();
    float x0 = zx[n * 2], x1 = zx[n * 2 + 1];
    float l = -FLT_MAX;
    if (tid < KK) {
        float dx = x0 - sz[tid * 2];
        float dy = x1 - sz[tid * 2 + 1];
        l = -0.5f * (dx * dx + dy * dy);
    }
    red[tid] = l;
    __syncthreads();
    for (int st = 128; st > 0; st >>= 1) {
        if (tid < st) red[tid] = fmaxf(red[tid], red[tid + st]);
        __syncthreads();
    }
    float mx = red[0];
    __syncthreads();
    float e = (tid < KK) ? expf(l - mx) : 0.f;
    red[tid] = e;
    __syncthreads();
    for (int st = 128; st > 0; st >>= 1) {
        if (tid < st) red[tid] += red[tid + st];
        __syncthreads();
    }
    float inv = 1.f / red[0];
    float th = e * inv;
    if (tid < KK) {
        gtheta[(size_t)n * KK + tid] = th;
        otheta[(size_t)n * KK + tid] = th;
    }
    if (tid < KR) sth[tid] = (tid < KK) ? th : 0.f;
    __syncthreads();
    if (tid < KRW) {
        g_bf[W_TH + (size_t)n * KRW + tid] =
            pk_h2(__float2half_rn(sth[2 * tid]), __float2half_rn(sth[2 * tid + 1]));
    }
}

// ---------------- decoder MLP ------------------------------------------------
__global__ void mu1_kernel(const float* __restrict__ zc, const float* __restrict__ W,
                           const float* __restrict__ b, float* __restrict__ out)
{
    int t = blockIdx.x * 256 + threadIdx.x;
    if (t >= KK * 100) return;
    int k = t / 100, j = t % 100;
    float v = zc[k * 2] * W[j * 2] + zc[k * 2 + 1] * W[j * 2 + 1] + b[j];
    out[t] = softplusf(v);
}

__global__ void mu2_kernel(const float* __restrict__ mu1, const float* __restrict__ W,
                           const float* __restrict__ b, float* __restrict__ out)
{
    __shared__ float row[100];
    int k = blockIdx.x, tid = threadIdx.x;
    if (tid < 100) row[tid] = mu1[k * 100 + tid];
    __syncthreads();
    if (tid < 100) {
        const float* w = W + tid * 100;
        float s = b[tid];
        for (int i = 0; i < 100; i++) s += row[i] * w[i];
        out[k * 100 + tid] = softplusf(s);
    }
}

__global__ void muz_kernel(const float* __restrict__ mu2, const float* __restrict__ W,
                           const float* __restrict__ b, float* __restrict__ out)
{
    __shared__ float row[100];
    int k = blockIdx.x, tid = threadIdx.x;
    if (tid < 100) row[tid] = mu2[k * 100 + tid];
    __syncthreads();
    for (int j = tid; j < EMB; j += 128) {
        const float* w = W + j * 100;
        float s = b[j];
        for (int i = 0; i < 100; i++) s += row[i] * w[i];
        out[k * EMB + j] = s;
    }
}

// =============================================================================
// beta: BN_topic + softmax, exp-once version.
// Pass 1: sum/sumsq/max/min of logits + max of bbias (one sweep).
// Pass 2: e = exp(y - mx̂) stored to beta, accumulate sum.
// Pass 3: scale by 1/sum.
// mx̂ = scale*(scale>0?max:min) + shift + max(bb) ≥ max(y) — softmax is
// shift-invariant so result is exact.
// =============================================================================
__global__ void __launch_bounds__(1024)
beta_kernel(const float* __restrict__ logits, const float* __restrict__ bbias,
            const float* __restrict__ gdec, const float* __restrict__ bdec,
            float* __restrict__ beta)
{
    __shared__ float rs[1024], rq[1024], rmx[1024], rmn[1024], rmb[1024];
    const int k = blockIdx.x, tid = threadIdx.x;
    const float* row = logits + (size_t)k * VV;
    const float* bb  = bbias + (size_t)k * VV;
    float* brow = beta + (size_t)k * VV;

    // pass 1: stats + bounds
    float s = 0.f, q = 0.f, mxx = -FLT_MAX, mnx = FLT_MAX, mxb = -FLT_MAX;
    for (int v = tid; v < VV; v += 1024) {
        float x = row[v];
        s += x; q += x * x;
        mxx = fmaxf(mxx, x);
        mnx = fminf(mnx, x);
        mxb = fmaxf(mxb, bb[v]);
    }
    rs[tid] = s; rq[tid] = q; rmx[tid] = mxx; rmn[tid] = mnx; rmb[tid] = mxb;
    __syncthreads();
    for (int st = 512; st > 0; st >>= 1) {
        if (tid < st) {
            rs[tid] += rs[tid + st];
            rq[tid] += rq[tid + st];
            rmx[tid] = fmaxf(rmx[tid], rmx[tid + st]);
            rmn[tid] = fminf(rmn[tid], rmn[tid + st]);
            rmb[tid] = fmaxf(rmb[tid], rmb[tid + st]);
        }
        __syncthreads();
    }
    const float mean = rs[0] / VV;
    const float var  = rq[0] / VV - mean * mean;
    const float scale = gdec[k] * rsqrtf(var + 1e-5f);
    const float shift = bdec[k] - mean * scale;
    const float mx = scale * (scale > 0.f ? rmx[0] : rmn[0]) + shift + rmb[0];
    __syncthreads();

    // pass 2: exp once, store, accumulate
    float se = 0.f;
    for (int v = tid; v < VV; v += 1024) {
        float e = expf(row[v] * scale + shift + bb[v] - mx);
        brow[v] = e;
        se += e;
    }
    rs[tid] = se;
    __syncthreads();
    for (int st = 512; st > 0; st >>= 1) {
        if (tid < st) rs[tid] += rs[tid + st];
        __syncthreads();
    }
    const float inv = 1.f / rs[0];

    // pass 3: normalize
    for (int v = tid; v < VV; v += 1024)
        brow[v] *= inv;
}

// ---------------- launch -----------------------------------------------------
extern "C" void kernel_launch(void* const* d_in, const int* in_sizes, int n_in,
                              void* d_out, int out_size)
{
    const float* input_   = (const float*)d_in[0];
    const float* eps      = (const float*)d_in[2];
    const float* en1_W    = (const float*)d_in[3];
    const float* en1_b    = (const float*)d_in[4];
    const float* en2_W    = (const float*)d_in[5];
    const float* en2_b    = (const float*)d_in[6];
    const float* mean_W   = (const float*)d_in[7];
    const float* mean_b   = (const float*)d_in[8];
    const float* logvar_W = (const float*)d_in[9];
    const float* logvar_b = (const float*)d_in[10];
    const float* mu1_W    = (const float*)d_in[11];
    const float* mu1_b    = (const float*)d_in[12];
    const float* mu2_W    = (const float*)d_in[13];
    const float* mu2_b    = (const float*)d_in[14];
    const float* mu_W     = (const float*)d_in[15];
    const float* mu_b     = (const float*)d_in[16];
    const float* topics   = (const float*)d_in[17];
    const float* bbias    = (const float*)d_in[18];
    const float* emb      = (const float*)d_in[19];
    const float* g_mean   = (const float*)d_in[20];
    const float* b_mean   = (const float*)d_in[21];
    const float* g_logvar = (const float*)d_in[22];
    const float* b_logvar = (const float*)d_in[23];
    const float* g_x      = (const float*)d_in[24];
    const float* b_x      = (const float*)d_in[25];
    const float* g_phi    = (const float*)d_in[26];
    const float* b_phi    = (const float*)d_in[27];
    const float* g_dec    = (const float*)d_in[28];
    const float* b_dec    = (const float*)d_in[29];

    float* out = (float*)d_out;
    float* out_z     = out;
    float* out_recon = out + (long long)NB * CC;
    float* out_zx    = out_recon + (long long)NB * VV;
    float* out_zc    = out_zx + (long long)NB * CC;
    float* out_theta = out_zc + (long long)KK * CC;

    void* sp = nullptr;
    cudaGetSymbolAddress(&sp, g_scratch);
    float* S = (float*)sp;
    float* s_en1    = S + OFF_EN1;
    float* s_en2    = S + OFF_EN2;
    float* s_pm     = S + OFF_PM;
    float* s_lv     = S + OFF_LV;
    float* s_zx     = S + OFF_ZX;
    float* s_zc     = S + OFF_ZC;
    float* s_theta  = S + OFF_THETA;
    float* s_mu1    = S + OFF_MU1;
    float* s_mu2    = S + OFF_MU2;
    float* s_muz    = S + OFF_MUZ;
    float* s_logits = S + OFF_LOGITS;
    float* s_beta   = S + OFF_BETA;
    float* st_t     = S + OFF_ST;

    cudaFuncSetAttribute(gemm1_fp16, cudaFuncAttributeMaxDynamicSharedMemorySize, G1_SMEM);
    cudaFuncSetAttribute(recon_f16, cudaFuncAttributeMaxDynamicSharedMemorySize, G1_SMEM);
    cudaFuncSetAttribute(gemm_nt_bf16x3<true, true, false>,
                         cudaFuncAttributeMaxDynamicSharedMemorySize, NTB_SMEM);

    // 0) pre-split: A -> 1 fp16 plane, B -> 1 fp16 plane
    split_fp16<<<NB + E1, 256>>>(input_, en1_W);

    // 1-4) decoder-side small kernels
    colstats_kernel<<<2, 256>>>(topics, KK, st_t);
    bn_apply_kernel<<<(KK * CC + 255) / 256, 256>>>(topics, st_t, g_phi, b_phi, KK * CC, s_zc, out_zc);
    mu1_kernel<<<(KK * 100 + 255) / 256, 256>>>(s_zc, mu1_W, mu1_b, s_mu1);
    mu2_kernel<<<KK, 128>>>(s_mu1, mu2_W, mu2_b, s_mu2);

    // 5) en1 = softplus(input @ en1_W^T + b) — plain fp16
    gemm1_fp16<<<dim3(E1 / 128, NB / 128), 256, G1_SMEM>>>(en1_b, s_en1);

    // 6) muz
    muz_kernel<<<KK, 128>>>(s_mu2, mu_W, mu_b, s_muz);

    // 7) en2 — bf16x3
    gemm_nt_bf16x3<true, true, false><<<dim3(E2 / 128, NB / 128), 512, NTB_SMEM>>>(
        s_en1, en2_W, en2_b, s_en2, NB, E2, E1);

    // 8) heads
    meanlogvar_kernel<<<(NB * 4 + 255) / 256, 256>>>(
        s_en2, mean_W, mean_b, logvar_W, logvar_b, s_pm, s_lv);

    // 9) fused mid-section
    mid_fused<<<1, 1024>>>(s_pm, s_lv, eps, g_mean, b_mean, g_logvar, b_logvar,
                           g_x, b_x, out_z, s_zx, out_zx);

    // 10) theta
    theta_kernel<<<NB, 256>>>(s_zx, s_zc, s_theta, out_theta);

    // 11) logits = mu_z @ emb^T — tf32 single pass
    logits_tf32<<<dim3((VV + 63) / 64, (KK + 63) / 64), 256>>>(s_muz, emb, s_logits);

    // 12) beta — exp-once
    beta_kernel<<<KK, 1024>>>(s_logits, bbias, g_dec, b_dec, s_beta);

    // 13) beta^T fp16
    transpose_beta<<<dim3(BTROWS / 32, KR / 32), 256>>>(s_beta);

    // 14) recon = theta @ beta — fp16 NT
    recon_f16<<<dim3(BTROWS / 128, NB / 128), 256, G1_SMEM>>>(out_recon);

    (void)in_sizes; (void)n_in; (void)out_size;
}

// round 14
// speedup vs baseline: 1.5588x; 1.1914x over previous
#include <cuda_runtime.h>
#include <cuda_bf16.h>
#include <cuda_fp16.h>
#include <math.h>
#include <float.h>
#include <stdint.h>

// ---------------- problem dims ----------------
#define NB   2048
#define VV   50000
#define E1   1024
#define E2   512
#define CC   2
#define KK   200
#define EMB  300

#define KP   50048
#define KPW  (KP/2)
#define G1NT (KP / 32)
#define SK   8                   // split-K factor for gemm1

#define KR   224
#define KRW  (KR/2)
#define RNT  (KR / 32)
#define BTROWS 50048

// ---------------- float scratch ----------------------------------------------
#define OFF_EN1    0LL
#define OFF_EN2    (OFF_EN1 + (long long)NB*E1)
#define OFF_PM     (OFF_EN2 + (long long)NB*E2)
#define OFF_LV     (OFF_PM + (long long)NB*CC)
#define OFF_Z      (OFF_LV + (long long)NB*CC)
#define OFF_ZX     (OFF_Z + (long long)NB*CC)
#define OFF_ZC     (OFF_ZX + (long long)NB*CC)
#define OFF_THETA  (OFF_ZC + (long long)KK*CC)
#define OFF_MU1    (OFF_THETA + (long long)NB*KK)
#define OFF_MU2    (OFF_MU1 + (long long)KK*100)
#define OFF_MUZ    (OFF_MU2 + (long long)KK*100)
#define OFF_LOGITS (OFF_MUZ + (long long)KK*EMB)
#define OFF_BETA   (OFF_LOGITS + (long long)KK*VV)
#define OFF_SPM    (OFF_BETA + (long long)KK*VV)
#define OFF_SLV    (OFF_SPM + 4)
#define OFF_SZ     (OFF_SLV + 4)
#define OFF_ST     (OFF_SZ + 4)
#define SCRATCH_FLOATS (OFF_ST + 8)

__device__ float g_scratch[SCRATCH_FLOATS];

// split-K partial planes for gemm1: SK x [NB x E1] fp32 (67 MB)
__device__ __align__(16) float g_part[(long long)SK * NB * E1];

// ---------------- fp16 planes (words) ----------------------------------------
#define WA 51249152LL
#define WB 25624576LL
#define W_AH 0LL
#define W_BH (W_AH + WA)
#define W_TH (W_BH + WB)
#define TWH  ((long long)NB * KRW)
#define W_BT (W_TH + TWH)
#define BTWH ((long long)BTROWS * KRW)

__device__ __align__(16) uint32_t g_bf[WA + WB + TWH + BTWH];

__device__ __forceinline__ float softplusf(float x) {
    return fmaxf(x, 0.0f) + log1pf(expf(-fabsf(x)));
}

__device__ __forceinline__ uint32_t pk_h2(__half lo, __half hi) {
    return ((uint32_t)__half_as_ushort(hi) << 16) | __half_as_ushort(lo);
}

__device__ __forceinline__ uint32_t pk_bf16(float lo, float hi) {
    uint32_t r;
    asm("cvt.rn.bf16x2.f32 %0, %1, %2;" : "=r"(r) : "f"(hi), "f"(lo));
    return r;
}

__device__ __forceinline__ unsigned tf32_rna(float x) {
    unsigned r;
    asm("cvt.rna.tf32.f32 %0, %1;" : "=r"(r) : "f"(x));
    return r;
}

__device__ __forceinline__ void mma_f16(float* d,
                                        uint32_t a0, uint32_t a1, uint32_t a2, uint32_t a3,
                                        uint32_t b0, uint32_t b1)
{
    asm volatile(
        "mma.sync.aligned.m16n8k16.row.col.f32.f16.f16.f32 "
        "{%0,%1,%2,%3},{%4,%5,%6,%7},{%8,%9},{%0,%1,%2,%3};"
        : "+f"(d[0]), "+f"(d[1]), "+f"(d[2]), "+f"(d[3])
        : "r"(a0), "r"(a1), "r"(a2), "r"(a3), "r"(b0), "r"(b1));
}

__device__ __forceinline__ void mma_bf16(float* d,
                                         uint32_t a0, uint32_t a1, uint32_t a2, uint32_t a3,
                                         uint32_t b0, uint32_t b1)
{
    asm volatile(
        "mma.sync.aligned.m16n8k16.row.col.f32.bf16.bf16.f32 "
        "{%0,%1,%2,%3},{%4,%5,%6,%7},{%8,%9},{%0,%1,%2,%3};"
        : "+f"(d[0]), "+f"(d[1]), "+f"(d[2]), "+f"(d[3])
        : "r"(a0), "r"(a1), "r"(a2), "r"(a3), "r"(b0), "r"(b1));
}

__device__ __forceinline__ void mma_tf32(float* d,
                                         unsigned a0, unsigned a1, unsigned a2, unsigned a3,
                                         unsigned b0, unsigned b1)
{
    asm volatile(
        "mma.sync.aligned.m16n8k8.row.col.f32.tf32.tf32.f32 "
        "{%0,%1,%2,%3},{%4,%5,%6,%7},{%8,%9},{%0,%1,%2,%3};"
        : "+f"(d[0]), "+f"(d[1]), "+f"(d[2]), "+f"(d[3])
        : "r"(a0), "r"(a1), "r"(a2), "r"(a3), "r"(b0), "r"(b1));
}

__device__ __forceinline__ void ldsm_x4(uint32_t& r0, uint32_t& r1, uint32_t& r2,
                                        uint32_t& r3, uint32_t addr)
{
    asm volatile("ldmatrix.sync.aligned.m8n8.x4.shared.b16 {%0,%1,%2,%3}, [%4];"
                 : "=r"(r0), "=r"(r1), "=r"(r2), "=r"(r3) : "r"(addr));
}

// =============================================================================
// Pre-pass: A=input, B=en1_W -> fp16 planes, zero pad.
// =============================================================================
__global__ void __launch_bounds__(256)
split_fp16(const float* __restrict__ A, const float* __restrict__ B)
{
    const int b = blockIdx.x, tid = threadIdx.x;
    const float* src;
    uint32_t* h;
    if (b < NB) {
        src = A + (size_t)b * VV;
        h = g_bf + W_AH + (size_t)b * KPW;
    } else {
        int r = b - NB;
        src = B + (size_t)r * VV;
        h = g_bf + W_BH + (size_t)r * KPW;
    }
    for (int i = tid; i < VV / 4; i += 256) {
        float4 v = *reinterpret_cast<const float4*>(src + i * 4);
        h[2*i]     = pk_h2(__float2half_rn(v.x), __float2half_rn(v.y));
        h[2*i + 1] = pk_h2(__float2half_rn(v.z), __float2half_rn(v.w));
    }
    if (tid < KPW - VV/2) h[VV/2 + tid] = 0u;
}

// =============================================================================
// GEMM1 split-K: partial[ks] = input @ en1_W^T over k-range of split ks.
// Block tile 128x128, BK=32, 256 threads, grid (8,16,SK) = 1024 CTAs.
// =============================================================================
#define STG    20480
#define G1_SMEM (3 * STG)

__global__ void __launch_bounds__(256, 2)
gemm1_fp16_sk()
{
    extern __shared__ __align__(16) char sm[];
    const uint32_t sb32 = (uint32_t)__cvta_generic_to_shared(sm);
    const int tid = threadIdx.x;
    const int lane = tid & 31, warp = tid >> 5;
    const int gid = lane >> 2, tig = lane & 3;
    const int wm = warp >> 1, wn = warp & 1;
    const int m0 = blockIdx.y * 128, n0 = blockIdx.x * 128;
    const int ks = blockIdx.z;
    const int ts = (G1NT * ks) / SK;
    const int te = (G1NT * (ks + 1)) / SK;

    float acc[2][8][4];
#pragma unroll
    for (int i = 0; i < 2; i++)
#pragma unroll
        for (int j = 0; j < 8; j++)
#pragma unroll
            for (int l = 0; l < 4; l++) acc[i][j][l] = 0.0f;

    const uint32_t* gsrc[4];
    uint32_t sdst[4];
#pragma unroll
    for (int i = 0; i < 2; i++) {
        int idx = tid + i * 256;
        int r = idx >> 2, part = idx & 3;
        gsrc[i] = g_bf + W_AH + (size_t)(m0 + r) * KPW + part * 4;
        sdst[i] = sb32 + (uint32_t)(r * 80 + part * 16);
    }
#pragma unroll
    for (int i = 0; i < 2; i++) {
        int idx = tid + i * 256;
        int r = idx >> 2, part = idx & 3;
        gsrc[2 + i] = g_bf + W_BH + (size_t)(n0 + r) * KPW + part * 4;
        sdst[2 + i] = sb32 + (uint32_t)(10240 + r * 80 + part * 16);
    }

    auto issue = [&](int t) {
        const uint32_t boff = (uint32_t)(t % 3) * STG;
        const size_t k = (size_t)t * 16;
#pragma unroll
        for (int i = 0; i < 4; i++)
            asm volatile("cp.async.cg.shared.global [%0], [%1], 16;"
                         :: "r"(sdst[i] + boff), "l"(gsrc[i] + k) : "memory");
        asm volatile("cp.async.commit_group;" ::: "memory");
    };

    const int lr = (lane & 7) + ((lane >> 3) & 1) * 8;
    const int kb = ((lane >> 4) & 1) * 16;
    const uint32_t aoff = (uint32_t)((wm * 32 + lr) * 80 + kb);
    const uint32_t boff2 = (uint32_t)(10240 + (wn * 64 + lr) * 80 + kb);

    issue(ts);
    issue(ts + 1);

    for (int t = ts; t < te; t++) {
        if (t == te - 1) asm volatile("cp.async.wait_group 0;" ::: "memory");
        else             asm volatile("cp.async.wait_group 1;" ::: "memory");
        __syncthreads();
        if (t + 2 < te) issue(t + 2);

        const uint32_t st = sb32 + (uint32_t)(t % 3) * STG;
#pragma unroll
        for (int kkw = 0; kkw < 2; kkw++) {
            const uint32_t ka = st + kkw * 32;
            uint32_t ah[2][4], bq[4][4];
#pragma unroll
            for (int ms = 0; ms < 2; ms++)
                ldsm_x4(ah[ms][0], ah[ms][1], ah[ms][2], ah[ms][3],
                        ka + aoff + ms * 1280);
#pragma unroll
            for (int pr = 0; pr < 4; pr++)
                ldsm_x4(bq[pr][0], bq[pr][1], bq[pr][2], bq[pr][3],
                        ka + boff2 + pr * 1280);
#pragma unroll
            for (int ms = 0; ms < 2; ms++)
#pragma unroll
                for (int pr = 0; pr < 4; pr++)
#pragma unroll
                    for (int j = 0; j < 2; j++) {
                        int ns = pr * 2 + j;
                        mma_f16(acc[ms][ns], ah[ms][0], ah[ms][1], ah[ms][2], ah[ms][3],
                                bq[pr][j], bq[pr][j + 2]);
                    }
        }
    }

    // epilogue: raw partial
    float* P = g_part + (size_t)ks * NB * E1;
#pragma unroll
    for (int ms = 0; ms < 2; ms++) {
        const int r0 = m0 + wm * 32 + ms * 16 + gid;
#pragma unroll
        for (int ns = 0; ns < 8; ns++) {
            const int c0 = n0 + wn * 64 + ns * 8 + 2 * tig;
            P[(size_t)r0 * E1 + c0]           = acc[ms][ns][0];
            P[(size_t)r0 * E1 + c0 + 1]       = acc[ms][ns][1];
            P[(size_t)(r0 + 8) * E1 + c0]     = acc[ms][ns][2];
            P[(size_t)(r0 + 8) * E1 + c0 + 1] = acc[ms][ns][3];
        }
    }
}

// =============================================================================
// reduce partials + bias + softplus -> en1
// =============================================================================
__global__ void __launch_bounds__(256)
reduce_en1(const float* __restrict__ bias, float* __restrict__ C)
{
    const size_t i = (size_t)blockIdx.x * 256 + threadIdx.x;   // float4 index
    float4 s = reinterpret_cast<const float4*>(g_part)[i];
#pragma unroll
    for (int p = 1; p < SK; p++) {
        float4 v = reinterpret_cast<const float4*>(g_part + (size_t)p * NB * E1)[i];
        s.x += v.x; s.y += v.y; s.z += v.z; s.w += v.w;
    }
    const int c = (int)((i * 4) & (E1 - 1));
    s.x = softplusf(s.x + bias[c]);
    s.y = softplusf(s.y + bias[c + 1]);
    s.z = softplusf(s.z + bias[c + 2]);
    s.w = softplusf(s.w + bias[c + 3]);
    reinterpret_cast<float4*>(C)[i] = s;
}

// =============================================================================
// recon = theta @ beta via NT fp16 planes.
// =============================================================================
__global__ void __launch_bounds__(256, 2)
recon_f16(float* __restrict__ C)
{
    extern __shared__ __align__(16) char sm[];
    const uint32_t sb32 = (uint32_t)__cvta_generic_to_shared(sm);
    const int tid = threadIdx.x;
    const int lane = tid & 31, warp = tid >> 5;
    const int gid = lane >> 2, tig = lane & 3;
    const int wm = warp >> 1, wn = warp & 1;
    const int m0 = blockIdx.y * 128, n0 = blockIdx.x * 128;

    float acc[2][8][4];
#pragma unroll
    for (int i = 0; i < 2; i++)
#pragma unroll
        for (int j = 0; j < 8; j++)
#pragma unroll
            for (int l = 0; l < 4; l++) acc[i][j][l] = 0.0f;

    const uint32_t* gsrc[4];
    uint32_t sdst[4];
#pragma unroll
    for (int i = 0; i < 2; i++) {
        int idx = tid + i * 256;
        int r = idx >> 2, part = idx & 3;
        gsrc[i] = g_bf + W_TH + (size_t)(m0 + r) * KRW + part * 4;
        sdst[i] = sb32 + (uint32_t)(r * 80 + part * 16);
    }
#pragma unroll
    for (int i = 0; i < 2; i++) {
        int idx = tid + i * 256;
        int r = idx >> 2, part = idx & 3;
        gsrc[2 + i] = g_bf + W_BT + (size_t)(n0 + r) * KRW + part * 4;
        sdst[2 + i] = sb32 + (uint32_t)(10240 + r * 80 + part * 16);
    }

    auto issue = [&](int t) {
        const uint32_t boff = (uint32_t)(t % 3) * STG;
        const size_t k = (size_t)t * 16;
#pragma unroll
        for (int i = 0; i < 4; i++)
            asm volatile("cp.async.cg.shared.global [%0], [%1], 16;"
                         :: "r"(sdst[i] + boff), "l"(gsrc[i] + k) : "memory");
        asm volatile("cp.async.commit_group;" ::: "memory");
    };

    const int lr = (lane & 7) + ((lane >> 3) & 1) * 8;
    const int kb = ((lane >> 4) & 1) * 16;
    const uint32_t aoff = (uint32_t)((wm * 32 + lr) * 80 + kb);
    const uint32_t boff2 = (uint32_t)(10240 + (wn * 64 + lr) * 80 + kb);

    issue(0);
    issue(1);

    for (int t = 0; t < RNT; t++) {
        if (t == RNT - 1) asm volatile("cp.async.wait_group 0;" ::: "memory");
        else              asm volatile("cp.async.wait_group 1;" ::: "memory");
        __syncthreads();
        if (t + 2 < RNT) issue(t + 2);

        const uint32_t st = sb32 + (uint32_t)(t % 3) * STG;
#pragma unroll
        for (int kkw = 0; kkw < 2; kkw++) {
            const uint32_t ka = st + kkw * 32;
            uint32_t ah[2][4], bq[4][4];
#pragma unroll
            for (int ms = 0; ms < 2; ms++)
                ldsm_x4(ah[ms][0], ah[ms][1], ah[ms][2], ah[ms][3],
                        ka + aoff + ms * 1280);
#pragma unroll
            for (int pr = 0; pr < 4; pr++)
                ldsm_x4(bq[pr][0], bq[pr][1], bq[pr][2], bq[pr][3],
                        ka + boff2 + pr * 1280);
#pragma unroll
            for (int ms = 0; ms < 2; ms++)
#pragma unroll
                for (int pr = 0; pr < 4; pr++)
#pragma unroll
                    for (int j = 0; j < 2; j++) {
                        int ns = pr * 2 + j;
                        mma_f16(acc[ms][ns], ah[ms][0], ah[ms][1], ah[ms][2], ah[ms][3],
                                bq[pr][j], bq[pr][j + 2]);
                    }
        }
    }

#pragma unroll
    for (int ms = 0; ms < 2; ms++) {
        const int r0 = m0 + wm * 32 + ms * 16 + gid;
#pragma unroll
        for (int ns = 0; ns < 8; ns++) {
            const int c0 = n0 + wn * 64 + ns * 8 + 2 * tig;
            if (c0 < VV) {
                C[(size_t)r0 * VV + c0]       = acc[ms][ns][0];
                C[(size_t)(r0 + 8) * VV + c0] = acc[ms][ns][2];
            }
            if (c0 + 1 < VV) {
                C[(size_t)r0 * VV + c0 + 1]       = acc[ms][ns][1];
                C[(size_t)(r0 + 8) * VV + c0 + 1] = acc[ms][ns][3];
            }
        }
    }
}

// =============================================================================
// beta^T fp16
// =============================================================================
__global__ void __launch_bounds__(256)
transpose_beta(const float* __restrict__ beta)
{
    __shared__ float s[32][33];
    const int tid = threadIdx.x;
    const int tx = tid & 31, ty = tid >> 5;
    const int v0 = blockIdx.x * 32, k0 = blockIdx.y * 32;

#pragma unroll
    for (int i = 0; i < 4; i++) {
        int k = ty + i * 8;
        int gk = k0 + k, gv = v0 + tx;
        float val = 0.f;
        if (gk < KK && gv < VV) val = beta[(size_t)gk * VV + gv];
        s[k][tx] = val;
    }
    __syncthreads();

#pragma unroll
    for (int i = 0; i < 2; i++) {
        int w = tid + i * 256;
        int v = w >> 4, kw = w & 15;
        uint32_t word = pk_h2(__float2half_rn(s[2 * kw][v]),
                              __float2half_rn(s[2 * kw + 1][v]));
        g_bf[W_BT + (size_t)(v0 + v) * KRW + (k0 >> 1) + kw] = word;
    }
}

// =============================================================================
// logits = mu_z[200,300] @ emb[50000,300]^T — single-pass tf32.
// =============================================================================
__global__ void __launch_bounds__(256)
logits_tf32(const float* __restrict__ A, const float* __restrict__ B,
            float* __restrict__ C)
{
    __shared__ float As[64][20];
    __shared__ float Bs[64][20];
    const int tid = threadIdx.x;
    const int lane = tid & 31, warp = tid >> 5;
    const int gid = lane >> 2, tig = lane & 3;
    const int wm = warp >> 1, wn = warp & 1;
    const int m0 = blockIdx.y * 64, n0 = blockIdx.x * 64;

    float acc[4][4];
#pragma unroll
    for (int j = 0; j < 4; j++)
#pragma unroll
        for (int l = 0; l < 4; l++) acc[j][l] = 0.0f;

    const int row = tid >> 2, q = (tid & 3) * 4;

    for (int k0 = 0; k0 < EMB; k0 += 16) {
        const int gk = k0 + q;
        {
            int gm = m0 + row;
            float4 v = make_float4(0.f, 0.f, 0.f, 0.f);
            if (gm < KK) {
                const float* p = A + (size_t)gm * EMB;
                if (gk + 3 < EMB) v = *reinterpret_cast<const float4*>(p + gk);
                else {
                    if (gk + 0 < EMB) v.x = p[gk + 0];
                    if (gk + 1 < EMB) v.y = p[gk + 1];
                    if (gk + 2 < EMB) v.z = p[gk + 2];
                    if (gk + 3 < EMB) v.w = p[gk + 3];
                }
            }
            As[row][q + 0] = __uint_as_float(tf32_rna(v.x));
            As[row][q + 1] = __uint_as_float(tf32_rna(v.y));
            As[row][q + 2] = __uint_as_float(tf32_rna(v.z));
            As[row][q + 3] = __uint_as_float(tf32_rna(v.w));
        }
        {
            int gn = n0 + row;
            float4 v = make_float4(0.f, 0.f, 0.f, 0.f);
            if (gn < VV) {
                const float* p = B + (size_t)gn * EMB;
                if (gk + 3 < EMB) v = *reinterpret_cast<const float4*>(p + gk);
                else {
                    if (gk + 0 < EMB) v.x = p[gk + 0];
                    if (gk + 1 < EMB) v.y = p[gk + 1];
                    if (gk + 2 < EMB) v.z = p[gk + 2];
                    if (gk + 3 < EMB) v.w = p[gk + 3];
                }
            }
            Bs[row][q + 0] = __uint_as_float(tf32_rna(v.x));
            Bs[row][q + 1] = __uint_as_float(tf32_rna(v.y));
            Bs[row][q + 2] = __uint_as_float(tf32_rna(v.z));
            Bs[row][q + 3] = __uint_as_float(tf32_rna(v.w));
        }
        __syncthreads();

#pragma unroll
        for (int kk = 0; kk < 16; kk += 8) {
            unsigned a[4], b[4][2];
            int r = wm * 16 + gid;
            a[0] = __float_as_uint(As[r][kk + tig]);
            a[1] = __float_as_uint(As[r + 8][kk + tig]);
            a[2] = __float_as_uint(As[r][kk + tig + 4]);
            a[3] = __float_as_uint(As[r + 8][kk + tig + 4]);
#pragma unroll
            for (int ns = 0; ns < 4; ns++) {
                int n = wn * 32 + ns * 8 + gid;
                b[ns][0] = __float_as_uint(Bs[n][kk + tig]);
                b[ns][1] = __float_as_uint(Bs[n][kk + tig + 4]);
            }
#pragma unroll
            for (int ns = 0; ns < 4; ns++)
                mma_tf32(acc[ns], a[0], a[1], a[2], a[3], b[ns][0], b[ns][1]);
        }
        __syncthreads();
    }

    const int r0 = m0 + wm * 16 + gid;
#pragma unroll
    for (int ns = 0; ns < 4; ns++) {
        const int c0 = n0 + wn * 32 + ns * 8 + 2 * tig;
        if (r0 < KK) {
            if (c0 < VV)     C[(size_t)r0 * VV + c0]     = acc[ns][0];
            if (c0 + 1 < VV) C[(size_t)r0 * VV + c0 + 1] = acc[ns][1];
        }
        if (r0 + 8 < KK) {
            if (c0 < VV)     C[(size_t)(r0 + 8) * VV + c0]     = acc[ns][2];
            if (c0 + 1 < VV) C[(size_t)(r0 + 8) * VV + c0 + 1] = acc[ns][3];
        }
    }
}

// ============================ bf16x3 NT GEMM (en2) ===========================
#define NTB_SMEM (2 * 10240 * 4)

template<bool SP, bool HB, bool CHKMN>
__global__ void __launch_bounds__(512, 1)
gemm_nt_bf16x3(const float* __restrict__ A, const float* __restrict__ B,
               const float* __restrict__ bias, float* __restrict__ C,
               int M, int N, int K)
{
    extern __shared__ __align__(16) uint32_t sw[];
    const int tid = threadIdx.x;
    const int lane = tid & 31, warp = tid >> 5;
    const int gid = lane >> 2, tig = lane & 3;
    const int wm = warp >> 2, wn = warp & 3;
    const int m0 = blockIdx.y * 128, n0 = blockIdx.x * 128;
    const int nt = (K + 31) / 32;

    float acc[2][4][4];
#pragma unroll
    for (int i = 0; i < 2; i++)
#pragma unroll
        for (int j = 0; j < 4; j++)
#pragma unroll
            for (int l = 0; l < 4; l++) acc[i][j][l] = 0.0f;

    const int srow = tid >> 3;
    const int sq   = tid & 7;
    float4 stA[2], stB[2];

    auto load_tile = [&](int t) {
        const int gk = t * 32 + sq * 4;
#pragma unroll
        for (int l = 0; l < 2; l++) {
            int r = srow + l * 64;
            {
                int gm = m0 + r;
                float4 v = make_float4(0.f, 0.f, 0.f, 0.f);
                if (((!CHKMN) || gm < M)) {
                    if (gk + 3 < K) v = *reinterpret_cast<const float4*>(A + (size_t)gm * K + gk);
                    else if (gk < K) {
                        const float* p = A + (size_t)gm * K;
                        v.x = p[gk];
                        if (gk + 1 < K) v.y = p[gk + 1];
                        if (gk + 2 < K) v.z = p[gk + 2];
                    }
                }
                stA[l] = v;
            }
            {
                int gn = n0 + r;
                float4 v = make_float4(0.f, 0.f, 0.f, 0.f);
                if (((!CHKMN) || gn < N)) {
                    if (gk + 3 < K) v = *reinterpret_cast<const float4*>(B + (size_t)gn * K + gk);
                    else if (gk < K) {
                        const float* p = B + (size_t)gn * K;
                        v.x = p[gk];
                        if (gk + 1 < K) v.y = p[gk + 1];
                        if (gk + 2 < K) v.z = p[gk + 2];
                    }
                }
                stB[l] = v;
            }
        }
    };

    auto store_tile = [&](uint32_t* buf) {
#pragma unroll
        for (int l = 0; l < 2; l++) {
            int r = srow + l * 64;
            uint32_t w = (uint32_t)(r * 20 + sq * 2);
            {
                float4 v = stA[l];
                __nv_bfloat16 hx = __float2bfloat16_rn(v.x), hy = __float2bfloat16_rn(v.y);
                __nv_bfloat16 hz = __float2bfloat16_rn(v.z), hw = __float2bfloat16_rn(v.w);
                buf[w]     = ((uint32_t)__bfloat16_as_ushort(hy) << 16) | __bfloat16_as_ushort(hx);
                buf[w + 1] = ((uint32_t)__bfloat16_as_ushort(hw) << 16) | __bfloat16_as_ushort(hz);
                buf[w + 2560]     = pk_bf16(v.x - __bfloat162float(hx), v.y - __bfloat162float(hy));
                buf[w + 2560 + 1] = pk_bf16(v.z - __bfloat162float(hz), v.w - __bfloat162float(hw));
            }
            {
                float4 v = stB[l];
                __nv_bfloat16 hx = __float2bfloat16_rn(v.x), hy = __float2bfloat16_rn(v.y);
                __nv_bfloat16 hz = __float2bfloat16_rn(v.z), hw = __float2bfloat16_rn(v.w);
                buf[w + 5120]     = ((uint32_t)__bfloat16_as_ushort(hy) << 16) | __bfloat16_as_ushort(hx);
                buf[w + 5120 + 1] = ((uint32_t)__bfloat16_as_ushort(hw) << 16) | __bfloat16_as_ushort(hz);
                buf[w + 7680]     = pk_bf16(v.x - __bfloat162float(hx), v.y - __bfloat162float(hy));
                buf[w + 7680 + 1] = pk_bf16(v.z - __bfloat162float(hz), v.w - __bfloat162float(hw));
            }
        }
    };

    load_tile(0);
    store_tile(sw);
    __syncthreads();

    for (int t = 0; t < nt; t++) {
        const int b = t & 1;
        uint32_t* bb = sw + b * 10240;
        if (t + 1 < nt) load_tile(t + 1);

#pragma unroll
        for (int kkw = 0; kkw < 16; kkw += 8) {
            uint32_t ah[2][4], al[2][4], bh[4][2], bl[4][2];
#pragma unroll
            for (int ms = 0; ms < 2; ms++) {
                int base = (wm * 32 + ms * 16 + gid) * 20 + kkw + tig;
                ah[ms][0] = bb[base];       ah[ms][1] = bb[base + 160];
                ah[ms][2] = bb[base + 4];   ah[ms][3] = bb[base + 164];
                al[ms][0] = bb[base + 2560];       al[ms][1] = bb[base + 2560 + 160];
                al[ms][2] = bb[base + 2560 + 4];   al[ms][3] = bb[base + 2560 + 164];
            }
#pragma unroll
            for (int ns = 0; ns < 4; ns++) {
                int base = 5120 + (wn * 32 + ns * 8 + gid) * 20 + kkw + tig;
                bh[ns][0] = bb[base];       bh[ns][1] = bb[base + 4];
                bl[ns][0] = bb[base + 2560]; bl[ns][1] = bb[base + 2560 + 4];
            }
#pragma unroll
            for (int ms = 0; ms < 2; ms++)
#pragma unroll
                for (int ns = 0; ns < 4; ns++) {
                    mma_bf16(acc[ms][ns], ah[ms][0], ah[ms][1], ah[ms][2], ah[ms][3],
                             bh[ns][0], bh[ns][1]);
                    mma_bf16(acc[ms][ns], ah[ms][0], ah[ms][1], ah[ms][2], ah[ms][3],
                             bl[ns][0], bl[ns][1]);
                    mma_bf16(acc[ms][ns], al[ms][0], al[ms][1], al[ms][2], al[ms][3],
                             bh[ns][0], bh[ns][1]);
                }
        }

        if (t + 1 < nt) store_tile(sw + (b ^ 1) * 10240);
        __syncthreads();
    }

#pragma unroll
    for (int ms = 0; ms < 2; ms++) {
        int r0 = m0 + wm * 32 + ms * 16 + gid;
#pragma unroll
        for (int ns = 0; ns < 4; ns++) {
            int c0 = n0 + wn * 32 + ns * 8 + 2 * tig;
            float bv0 = 0.f, bv1 = 0.f;
            if (HB) { bv0 = bias[c0]; bv1 = bias[c0 + 1]; }
            float v00 = acc[ms][ns][0] + bv0;
            float v01 = acc[ms][ns][1] + bv1;
            float v10 = acc[ms][ns][2] + bv0;
            float v11 = acc[ms][ns][3] + bv1;
            if (SP) { v00 = softplusf(v00); v01 = softplusf(v01);
                      v10 = softplusf(v10); v11 = softplusf(v11); }
            if (!CHKMN) {
                C[(size_t)r0 * N + c0]           = v00;
                C[(size_t)r0 * N + c0 + 1]       = v01;
                C[(size_t)(r0 + 8) * N + c0]     = v10;
                C[(size_t)(r0 + 8) * N + c0 + 1] = v11;
            } else {
                if (r0 < M) {
                    if (c0 < N)     C[(size_t)r0 * N + c0]     = v00;
                    if (c0 + 1 < N) C[(size_t)r0 * N + c0 + 1] = v01;
                }
                if (r0 + 8 < M) {
                    if (c0 < N)     C[(size_t)(r0 + 8) * N + c0]     = v10;
                    if (c0 + 1 < N) C[(size_t)(r0 + 8) * N + c0 + 1] = v11;
                }
            }
        }
    }
}

// ---------------- mean / logvar heads ---------------------------------------
__global__ void meanlogvar_kernel(const float* __restrict__ en2,
                                  const float* __restrict__ mW, const float* __restrict__ mb,
                                  const float* __restrict__ lW, const float* __restrict__ lb,
                                  float* __restrict__ pm, float* __restrict__ lv)
{
    int t = blockIdx.x * blockDim.x + threadIdx.x;
    if (t >= NB * 4) return;
    int n = t >> 2, j = t & 3;
    const float* w = (j < 2) ? (mW + j * E2) : (lW + (j - 2) * E2);
    const float* x = en2 + (size_t)n * E2;
    float s = 0.f;
    for (int i = 0; i < E2; i += 4) {
        float4 xa = *reinterpret_cast<const float4*>(x + i);
        float4 wa = *reinterpret_cast<const float4*>(w + i);
        s += xa.x * wa.x + xa.y * wa.y + xa.z * wa.z + xa.w * wa.w;
    }
    if (j < 2) pm[n * 2 + j] = s + mb[j];
    else       lv[n * 2 + (j - 2)] = s + lb[j - 2];
}

// ---------------- column stats (topics) --------------------------------------
__global__ void colstats_kernel(const float* __restrict__ X, int R, float* __restrict__ out)
{
    __shared__ float ss[256], s2[256];
    int c = blockIdx.x, tid = threadIdx.x;
    float s = 0.f, q = 0.f;
    for (int r = tid; r < R; r += 256) {
        float x = X[r * 2 + c];
        s += x; q += x * x;
    }
    ss[tid] = s; s2[tid] = q;
    __syncthreads();
    for (int st = 128; st > 0; st >>= 1) {
        if (tid < st) { ss[tid] += ss[tid + st]; s2[tid] += s2[tid + st]; }
        __syncthreads();
    }
    if (tid == 0) {
        float m = ss[0] / R;
        out[c] = m;
        out[2 + c] = s2[0] / R - m * m;
    }
}

// ---------------- BN apply (zc) ----------------------------------------------
__global__ void bn_apply_kernel(const float* __restrict__ X, const float* __restrict__ stats,
                                const float* __restrict__ g, const float* __restrict__ b,
                                int total, float* __restrict__ o1, float* __restrict__ o2)
{
    int idx = blockIdx.x * 256 + threadIdx.x;
    if (idx >= total) return;
    int c = idx & 1;
    float y = g[c] * (X[idx] - stats[c]) * rsqrtf(stats[2 + c] + 1e-5f) + b[c];
    o1[idx] = y;
    o2[idx] = y;
}

// =============================================================================
// Fused mid-section: pm/lv stats -> z -> z stats -> zx.
// =============================================================================
__global__ void __launch_bounds__(1024)
mid_fused(const float* __restrict__ pm, const float* __restrict__ lv,
          const float* __restrict__ epsin,
          const float* __restrict__ gm, const float* __restrict__ bm,
          const float* __restrict__ gl, const float* __restrict__ bl,
          const float* __restrict__ gx, const float* __restrict__ bxx,
          float* __restrict__ out_z, float* __restrict__ s_zx,
          float* __restrict__ out_zx)
{
    __shared__ float4 red[1024];
    __shared__ float st[12];
    const int tid = threadIdx.x;

    auto reduce4 = [&](float s0, float q0, float s1, float q1, int base) {
        red[tid] = make_float4(s0, q0, s1, q1);
        __syncthreads();
        for (int s = 512; s > 0; s >>= 1) {
            if (tid < s) {
                float4 a = red[tid], b2 = red[tid + s];
                red[tid] = make_float4(a.x + b2.x, a.y + b2.y, a.z + b2.z, a.w + b2.w);
            }
            __syncthreads();
        }
        if (tid == 0) {
            float4 r = red[0];
            float m0 = r.x / NB, m1 = r.z / NB;
            st[base + 0] = m0;
            st[base + 1] = m1;
            st[base + 2] = r.y / NB - m0 * m0;
            st[base + 3] = r.w / NB - m1 * m1;
        }
        __syncthreads();
    };

    {
        float s0 = 0, q0 = 0, s1 = 0, q1 = 0;
#pragma unroll
        for (int i = 0; i < 2; i++) {
            int r = tid + i * 1024;
            float x0 = pm[r * 2], x1 = pm[r * 2 + 1];
            s0 += x0; q0 += x0 * x0; s1 += x1; q1 += x1 * x1;
        }
        reduce4(s0, q0, s1, q1, 0);
    }
    {
        float s0 = 0, q0 = 0, s1 = 0, q1 = 0;
#pragma unroll
        for (int i = 0; i < 2; i++) {
            int r = tid + i * 1024;
            float x0 = lv[r * 2], x1 = lv[r * 2 + 1];
            s0 += x0; q0 += x0 * x0; s1 += x1; q1 += x1 * x1;
        }
        reduce4(s0, q0, s1, q1, 4);
    }
    float zr[2][2];
    {
        const float pmi0 = rsqrtf(st[2] + 1e-5f), pmi1 = rsqrtf(st[3] + 1e-5f);
        const float lvi0 = rsqrtf(st[6] + 1e-5f), lvi1 = rsqrtf(st[7] + 1e-5f);
        const float gm0 = gm[0], gm1 = gm[1], bm0 = bm[0], bm1 = bm[1];
        const float gl0 = gl[0], gl1 = gl[1], bl0 = bl[0], bl1 = bl[1];
        float s0 = 0, q0 = 0, s1 = 0, q1 = 0;
#pragma unroll
        for (int i = 0; i < 2; i++) {
            int r = tid + i * 1024;
            float p0 = gm0 * (pm[r * 2] - st[0]) * pmi0 + bm0;
            float p1 = gm1 * (pm[r * 2 + 1] - st[1]) * pmi1 + bm1;
            float l0 = gl0 * (lv[r * 2] - st[4]) * lvi0 + bl0;
            float l1 = gl1 * (lv[r * 2 + 1] - st[5]) * lvi1 + bl1;
            float z0 = p0 + sqrtf(expf(l0)) * epsin[r * 2];
            float z1 = p1 + sqrtf(expf(l1)) * epsin[r * 2 + 1];
            out_z[r * 2] = z0;
            out_z[r * 2 + 1] = z1;
            zr[i][0] = z0; zr[i][1] = z1;
            s0 += z0; q0 += z0 * z0; s1 += z1; q1 += z1 * z1;
        }
        reduce4(s0, q0, s1, q1, 8);
    }
    {
        const float zi0 = rsqrtf(st[10] + 1e-5f), zi1 = rsqrtf(st[11] + 1e-5f);
        const float gx0 = gx[0], gx1 = gx[1], bx0 = bxx[0], bx1 = bxx[1];
#pragma unroll
        for (int i = 0; i < 2; i++) {
            int r = tid + i * 1024;
            float y0 = gx0 * (zr[i][0] - st[8]) * zi0 + bx0;
            float y1 = gx1 * (zr[i][1] - st[9]) * zi1 + bx1;
            s_zx[r * 2] = y0;    s_zx[r * 2 + 1] = y1;
            out_zx[r * 2] = y0;  out_zx[r * 2 + 1] = y1;
        }
    }
}

// ---------------- theta (fp32 outputs + fp16 plane) --------------------------
__global__ void theta_kernel(const float* __restrict__ zx, const float* __restrict__ zc,
                             float* __restrict__ gtheta, float* __restrict__ otheta)
{
    __shared__ float sz[KK * 2];
    __shared__ float red[256];
    __shared__ float sth[KR];
    int n = blockIdx.x, tid = threadIdx.x;
    for (int i = tid; i < KK * 2; i += 256) sz[i] = zc[i];
    __syncthreads();
    float x0 = zx[n * 2], x1 = zx[n * 2 + 1];
    float l = -FLT_MAX;
    if (tid < KK) {
        float dx = x0 - sz[tid * 2];
        float dy = x1 - sz[tid * 2 + 1];
        l = -0.5f * (dx * dx + dy * dy);
    }
    red[tid] = l;
    __syncthreads();
    for (int st = 128; st > 0; st >>= 1) {
        if (tid < st) red[tid] = fmaxf(red[tid], red[tid + st]);
        __syncthreads();
    }
    float mx = red[0];
    __syncthreads();
    float e = (tid < KK) ? expf(l - mx) : 0.f;
    red[tid] = e;
    __syncthreads();
    for (int st = 128; st > 0; st >>= 1) {
        if (tid < st) red[tid] += red[tid + st];
        __syncthreads();
    }
    float inv = 1.f / red[0];
    float th = e * inv;
    if (tid < KK) {
        gtheta[(size_t)n * KK + tid] = th;
        otheta[(size_t)n * KK + tid] = th;
    }
    if (tid < KR) sth[tid] = (tid < KK) ? th : 0.f;
    __syncthreads();
    if (tid < KRW) {
        g_bf[W_TH + (size_t)n * KRW + tid] =
            pk_h2(__float2half_rn(sth[2 * tid]), __float2half_rn(sth[2 * tid + 1]));
    }
}

// ---------------- decoder MLP ------------------------------------------------
__global__ void mu1_kernel(const float* __restrict__ zc, const float* __restrict__ W,
                           const float* __restrict__ b, float* __restrict__ out)
{
    int t = blockIdx.x * 256 + threadIdx.x;
    if (t >= KK * 100) return;
    int k = t / 100, j = t % 100;
    float v = zc[k * 2] * W[j * 2] + zc[k * 2 + 1] * W[j * 2 + 1] + b[j];
    out[t] = softplusf(v);
}

__global__ void mu2_kernel(const float* __restrict__ mu1, const float* __restrict__ W,
                           const float* __restrict__ b, float* __restrict__ out)
{
    __shared__ float row[100];
    int k = blockIdx.x, tid = threadIdx.x;
    if (tid < 100) row[tid] = mu1[k * 100 + tid];
    __syncthreads();
    if (tid < 100) {
        const float* w = W + tid * 100;
        float s = b[tid];
        for (int i = 0; i < 100; i++) s += row[i] * w[i];
        out[k * 100 + tid] = softplusf(s);
    }
}

__global__ void muz_kernel(const float* __restrict__ mu2, const float* __restrict__ W,
                           const float* __restrict__ b, float* __restrict__ out)
{
    __shared__ float row[100];
    int k = blockIdx.x, tid = threadIdx.x;
    if (tid < 100) row[tid] = mu2[k * 100 + tid];
    __syncthreads();
    for (int j = tid; j < EMB; j += 128) {
        const float* w = W + j * 100;
        float s = b[j];
        for (int i = 0; i < 100; i++) s += row[i] * w[i];
        out[k * EMB + j] = s;
    }
}

// =============================================================================
// beta: BN_topic + softmax, exp-once (upper-bound shift; softmax shift-invariant).
// =============================================================================
__global__ void __launch_bounds__(1024)
beta_kernel(const float* __restrict__ logits, const float* __restrict__ bbias,
            const float* __restrict__ gdec, const float* __restrict__ bdec,
            float* __restrict__ beta)
{
    __shared__ float rs[1024], rq[1024], rmx[1024], rmn[1024], rmb[1024];
    const int k = blockIdx.x, tid = threadIdx.x;
    const float* row = logits + (size_t)k * VV;
    const float* bb  = bbias + (size_t)k * VV;
    float* brow = beta + (size_t)k * VV;

    float s = 0.f, q = 0.f, mxx = -FLT_MAX, mnx = FLT_MAX, mxb = -FLT_MAX;
    for (int v = tid; v < VV; v += 1024) {
        float x = row[v];
        s += x; q += x * x;
        mxx = fmaxf(mxx, x);
        mnx = fminf(mnx, x);
        mxb = fmaxf(mxb, bb[v]);
    }
    rs[tid] = s; rq[tid] = q; rmx[tid] = mxx; rmn[tid] = mnx; rmb[tid] = mxb;
    __syncthreads();
    for (int st = 512; st > 0; st >>= 1) {
        if (tid < st) {
            rs[tid] += rs[tid + st];
            rq[tid] += rq[tid + st];
            rmx[tid] = fmaxf(rmx[tid], rmx[tid + st]);
            rmn[tid] = fminf(rmn[tid], rmn[tid + st]);
            rmb[tid] = fmaxf(rmb[tid], rmb[tid + st]);
        }
        __syncthreads();
    }
    const float mean = rs[0] / VV;
    const float var  = rq[0] / VV - mean * mean;
    const float scale = gdec[k] * rsqrtf(var + 1e-5f);
    const float shift = bdec[k] - mean * scale;
    const float mx = scale * (scale > 0.f ? rmx[0] : rmn[0]) + shift + rmb[0];
    __syncthreads();

    float se = 0.f;
    for (int v = tid; v < VV; v += 1024) {
        float e = expf(row[v] * scale + shift + bb[v] - mx);
        brow[v] = e;
        se += e;
    }
    rs[tid] = se;
    __syncthreads();
    for (int st = 512; st > 0; st >>= 1) {
        if (tid < st) rs[tid] += rs[tid + st];
        __syncthreads();
    }
    const float inv = 1.f / rs[0];

    for (int v = tid; v < VV; v += 1024)
        brow[v] *= inv;
}

// ---------------- launch -----------------------------------------------------
extern "C" void kernel_launch(void* const* d_in, const int* in_sizes, int n_in,
                              void* d_out, int out_size)
{
    const float* input_   = (const float*)d_in[0];
    const float* eps      = (const float*)d_in[2];
    const float* en1_W    = (const float*)d_in[3];
    const float* en1_b    = (const float*)d_in[4];
    const float* en2_W    = (const float*)d_in[5];
    const float* en2_b    = (const float*)d_in[6];
    const float* mean_W   = (const float*)d_in[7];
    const float* mean_b   = (const float*)d_in[8];
    const float* logvar_W = (const float*)d_in[9];
    const float* logvar_b = (const float*)d_in[10];
    const float* mu1_W    = (const float*)d_in[11];
    const float* mu1_b    = (const float*)d_in[12];
    const float* mu2_W    = (const float*)d_in[13];
    const float* mu2_b    = (const float*)d_in[14];
    const float* mu_W     = (const float*)d_in[15];
    const float* mu_b     = (const float*)d_in[16];
    const float* topics   = (const float*)d_in[17];
    const float* bbias    = (const float*)d_in[18];
    const float* emb      = (const float*)d_in[19];
    const float* g_mean   = (const float*)d_in[20];
    const float* b_mean   = (const float*)d_in[21];
    const float* g_logvar = (const float*)d_in[22];
    const float* b_logvar = (const float*)d_in[23];
    const float* g_x      = (const float*)d_in[24];
    const float* b_x      = (const float*)d_in[25];
    const float* g_phi    = (const float*)d_in[26];
    const float* b_phi    = (const float*)d_in[27];
    const float* g_dec    = (const float*)d_in[28];
    const float* b_dec    = (const float*)d_in[29];

    float* out = (float*)d_out;
    float* out_z     = out;
    float* out_recon = out + (long long)NB * CC;
    float* out_zx    = out_recon + (long long)NB * VV;
    float* out_zc    = out_zx + (long long)NB * CC;
    float* out_theta = out_zc + (long long)KK * CC;

    void* sp = nullptr;
    cudaGetSymbolAddress(&sp, g_scratch);
    float* S = (float*)sp;
    float* s_en1    = S + OFF_EN1;
    float* s_en2    = S + OFF_EN2;
    float* s_pm     = S + OFF_PM;
    float* s_lv     = S + OFF_LV;
    float* s_zx     = S + OFF_ZX;
    float* s_zc     = S + OFF_ZC;
    float* s_theta  = S + OFF_THETA;
    float* s_mu1    = S + OFF_MU1;
    float* s_mu2    = S + OFF_MU2;
    float* s_muz    = S + OFF_MUZ;
    float* s_logits = S + OFF_LOGITS;
    float* s_beta   = S + OFF_BETA;
    float* st_t     = S + OFF_ST;

    cudaFuncSetAttribute(gemm1_fp16_sk, cudaFuncAttributeMaxDynamicSharedMemorySize, G1_SMEM);
    cudaFuncSetAttribute(recon_f16, cudaFuncAttributeMaxDynamicSharedMemorySize, G1_SMEM);
    cudaFuncSetAttribute(gemm_nt_bf16x3<true, true, false>,
                         cudaFuncAttributeMaxDynamicSharedMemorySize, NTB_SMEM);

    // 0) pre-split: A -> 1 fp16 plane, B -> 1 fp16 plane
    split_fp16<<<NB + E1, 256>>>(input_, en1_W);

    // 1-4) decoder-side small kernels
    colstats_kernel<<<2, 256>>>(topics, KK, st_t);
    bn_apply_kernel<<<(KK * CC + 255) / 256, 256>>>(topics, st_t, g_phi, b_phi, KK * CC, s_zc, out_zc);
    mu1_kernel<<<(KK * 100 + 255) / 256, 256>>>(s_zc, mu1_W, mu1_b, s_mu1);
    mu2_kernel<<<KK, 128>>>(s_mu1, mu2_W, mu2_b, s_mu2);

    // 5) en1 partials — split-K fp16 GEMM, 1024 CTAs (full-chip packing)
    gemm1_fp16_sk<<<dim3(E1 / 128, NB / 128, SK), 256, G1_SMEM>>>();

    // 6) muz (overlaps gemm1 tail-wave slack)
    muz_kernel<<<KK, 128>>>(s_mu2, mu_W, mu_b, s_muz);

    // 7) reduce partials -> en1
    reduce_en1<<<(NB * E1 / 4) / 256, 256>>>(en1_b, s_en1);

    // 8) en2 — bf16x3
    gemm_nt_bf16x3<true, true, false><<<dim3(E2 / 128, NB / 128), 512, NTB_SMEM>>>(
        s_en1, en2_W, en2_b, s_en2, NB, E2, E1);

    // 9) heads
    meanlogvar_kernel<<<(NB * 4 + 255) / 256, 256>>>(
        s_en2, mean_W, mean_b, logvar_W, logvar_b, s_pm, s_lv);

    // 10) fused mid-section
    mid_fused<<<1, 1024>>>(s_pm, s_lv, eps, g_mean, b_mean, g_logvar, b_logvar,
                           g_x, b_x, out_z, s_zx, out_zx);

    // 11) theta
    theta_kernel<<<NB, 256>>>(s_zx, s_zc, s_theta, out_theta);

    // 12) logits = mu_z @ emb^T — tf32 single pass
    logits_tf32<<<dim3((VV + 63) / 64, (KK + 63) / 64), 256>>>(s_muz, emb, s_logits);

    // 13) beta — exp-once
    beta_kernel<<<KK, 1024>>>(s_logits, bbias, g_dec, b_dec, s_beta);

    // 14) beta^T fp16
    transpose_beta<<<dim3(BTROWS / 32, KR / 32), 256>>>(s_beta);

    // 15) recon = theta @ beta — fp16 NT
    recon_f16<<<dim3(BTROWS / 128, NB / 128), 256, G1_SMEM>>>(out_recon);

    (void)in_sizes; (void)n_in; (void)out_size;
}

// round 15
// speedup vs baseline: 1.5713x; 1.0080x over previous
#include <cuda_runtime.h>
#include <cuda_bf16.h>
#include <cuda_fp16.h>
#include <math.h>
#include <float.h>
#include <stdint.h>

// ---------------- problem dims ----------------
#define NB   2048
#define VV   50000
#define E1   1024
#define E2   512
#define CC   2
#define KK   200
#define EMB  300

#define KP   50048
#define KPW  (KP/2)
#define G1NT (KP / 32)
#define SK   8                   // split-K factor for gemm1

#define KR   224
#define KRW  (KR/2)
#define RNT  (KR / 32)
#define BTROWS 50048

// ---------------- float scratch ----------------------------------------------
#define OFF_EN1    0LL
#define OFF_EN2    (OFF_EN1 + (long long)NB*E1)
#define OFF_PM     (OFF_EN2 + (long long)NB*E2)
#define OFF_LV     (OFF_PM + (long long)NB*CC)
#define OFF_Z      (OFF_LV + (long long)NB*CC)
#define OFF_ZX     (OFF_Z + (long long)NB*CC)
#define OFF_ZC     (OFF_ZX + (long long)NB*CC)
#define OFF_THETA  (OFF_ZC + (long long)KK*CC)
#define OFF_MU1    (OFF_THETA + (long long)NB*KK)
#define OFF_MU2    (OFF_MU1 + (long long)KK*100)
#define OFF_MUZ    (OFF_MU2 + (long long)KK*100)
#define OFF_LOGITS (OFF_MUZ + (long long)KK*EMB)
#define OFF_BETA   (OFF_LOGITS + (long long)KK*VV)
#define OFF_SPM    (OFF_BETA + (long long)KK*VV)
#define OFF_SLV    (OFF_SPM + 4)
#define OFF_SZ     (OFF_SLV + 4)
#define OFF_ST     (OFF_SZ + 4)
#define SCRATCH_FLOATS (OFF_ST + 8)

__device__ float g_scratch[SCRATCH_FLOATS];

// split-K partial planes for gemm1
__device__ __align__(16) float g_part[(long long)SK * NB * E1];
// per-topic 1/sum for beta softmax
__device__ float g_binv[KK];

// ---------------- fp16 planes (words) ----------------------------------------
#define WA 51249152LL
#define WB 25624576LL
#define W_AH 0LL
#define W_BH (W_AH + WA)
#define W_TH (W_BH + WB)
#define TWH  ((long long)NB * KRW)
#define W_BT (W_TH + TWH)
#define BTWH ((long long)BTROWS * KRW)

__device__ __align__(16) uint32_t g_bf[WA + WB + TWH + BTWH];

__device__ __forceinline__ float softplusf(float x) {
    return fmaxf(x, 0.0f) + log1pf(expf(-fabsf(x)));
}

__device__ __forceinline__ uint32_t pk_h2(__half lo, __half hi) {
    return ((uint32_t)__half_as_ushort(hi) << 16) | __half_as_ushort(lo);
}

__device__ __forceinline__ uint32_t pk_bf16(float lo, float hi) {
    uint32_t r;
    asm("cvt.rn.bf16x2.f32 %0, %1, %2;" : "=r"(r) : "f"(hi), "f"(lo));
    return r;
}

__device__ __forceinline__ unsigned tf32_rna(float x) {
    unsigned r;
    asm("cvt.rna.tf32.f32 %0, %1;" : "=r"(r) : "f"(x));
    return r;
}

__device__ __forceinline__ void mma_f16(float* d,
                                        uint32_t a0, uint32_t a1, uint32_t a2, uint32_t a3,
                                        uint32_t b0, uint32_t b1)
{
    asm volatile(
        "mma.sync.aligned.m16n8k16.row.col.f32.f16.f16.f32 "
        "{%0,%1,%2,%3},{%4,%5,%6,%7},{%8,%9},{%0,%1,%2,%3};"
        : "+f"(d[0]), "+f"(d[1]), "+f"(d[2]), "+f"(d[3])
        : "r"(a0), "r"(a1), "r"(a2), "r"(a3), "r"(b0), "r"(b1));
}

__device__ __forceinline__ void mma_bf16(float* d,
                                         uint32_t a0, uint32_t a1, uint32_t a2, uint32_t a3,
                                         uint32_t b0, uint32_t b1)
{
    asm volatile(
        "mma.sync.aligned.m16n8k16.row.col.f32.bf16.bf16.f32 "
        "{%0,%1,%2,%3},{%4,%5,%6,%7},{%8,%9},{%0,%1,%2,%3};"
        : "+f"(d[0]), "+f"(d[1]), "+f"(d[2]), "+f"(d[3])
        : "r"(a0), "r"(a1), "r"(a2), "r"(a3), "r"(b0), "r"(b1));
}

__device__ __forceinline__ void mma_tf32(float* d,
                                         unsigned a0, unsigned a1, unsigned a2, unsigned a3,
                                         unsigned b0, unsigned b1)
{
    asm volatile(
        "mma.sync.aligned.m16n8k8.row.col.f32.tf32.tf32.f32 "
        "{%0,%1,%2,%3},{%4,%5,%6,%7},{%8,%9},{%0,%1,%2,%3};"
        : "+f"(d[0]), "+f"(d[1]), "+f"(d[2]), "+f"(d[3])
        : "r"(a0), "r"(a1), "r"(a2), "r"(a3), "r"(b0), "r"(b1));
}

__device__ __forceinline__ void ldsm_x4(uint32_t& r0, uint32_t& r1, uint32_t& r2,
                                        uint32_t& r3, uint32_t addr)
{
    asm volatile("ldmatrix.sync.aligned.m8n8.x4.shared.b16 {%0,%1,%2,%3}, [%4];"
                 : "=r"(r0), "=r"(r1), "=r"(r2), "=r"(r3) : "r"(addr));
}

// =============================================================================
// Pre-pass: A=input, B=en1_W -> fp16 planes, zero pad.
// =============================================================================
__global__ void __launch_bounds__(256)
split_fp16(const float* __restrict__ A, const float* __restrict__ B)
{
    const int b = blockIdx.x, tid = threadIdx.x;
    const float* src;
    uint32_t* h;
    if (b < NB) {
        src = A + (size_t)b * VV;
        h = g_bf + W_AH + (size_t)b * KPW;
    } else {
        int r = b - NB;
        src = B + (size_t)r * VV;
        h = g_bf + W_BH + (size_t)r * KPW;
    }
    for (int i = tid; i < VV / 4; i += 256) {
        float4 v = *reinterpret_cast<const float4*>(src + i * 4);
        h[2*i]     = pk_h2(__float2half_rn(v.x), __float2half_rn(v.y));
        h[2*i + 1] = pk_h2(__float2half_rn(v.z), __float2half_rn(v.w));
    }
    if (tid < KPW - VV/2) h[VV/2 + tid] = 0u;
}

// =============================================================================
// GEMM1 split-K: partial[ks] = input @ en1_W^T over k-range of split ks.
// =============================================================================
#define STG    20480
#define G1_SMEM (3 * STG)

__global__ void __launch_bounds__(256, 2)
gemm1_fp16_sk()
{
    extern __shared__ __align__(16) char sm[];
    const uint32_t sb32 = (uint32_t)__cvta_generic_to_shared(sm);
    const int tid = threadIdx.x;
    const int lane = tid & 31, warp = tid >> 5;
    const int gid = lane >> 2, tig = lane & 3;
    const int wm = warp >> 1, wn = warp & 1;
    const int m0 = blockIdx.y * 128, n0 = blockIdx.x * 128;
    const int ks = blockIdx.z;
    const int ts = (G1NT * ks) / SK;
    const int te = (G1NT * (ks + 1)) / SK;

    float acc[2][8][4];
#pragma unroll
    for (int i = 0; i < 2; i++)
#pragma unroll
        for (int j = 0; j < 8; j++)
#pragma unroll
            for (int l = 0; l < 4; l++) acc[i][j][l] = 0.0f;

    const uint32_t* gsrc[4];
    uint32_t sdst[4];
#pragma unroll
    for (int i = 0; i < 2; i++) {
        int idx = tid + i * 256;
        int r = idx >> 2, part = idx & 3;
        gsrc[i] = g_bf + W_AH + (size_t)(m0 + r) * KPW + part * 4;
        sdst[i] = sb32 + (uint32_t)(r * 80 + part * 16);
    }
#pragma unroll
    for (int i = 0; i < 2; i++) {
        int idx = tid + i * 256;
        int r = idx >> 2, part = idx & 3;
        gsrc[2 + i] = g_bf + W_BH + (size_t)(n0 + r) * KPW + part * 4;
        sdst[2 + i] = sb32 + (uint32_t)(10240 + r * 80 + part * 16);
    }

    auto issue = [&](int t) {
        const uint32_t boff = (uint32_t)(t % 3) * STG;
        const size_t k = (size_t)t * 16;
#pragma unroll
        for (int i = 0; i < 4; i++)
            asm volatile("cp.async.cg.shared.global [%0], [%1], 16;"
                         :: "r"(sdst[i] + boff), "l"(gsrc[i] + k) : "memory");
        asm volatile("cp.async.commit_group;" ::: "memory");
    };

    const int lr = (lane & 7) + ((lane >> 3) & 1) * 8;
    const int kb = ((lane >> 4) & 1) * 16;
    const uint32_t aoff = (uint32_t)((wm * 32 + lr) * 80 + kb);
    const uint32_t boff2 = (uint32_t)(10240 + (wn * 64 + lr) * 80 + kb);

    issue(ts);
    issue(ts + 1);

    for (int t = ts; t < te; t++) {
        if (t == te - 1) asm volatile("cp.async.wait_group 0;" ::: "memory");
        else             asm volatile("cp.async.wait_group 1;" ::: "memory");
        __syncthreads();
        if (t + 2 < te) issue(t + 2);

        const uint32_t st = sb32 + (uint32_t)(t % 3) * STG;
#pragma unroll
        for (int kkw = 0; kkw < 2; kkw++) {
            const uint32_t ka = st + kkw * 32;
            uint32_t ah[2][4], bq[4][4];
#pragma unroll
            for (int ms = 0; ms < 2; ms++)
                ldsm_x4(ah[ms][0], ah[ms][1], ah[ms][2], ah[ms][3],
                        ka + aoff + ms * 1280);
#pragma unroll
            for (int pr = 0; pr < 4; pr++)
                ldsm_x4(bq[pr][0], bq[pr][1], bq[pr][2], bq[pr][3],
                        ka + boff2 + pr * 1280);
#pragma unroll
            for (int ms = 0; ms < 2; ms++)
#pragma unroll
                for (int pr = 0; pr < 4; pr++)
#pragma unroll
                    for (int j = 0; j < 2; j++) {
                        int ns = pr * 2 + j;
                        mma_f16(acc[ms][ns], ah[ms][0], ah[ms][1], ah[ms][2], ah[ms][3],
                                bq[pr][j], bq[pr][j + 2]);
                    }
        }
    }

    float* P = g_part + (size_t)ks * NB * E1;
#pragma unroll
    for (int ms = 0; ms < 2; ms++) {
        const int r0 = m0 + wm * 32 + ms * 16 + gid;
#pragma unroll
        for (int ns = 0; ns < 8; ns++) {
            const int c0 = n0 + wn * 64 + ns * 8 + 2 * tig;
            P[(size_t)r0 * E1 + c0]           = acc[ms][ns][0];
            P[(size_t)r0 * E1 + c0 + 1]       = acc[ms][ns][1];
            P[(size_t)(r0 + 8) * E1 + c0]     = acc[ms][ns][2];
            P[(size_t)(r0 + 8) * E1 + c0 + 1] = acc[ms][ns][3];
        }
    }
}

// =============================================================================
// reduce partials + bias + softplus -> en1
// =============================================================================
__global__ void __launch_bounds__(256)
reduce_en1(const float* __restrict__ bias, float* __restrict__ C)
{
    const size_t i = (size_t)blockIdx.x * 256 + threadIdx.x;
    float4 s = reinterpret_cast<const float4*>(g_part)[i];
#pragma unroll
    for (int p = 1; p < SK; p++) {
        float4 v = reinterpret_cast<const float4*>(g_part + (size_t)p * NB * E1)[i];
        s.x += v.x; s.y += v.y; s.z += v.z; s.w += v.w;
    }
    const int c = (int)((i * 4) & (E1 - 1));
    s.x = softplusf(s.x + bias[c]);
    s.y = softplusf(s.y + bias[c + 1]);
    s.z = softplusf(s.z + bias[c + 2]);
    s.w = softplusf(s.w + bias[c + 3]);
    reinterpret_cast<float4*>(C)[i] = s;
}

// =============================================================================
// recon = theta @ beta via NT fp16 planes.
// =============================================================================
__global__ void __launch_bounds__(256, 2)
recon_f16(float* __restrict__ C)
{
    extern __shared__ __align__(16) char sm[];
    const uint32_t sb32 = (uint32_t)__cvta_generic_to_shared(sm);
    const int tid = threadIdx.x;
    const int lane = tid & 31, warp = tid >> 5;
    const int gid = lane >> 2, tig = lane & 3;
    const int wm = warp >> 1, wn = warp & 1;
    const int m0 = blockIdx.y * 128, n0 = blockIdx.x * 128;

    float acc[2][8][4];
#pragma unroll
    for (int i = 0; i < 2; i++)
#pragma unroll
        for (int j = 0; j < 8; j++)
#pragma unroll
            for (int l = 0; l < 4; l++) acc[i][j][l] = 0.0f;

    const uint32_t* gsrc[4];
    uint32_t sdst[4];
#pragma unroll
    for (int i = 0; i < 2; i++) {
        int idx = tid + i * 256;
        int r = idx >> 2, part = idx & 3;
        gsrc[i] = g_bf + W_TH + (size_t)(m0 + r) * KRW + part * 4;
        sdst[i] = sb32 + (uint32_t)(r * 80 + part * 16);
    }
#pragma unroll
    for (int i = 0; i < 2; i++) {
        int idx = tid + i * 256;
        int r = idx >> 2, part = idx & 3;
        gsrc[2 + i] = g_bf + W_BT + (size_t)(n0 + r) * KRW + part * 4;
        sdst[2 + i] = sb32 + (uint32_t)(10240 + r * 80 + part * 16);
    }

    auto issue = [&](int t) {
        const uint32_t boff = (uint32_t)(t % 3) * STG;
        const size_t k = (size_t)t * 16;
#pragma unroll
        for (int i = 0; i < 4; i++)
            asm volatile("cp.async.cg.shared.global [%0], [%1], 16;"
                         :: "r"(sdst[i] + boff), "l"(gsrc[i] + k) : "memory");
        asm volatile("cp.async.commit_group;" ::: "memory");
    };

    const int lr = (lane & 7) + ((lane >> 3) & 1) * 8;
    const int kb = ((lane >> 4) & 1) * 16;
    const uint32_t aoff = (uint32_t)((wm * 32 + lr) * 80 + kb);
    const uint32_t boff2 = (uint32_t)(10240 + (wn * 64 + lr) * 80 + kb);

    issue(0);
    issue(1);

    for (int t = 0; t < RNT; t++) {
        if (t == RNT - 1) asm volatile("cp.async.wait_group 0;" ::: "memory");
        else              asm volatile("cp.async.wait_group 1;" ::: "memory");
        __syncthreads();
        if (t + 2 < RNT) issue(t + 2);

        const uint32_t st = sb32 + (uint32_t)(t % 3) * STG;
#pragma unroll
        for (int kkw = 0; kkw < 2; kkw++) {
            const uint32_t ka = st + kkw * 32;
            uint32_t ah[2][4], bq[4][4];
#pragma unroll
            for (int ms = 0; ms < 2; ms++)
                ldsm_x4(ah[ms][0], ah[ms][1], ah[ms][2], ah[ms][3],
                        ka + aoff + ms * 1280);
#pragma unroll
            for (int pr = 0; pr < 4; pr++)
                ldsm_x4(bq[pr][0], bq[pr][1], bq[pr][2], bq[pr][3],
                        ka + boff2 + pr * 1280);
#pragma unroll
            for (int ms = 0; ms < 2; ms++)
#pragma unroll
                for (int pr = 0; pr < 4; pr++)
#pragma unroll
                    for (int j = 0; j < 2; j++) {
                        int ns = pr * 2 + j;
                        mma_f16(acc[ms][ns], ah[ms][0], ah[ms][1], ah[ms][2], ah[ms][3],
                                bq[pr][j], bq[pr][j + 2]);
                    }
        }
    }

#pragma unroll
    for (int ms = 0; ms < 2; ms++) {
        const int r0 = m0 + wm * 32 + ms * 16 + gid;
#pragma unroll
        for (int ns = 0; ns < 8; ns++) {
            const int c0 = n0 + wn * 64 + ns * 8 + 2 * tig;
            if (c0 < VV) {
                C[(size_t)r0 * VV + c0]       = acc[ms][ns][0];
                C[(size_t)(r0 + 8) * VV + c0] = acc[ms][ns][2];
            }
            if (c0 + 1 < VV) {
                C[(size_t)r0 * VV + c0 + 1]       = acc[ms][ns][1];
                C[(size_t)(r0 + 8) * VV + c0 + 1] = acc[ms][ns][3];
            }
        }
    }
}

// =============================================================================
// beta^T fp16 with softmax normalization applied during conversion.
// =============================================================================
__global__ void __launch_bounds__(256)
transpose_beta(const float* __restrict__ beta)
{
    __shared__ float s[32][33];
    __shared__ float sinv[32];
    const int tid = threadIdx.x;
    const int tx = tid & 31, ty = tid >> 5;
    const int v0 = blockIdx.x * 32, k0 = blockIdx.y * 32;

    if (tid < 32) {
        int gk = k0 + tid;
        sinv[tid] = (gk < KK) ? g_binv[gk] : 0.f;
    }
#pragma unroll
    for (int i = 0; i < 4; i++) {
        int k = ty + i * 8;
        int gk = k0 + k, gv = v0 + tx;
        float val = 0.f;
        if (gk < KK && gv < VV) val = beta[(size_t)gk * VV + gv];
        s[k][tx] = val;
    }
    __syncthreads();

#pragma unroll
    for (int i = 0; i < 2; i++) {
        int w = tid + i * 256;
        int v = w >> 4, kw = w & 15;
        uint32_t word = pk_h2(__float2half_rn(s[2 * kw][v] * sinv[2 * kw]),
                              __float2half_rn(s[2 * kw + 1][v] * sinv[2 * kw + 1]));
        g_bf[W_BT + (size_t)(v0 + v) * KRW + (k0 >> 1) + kw] = word;
    }
}

// =============================================================================
// logits = mu_z[200,300] @ emb[50000,300]^T — single-pass tf32.
// =============================================================================
__global__ void __launch_bounds__(256)
logits_tf32(const float* __restrict__ A, const float* __restrict__ B,
            float* __restrict__ C)
{
    __shared__ float As[64][20];
    __shared__ float Bs[64][20];
    const int tid = threadIdx.x;
    const int lane = tid & 31, warp = tid >> 5;
    const int gid = lane >> 2, tig = lane & 3;
    const int wm = warp >> 1, wn = warp & 1;
    const int m0 = blockIdx.y * 64, n0 = blockIdx.x * 64;

    float acc[4][4];
#pragma unroll
    for (int j = 0; j < 4; j++)
#pragma unroll
        for (int l = 0; l < 4; l++) acc[j][l] = 0.0f;

    const int row = tid >> 2, q = (tid & 3) * 4;

    for (int k0 = 0; k0 < EMB; k0 += 16) {
        const int gk = k0 + q;
        {
            int gm = m0 + row;
            float4 v = make_float4(0.f, 0.f, 0.f, 0.f);
            if (gm < KK) {
                const float* p = A + (size_t)gm * EMB;
                if (gk + 3 < EMB) v = *reinterpret_cast<const float4*>(p + gk);
                else {
                    if (gk + 0 < EMB) v.x = p[gk + 0];
                    if (gk + 1 < EMB) v.y = p[gk + 1];
                    if (gk + 2 < EMB) v.z = p[gk + 2];
                    if (gk + 3 < EMB) v.w = p[gk + 3];
                }
            }
            As[row][q + 0] = __uint_as_float(tf32_rna(v.x));
            As[row][q + 1] = __uint_as_float(tf32_rna(v.y));
            As[row][q + 2] = __uint_as_float(tf32_rna(v.z));
            As[row][q + 3] = __uint_as_float(tf32_rna(v.w));
        }
        {
            int gn = n0 + row;
            float4 v = make_float4(0.f, 0.f, 0.f, 0.f);
            if (gn < VV) {
                const float* p = B + (size_t)gn * EMB;
                if (gk + 3 < EMB) v = *reinterpret_cast<const float4*>(p + gk);
                else {
                    if (gk + 0 < EMB) v.x = p[gk + 0];
                    if (gk + 1 < EMB) v.y = p[gk + 1];
                    if (gk + 2 < EMB) v.z = p[gk + 2];
                    if (gk + 3 < EMB) v.w = p[gk + 3];
                }
            }
            Bs[row][q + 0] = __uint_as_float(tf32_rna(v.x));
            Bs[row][q + 1] = __uint_as_float(tf32_rna(v.y));
            Bs[row][q + 2] = __uint_as_float(tf32_rna(v.z));
            Bs[row][q + 3] = __uint_as_float(tf32_rna(v.w));
        }
        __syncthreads();

#pragma unroll
        for (int kk = 0; kk < 16; kk += 8) {
            unsigned a[4], b[4][2];
            int r = wm * 16 + gid;
            a[0] = __float_as_uint(As[r][kk + tig]);
            a[1] = __float_as_uint(As[r + 8][kk + tig]);
            a[2] = __float_as_uint(As[r][kk + tig + 4]);
            a[3] = __float_as_uint(As[r + 8][kk + tig + 4]);
#pragma unroll
            for (int ns = 0; ns < 4; ns++) {
                int n = wn * 32 + ns * 8 + gid;
                b[ns][0] = __float_as_uint(Bs[n][kk + tig]);
                b[ns][1] = __float_as_uint(Bs[n][kk + tig + 4]);
            }
#pragma unroll
            for (int ns = 0; ns < 4; ns++)
                mma_tf32(acc[ns], a[0], a[1], a[2], a[3], b[ns][0], b[ns][1]);
        }
        __syncthreads();
    }

    const int r0 = m0 + wm * 16 + gid;
#pragma unroll
    for (int ns = 0; ns < 4; ns++) {
        const int c0 = n0 + wn * 32 + ns * 8 + 2 * tig;
        if (r0 < KK) {
            if (c0 < VV)     C[(size_t)r0 * VV + c0]     = acc[ns][0];
            if (c0 + 1 < VV) C[(size_t)r0 * VV + c0 + 1] = acc[ns][1];
        }
        if (r0 + 8 < KK) {
            if (c0 < VV)     C[(size_t)(r0 + 8) * VV + c0]     = acc[ns][2];
            if (c0 + 1 < VV) C[(size_t)(r0 + 8) * VV + c0 + 1] = acc[ns][3];
        }
    }
}

// ============================ bf16x3 NT GEMM (en2) ===========================
#define NTB_SMEM (2 * 10240 * 4)

template<bool SP, bool HB, bool CHKMN>
__global__ void __launch_bounds__(512, 1)
gemm_nt_bf16x3(const float* __restrict__ A, const float* __restrict__ B,
               const float* __restrict__ bias, float* __restrict__ C,
               int M, int N, int K)
{
    extern __shared__ __align__(16) uint32_t sw[];
    const int tid = threadIdx.x;
    const int lane = tid & 31, warp = tid >> 5;
    const int gid = lane >> 2, tig = lane & 3;
    const int wm = warp >> 2, wn = warp & 3;
    const int m0 = blockIdx.y * 128, n0 = blockIdx.x * 128;
    const int nt = (K + 31) / 32;

    float acc[2][4][4];
#pragma unroll
    for (int i = 0; i < 2; i++)
#pragma unroll
        for (int j = 0; j < 4; j++)
#pragma unroll
            for (int l = 0; l < 4; l++) acc[i][j][l] = 0.0f;

    const int srow = tid >> 3;
    const int sq   = tid & 7;
    float4 stA[2], stB[2];

    auto load_tile = [&](int t) {
        const int gk = t * 32 + sq * 4;
#pragma unroll
        for (int l = 0; l < 2; l++) {
            int r = srow + l * 64;
            {
                int gm = m0 + r;
                float4 v = make_float4(0.f, 0.f, 0.f, 0.f);
                if (((!CHKMN) || gm < M)) {
                    if (gk + 3 < K) v = *reinterpret_cast<const float4*>(A + (size_t)gm * K + gk);
                    else if (gk < K) {
                        const float* p = A + (size_t)gm * K;
                        v.x = p[gk];
                        if (gk + 1 < K) v.y = p[gk + 1];
                        if (gk + 2 < K) v.z = p[gk + 2];
                    }
                }
                stA[l] = v;
            }
            {
                int gn = n0 + r;
                float4 v = make_float4(0.f, 0.f, 0.f, 0.f);
                if (((!CHKMN) || gn < N)) {
                    if (gk + 3 < K) v = *reinterpret_cast<const float4*>(B + (size_t)gn * K + gk);
                    else if (gk < K) {
                        const float* p = B + (size_t)gn * K;
                        v.x = p[gk];
                        if (gk + 1 < K) v.y = p[gk + 1];
                        if (gk + 2 < K) v.z = p[gk + 2];
                    }
                }
                stB[l] = v;
            }
        }
    };

    auto store_tile = [&](uint32_t* buf) {
#pragma unroll
        for (int l = 0; l < 2; l++) {
            int r = srow + l * 64;
            uint32_t w = (uint32_t)(r * 20 + sq * 2);
            {
                float4 v = stA[l];
                __nv_bfloat16 hx = __float2bfloat16_rn(v.x), hy = __float2bfloat16_rn(v.y);
                __nv_bfloat16 hz = __float2bfloat16_rn(v.z), hw = __float2bfloat16_rn(v.w);
                buf[w]     = ((uint32_t)__bfloat16_as_ushort(hy) << 16) | __bfloat16_as_ushort(hx);
                buf[w + 1] = ((uint32_t)__bfloat16_as_ushort(hw) << 16) | __bfloat16_as_ushort(hz);
                buf[w + 2560]     = pk_bf16(v.x - __bfloat162float(hx), v.y - __bfloat162float(hy));
                buf[w + 2560 + 1] = pk_bf16(v.z - __bfloat162float(hz), v.w - __bfloat162float(hw));
            }
            {
                float4 v = stB[l];
                __nv_bfloat16 hx = __float2bfloat16_rn(v.x), hy = __float2bfloat16_rn(v.y);
                __nv_bfloat16 hz = __float2bfloat16_rn(v.z), hw = __float2bfloat16_rn(v.w);
                buf[w + 5120]     = ((uint32_t)__bfloat16_as_ushort(hy) << 16) | __bfloat16_as_ushort(hx);
                buf[w + 5120 + 1] = ((uint32_t)__bfloat16_as_ushort(hw) << 16) | __bfloat16_as_ushort(hz);
                buf[w + 7680]     = pk_bf16(v.x - __bfloat162float(hx), v.y - __bfloat162float(hy));
                buf[w + 7680 + 1] = pk_bf16(v.z - __bfloat162float(hz), v.w - __bfloat162float(hw));
            }
        }
    };

    load_tile(0);
    store_tile(sw);
    __syncthreads();

    for (int t = 0; t < nt; t++) {
        const int b = t & 1;
        uint32_t* bb = sw + b * 10240;
        if (t + 1 < nt) load_tile(t + 1);

#pragma unroll
        for (int kkw = 0; kkw < 16; kkw += 8) {
            uint32_t ah[2][4], al[2][4], bh[4][2], bl[4][2];
#pragma unroll
            for (int ms = 0; ms < 2; ms++) {
                int base = (wm * 32 + ms * 16 + gid) * 20 + kkw + tig;
                ah[ms][0] = bb[base];       ah[ms][1] = bb[base + 160];
                ah[ms][2] = bb[base + 4];   ah[ms][3] = bb[base + 164];
                al[ms][0] = bb[base + 2560];       al[ms][1] = bb[base + 2560 + 160];
                al[ms][2] = bb[base + 2560 + 4];   al[ms][3] = bb[base + 2560 + 164];
            }
#pragma unroll
            for (int ns = 0; ns < 4; ns++) {
                int base = 5120 + (wn * 32 + ns * 8 + gid) * 20 + kkw + tig;
                bh[ns][0] = bb[base];       bh[ns][1] = bb[base + 4];
                bl[ns][0] = bb[base + 2560]; bl[ns][1] = bb[base + 2560 + 4];
            }
#pragma unroll
            for (int ms = 0; ms < 2; ms++)
#pragma unroll
                for (int ns = 0; ns < 4; ns++) {
                    mma_bf16(acc[ms][ns], ah[ms][0], ah[ms][1], ah[ms][2], ah[ms][3],
                             bh[ns][0], bh[ns][1]);
                    mma_bf16(acc[ms][ns], ah[ms][0], ah[ms][1], ah[ms][2], ah[ms][3],
                             bl[ns][0], bl[ns][1]);
                    mma_bf16(acc[ms][ns], al[ms][0], al[ms][1], al[ms][2], al[ms][3],
                             bh[ns][0], bh[ns][1]);
                }
        }

        if (t + 1 < nt) store_tile(sw + (b ^ 1) * 10240);
        __syncthreads();
    }

#pragma unroll
    for (int ms = 0; ms < 2; ms++) {
        int r0 = m0 + wm * 32 + ms * 16 + gid;
#pragma unroll
        for (int ns = 0; ns < 4; ns++) {
            int c0 = n0 + wn * 32 + ns * 8 + 2 * tig;
            float bv0 = 0.f, bv1 = 0.f;
            if (HB) { bv0 = bias[c0]; bv1 = bias[c0 + 1]; }
            float v00 = acc[ms][ns][0] + bv0;
            float v01 = acc[ms][ns][1] + bv1;
            float v10 = acc[ms][ns][2] + bv0;
            float v11 = acc[ms][ns][3] + bv1;
            if (SP) { v00 = softplusf(v00); v01 = softplusf(v01);
                      v10 = softplusf(v10); v11 = softplusf(v11); }
            if (!CHKMN) {
                C[(size_t)r0 * N + c0]           = v00;
                C[(size_t)r0 * N + c0 + 1]       = v01;
                C[(size_t)(r0 + 8) * N + c0]     = v10;
                C[(size_t)(r0 + 8) * N + c0 + 1] = v11;
            } else {
                if (r0 < M) {
                    if (c0 < N)     C[(size_t)r0 * N + c0]     = v00;
                    if (c0 + 1 < N) C[(size_t)r0 * N + c0 + 1] = v01;
                }
                if (r0 + 8 < M) {
                    if (c0 < N)     C[(size_t)(r0 + 8) * N + c0]     = v10;
                    if (c0 + 1 < N) C[(size_t)(r0 + 8) * N + c0 + 1] = v11;
                }
            }
        }
    }
}

// ---------------- mean / logvar heads ---------------------------------------
__global__ void meanlogvar_kernel(const float* __restrict__ en2,
                                  const float* __restrict__ mW, const float* __restrict__ mb,
                                  const float* __restrict__ lW, const float* __restrict__ lb,
                                  float* __restrict__ pm, float* __restrict__ lv)
{
    int t = blockIdx.x * blockDim.x + threadIdx.x;
    if (t >= NB * 4) return;
    int n = t >> 2, j = t & 3;
    const float* w = (j < 2) ? (mW + j * E2) : (lW + (j - 2) * E2);
    const float* x = en2 + (size_t)n * E2;
    float s = 0.f;
    for (int i = 0; i < E2; i += 4) {
        float4 xa = *reinterpret_cast<const float4*>(x + i);
        float4 wa = *reinterpret_cast<const float4*>(w + i);
        s += xa.x * wa.x + xa.y * wa.y + xa.z * wa.z + xa.w * wa.w;
    }
    if (j < 2) pm[n * 2 + j] = s + mb[j];
    else       lv[n * 2 + (j - 2)] = s + lb[j - 2];
}

// =============================================================================
// zc fused: column stats of topics (200x2) + BN apply. One block, 256 thr.
// =============================================================================
__global__ void __launch_bounds__(256)
zc_fused(const float* __restrict__ topics,
         const float* __restrict__ g, const float* __restrict__ b,
         float* __restrict__ o1, float* __restrict__ o2)
{
    __shared__ float4 red[256];
    __shared__ float st[4];
    const int tid = threadIdx.x;
    float x0 = 0.f, x1 = 0.f;
    const bool act = tid < KK;
    if (act) { x0 = topics[tid * 2]; x1 = topics[tid * 2 + 1]; }
    red[tid] = make_float4(x0, x0 * x0, x1, x1 * x1);
    __syncthreads();
    for (int s = 128; s > 0; s >>= 1) {
        if (tid < s) {
            float4 a = red[tid], c = red[tid + s];
            red[tid] = make_float4(a.x + c.x, a.y + c.y, a.z + c.z, a.w + c.w);
        }
        __syncthreads();
    }
    if (tid == 0) {
        float4 r = red[0];
        float m0 = r.x / KK, m1 = r.z / KK;
        st[0] = m0; st[1] = m1;
        st[2] = r.y / KK - m0 * m0;
        st[3] = r.w / KK - m1 * m1;
    }
    __syncthreads();
    if (act) {
        float y0 = g[0] * (x0 - st[0]) * rsqrtf(st[2] + 1e-5f) + b[0];
        float y1 = g[1] * (x1 - st[1]) * rsqrtf(st[3] + 1e-5f) + b[1];
        o1[tid * 2] = y0;     o1[tid * 2 + 1] = y1;
        o2[tid * 2] = y0;     o2[tid * 2 + 1] = y1;
    }
}

// =============================================================================
// Fused mid-section: pm/lv stats -> z -> z stats -> zx.
// =============================================================================
__global__ void __launch_bounds__(1024)
mid_fused(const float* __restrict__ pm, const float* __restrict__ lv,
          const float* __restrict__ epsin,
          const float* __restrict__ gm, const float* __restrict__ bm,
          const float* __restrict__ gl, const float* __restrict__ bl,
          const float* __restrict__ gx, const float* __restrict__ bxx,
          float* __restrict__ out_z, float* __restrict__ s_zx,
          float* __restrict__ out_zx)
{
    __shared__ float4 red[1024];
    __shared__ float st[12];
    const int tid = threadIdx.x;

    auto reduce4 = [&](float s0, float q0, float s1, float q1, int base) {
        red[tid] = make_float4(s0, q0, s1, q1);
        __syncthreads();
        for (int s = 512; s > 0; s >>= 1) {
            if (tid < s) {
                float4 a = red[tid], b2 = red[tid + s];
                red[tid] = make_float4(a.x + b2.x, a.y + b2.y, a.z + b2.z, a.w + b2.w);
            }
            __syncthreads();
        }
        if (tid == 0) {
            float4 r = red[0];
            float m0 = r.x / NB, m1 = r.z / NB;
            st[base + 0] = m0;
            st[base + 1] = m1;
            st[base + 2] = r.y / NB - m0 * m0;
            st[base + 3] = r.w / NB - m1 * m1;
        }
        __syncthreads();
    };

    {
        float s0 = 0, q0 = 0, s1 = 0, q1 = 0;
#pragma unroll
        for (int i = 0; i < 2; i++) {
            int r = tid + i * 1024;
            float x0 = pm[r * 2], x1 = pm[r * 2 + 1];
            s0 += x0; q0 += x0 * x0; s1 += x1; q1 += x1 * x1;
        }
        reduce4(s0, q0, s1, q1, 0);
    }
    {
        float s0 = 0, q0 = 0, s1 = 0, q1 = 0;
#pragma unroll
        for (int i = 0; i < 2; i++) {
            int r = tid + i * 1024;
            float x0 = lv[r * 2], x1 = lv[r * 2 + 1];
            s0 += x0; q0 += x0 * x0; s1 += x1; q1 += x1 * x1;
        }
        reduce4(s0, q0, s1, q1, 4);
    }
    float zr[2][2];
    {
        const float pmi0 = rsqrtf(st[2] + 1e-5f), pmi1 = rsqrtf(st[3] + 1e-5f);
        const float lvi0 = rsqrtf(st[6] + 1e-5f), lvi1 = rsqrtf(st[7] + 1e-5f);
        const float gm0 = gm[0], gm1 = gm[1], bm0 = bm[0], bm1 = bm[1];
        const float gl0 = gl[0], gl1 = gl[1], bl0 = bl[0], bl1 = bl[1];
        float s0 = 0, q0 = 0, s1 = 0, q1 = 0;
#pragma unroll
        for (int i = 0; i < 2; i++) {
            int r = tid + i * 1024;
            float p0 = gm0 * (pm[r * 2] - st[0]) * pmi0 + bm0;
            float p1 = gm1 * (pm[r * 2 + 1] - st[1]) * pmi1 + bm1;
            float l0 = gl0 * (lv[r * 2] - st[4]) * lvi0 + bl0;
            float l1 = gl1 * (lv[r * 2 + 1] - st[5]) * lvi1 + bl1;
            float z0 = p0 + sqrtf(expf(l0)) * epsin[r * 2];
            float z1 = p1 + sqrtf(expf(l1)) * epsin[r * 2 + 1];
            out_z[r * 2] = z0;
            out_z[r * 2 + 1] = z1;
            zr[i][0] = z0; zr[i][1] = z1;
            s0 += z0; q0 += z0 * z0; s1 += z1; q1 += z1 * z1;
        }
        reduce4(s0, q0, s1, q1, 8);
    }
    {
        const float zi0 = rsqrtf(st[10] + 1e-5f), zi1 = rsqrtf(st[11] + 1e-5f);
        const float gx0 = gx[0], gx1 = gx[1], bx0 = bxx[0], bx1 = bxx[1];
#pragma unroll
        for (int i = 0; i < 2; i++) {
            int r = tid + i * 1024;
            float y0 = gx0 * (zr[i][0] - st[8]) * zi0 + bx0;
            float y1 = gx1 * (zr[i][1] - st[9]) * zi1 + bx1;
            s_zx[r * 2] = y0;    s_zx[r * 2 + 1] = y1;
            out_zx[r * 2] = y0;  out_zx[r * 2 + 1] = y1;
        }
    }
}

// ---------------- theta (fp32 outputs + fp16 plane) --------------------------
__global__ void theta_kernel(const float* __restrict__ zx, const float* __restrict__ zc,
                             float* __restrict__ gtheta, float* __restrict__ otheta)
{
    __shared__ float sz[KK * 2];
    __shared__ float red[256];
    __shared__ float sth[KR];
    int n = blockIdx.x, tid = threadIdx.x;
    for (int i = tid; i < KK * 2; i += 256) sz[i] = zc[i];
    __syncthreads();
    float x0 = zx[n * 2], x1 = zx[n * 2 + 1];
    float l = -FLT_MAX;
    if (tid < KK) {
        float dx = x0 - sz[tid * 2];
        float dy = x1 - sz[tid * 2 + 1];
        l = -0.5f * (dx * dx + dy * dy);
    }
    red[tid] = l;
    __syncthreads();
    for (int st = 128; st > 0; st >>= 1) {
        if (tid < st) red[tid] = fmaxf(red[tid], red[tid + st]);
        __syncthreads();
    }
    float mx = red[0];
    __syncthreads();
    float e = (tid < KK) ? expf(l - mx) : 0.f;
    red[tid] = e;
    __syncthreads();
    for (int st = 128; st > 0; st >>= 1) {
        if (tid < st) red[tid] += red[tid + st];
        __syncthreads();
    }
    float inv = 1.f / red[0];
    float th = e * inv;
    if (tid < KK) {
        gtheta[(size_t)n * KK + tid] = th;
        otheta[(size_t)n * KK + tid] = th;
    }
    if (tid < KR) sth[tid] = (tid < KK) ? th : 0.f;
    __syncthreads();
    if (tid < KRW) {
        g_bf[W_TH + (size_t)n * KRW + tid] =
            pk_h2(__float2half_rn(sth[2 * tid]), __float2half_rn(sth[2 * tid + 1]));
    }
}

// ---------------- decoder MLP ------------------------------------------------
__global__ void mu1_kernel(const float* __restrict__ zc, const float* __restrict__ W,
                           const float* __restrict__ b, float* __restrict__ out)
{
    int t = blockIdx.x * 256 + threadIdx.x;
    if (t >= KK * 100) return;
    int k = t / 100, j = t % 100;
    float v = zc[k * 2] * W[j * 2] + zc[k * 2 + 1] * W[j * 2 + 1] + b[j];
    out[t] = softplusf(v);
}

__global__ void mu2_kernel(const float* __restrict__ mu1, const float* __restrict__ W,
                           const float* __restrict__ b, float* __restrict__ out)
{
    __shared__ float row[100];
    int k = blockIdx.x, tid = threadIdx.x;
    if (tid < 100) row[tid] = mu1[k * 100 + tid];
    __syncthreads();
    if (tid < 100) {
        const float* w = W + tid * 100;
        float s = b[tid];
        for (int i = 0; i < 100; i++) s += row[i] * w[i];
        out[k * 100 + tid] = softplusf(s);
    }
}

__global__ void muz_kernel(const float* __restrict__ mu2, const float* __restrict__ W,
                           const float* __restrict__ b, float* __restrict__ out)
{
    __shared__ float row[100];
    int k = blockIdx.x, tid = threadIdx.x;
    if (tid < 100) row[tid] = mu2[k * 100 + tid];
    __syncthreads();
    for (int j = tid; j < EMB; j += 128) {
        const float* w = W + j * 100;
        float s = b[j];
        for (int i = 0; i < 100; i++) s += row[i] * w[i];
        out[k * EMB + j] = s;
    }
}

// =============================================================================
// beta: BN_topic + softmax numerator only (exp-once, __expf); stores
// unnormalized e and per-topic 1/sum; normalization folded into transpose.
// Upper-bound shift keeps exp args <= 0 (softmax shift-invariant).
// =============================================================================
__global__ void __launch_bounds__(1024)
beta_kernel(const float* __restrict__ logits, const float* __restrict__ bbias,
            const float* __restrict__ gdec, const float* __restrict__ bdec,
            float* __restrict__ beta)
{
    __shared__ float rs[1024], rq[1024], rmx[1024], rmn[1024], rmb[1024];
    const int k = blockIdx.x, tid = threadIdx.x;
    const float* row = logits + (size_t)k * VV;
    const float* bb  = bbias + (size_t)k * VV;
    float* brow = beta + (size_t)k * VV;

    float s = 0.f, q = 0.f, mxx = -FLT_MAX, mnx = FLT_MAX, mxb = -FLT_MAX;
    for (int v = tid; v < VV; v += 1024) {
        float x = row[v];
        s += x; q += x * x;
        mxx = fmaxf(mxx, x);
        mnx = fminf(mnx, x);
        mxb = fmaxf(mxb, bb[v]);
    }
    rs[tid] = s; rq[tid] = q; rmx[tid] = mxx; rmn[tid] = mnx; rmb[tid] = mxb;
    __syncthreads();
    for (int st = 512; st > 0; st >>= 1) {
        if (tid < st) {
            rs[tid] += rs[tid + st];
            rq[tid] += rq[tid + st];
            rmx[tid] = fmaxf(rmx[tid], rmx[tid + st]);
            rmn[tid] = fminf(rmn[tid], rmn[tid + st]);
            rmb[tid] = fmaxf(rmb[tid], rmb[tid + st]);
        }
        __syncthreads();
    }
    const float mean = rs[0] / VV;
    const float var  = rq[0] / VV - mean * mean;
    const float scale = gdec[k] * rsqrtf(var + 1e-5f);
    const float shift = bdec[k] - mean * scale;
    const float mx = scale * (scale > 0.f ? rmx[0] : rmn[0]) + shift + rmb[0];
    __syncthreads();

    float se = 0.f;
    for (int v = tid; v < VV; v += 1024) {
        float e = __expf(row[v] * scale + shift + bb[v] - mx);
        brow[v] = e;
        se += e;
    }
    rs[tid] = se;
    __syncthreads();
    for (int st = 512; st > 0; st >>= 1) {
        if (tid < st) rs[tid] += rs[tid + st];
        __syncthreads();
    }
    if (tid == 0) g_binv[k] = 1.f / rs[0];
}

// ---------------- launch -----------------------------------------------------
extern "C" void kernel_launch(void* const* d_in, const int* in_sizes, int n_in,
                              void* d_out, int out_size)
{
    const float* input_   = (const float*)d_in[0];
    const float* eps      = (const float*)d_in[2];
    const float* en1_W    = (const float*)d_in[3];
    const float* en1_b    = (const float*)d_in[4];
    const float* en2_W    = (const float*)d_in[5];
    const float* en2_b    = (const float*)d_in[6];
    const float* mean_W   = (const float*)d_in[7];
    const float* mean_b   = (const float*)d_in[8];
    const float* logvar_W = (const float*)d_in[9];
    const float* logvar_b = (const float*)d_in[10];
    const float* mu1_W    = (const float*)d_in[11];
    const float* mu1_b    = (const float*)d_in[12];
    const float* mu2_W    = (const float*)d_in[13];
    const float* mu2_b    = (const float*)d_in[14];
    const float* mu_W     = (const float*)d_in[15];
    const float* mu_b     = (const float*)d_in[16];
    const float* topics   = (const float*)d_in[17];
    const float* bbias    = (const float*)d_in[18];
    const float* emb      = (const float*)d_in[19];
    const float* g_mean   = (const float*)d_in[20];
    const float* b_mean   = (const float*)d_in[21];
    const float* g_logvar = (const float*)d_in[22];
    const float* b_logvar = (const float*)d_in[23];
    const float* g_x      = (const float*)d_in[24];
    const float* b_x      = (const float*)d_in[25];
    const float* g_phi    = (const float*)d_in[26];
    const float* b_phi    = (const float*)d_in[27];
    const float* g_dec    = (const float*)d_in[28];
    const float* b_dec    = (const float*)d_in[29];

    float* out = (float*)d_out;
    float* out_z     = out;
    float* out_recon = out + (long long)NB * CC;
    float* out_zx    = out_recon + (long long)NB * VV;
    float* out_zc    = out_zx + (long long)NB * CC;
    float* out_theta = out_zc + (long long)KK * CC;

    void* sp = nullptr;
    cudaGetSymbolAddress(&sp, g_scratch);
    float* S = (float*)sp;
    float* s_en1    = S + OFF_EN1;
    float* s_en2    = S + OFF_EN2;
    float* s_pm     = S + OFF_PM;
    float* s_lv     = S + OFF_LV;
    float* s_zx     = S + OFF_ZX;
    float* s_zc     = S + OFF_ZC;
    float* s_theta  = S + OFF_THETA;
    float* s_mu1    = S + OFF_MU1;
    float* s_mu2    = S + OFF_MU2;
    float* s_muz    = S + OFF_MUZ;
    float* s_logits = S + OFF_LOGITS;
    float* s_beta   = S + OFF_BETA;

    cudaFuncSetAttribute(gemm1_fp16_sk, cudaFuncAttributeMaxDynamicSharedMemorySize, G1_SMEM);
    cudaFuncSetAttribute(recon_f16, cudaFuncAttributeMaxDynamicSharedMemorySize, G1_SMEM);
    cudaFuncSetAttribute(gemm_nt_bf16x3<true, true, false>,
                         cudaFuncAttributeMaxDynamicSharedMemorySize, NTB_SMEM);

    // 0) pre-split: A -> 1 fp16 plane, B -> 1 fp16 plane
    split_fp16<<<NB + E1, 256>>>(input_, en1_W);

    // 1-3) decoder-side small kernels
    zc_fused<<<1, 256>>>(topics, g_phi, b_phi, s_zc, out_zc);
    mu1_kernel<<<(KK * 100 + 255) / 256, 256>>>(s_zc, mu1_W, mu1_b, s_mu1);
    mu2_kernel<<<KK, 128>>>(s_mu1, mu2_W, mu2_b, s_mu2);

    // 4) en1 partials — split-K fp16 GEMM (full-chip packing)
    gemm1_fp16_sk<<<dim3(E1 / 128, NB / 128, SK), 256, G1_SMEM>>>();

    // 5) muz
    muz_kernel<<<KK, 128>>>(s_mu2, mu_W, mu_b, s_muz);

    // 6) reduce partials -> en1
    reduce_en1<<<(NB * E1 / 4) / 256, 256>>>(en1_b, s_en1);

    // 7) en2 — bf16x3
    gemm_nt_bf16x3<true, true, false><<<dim3(E2 / 128, NB / 128), 512, NTB_SMEM>>>(
        s_en1, en2_W, en2_b, s_en2, NB, E2, E1);

    // 8) heads
    meanlogvar_kernel<<<(NB * 4 + 255) / 256, 256>>>(
        s_en2, mean_W, mean_b, logvar_W, logvar_b, s_pm, s_lv);

    // 9) fused mid-section
    mid_fused<<<1, 1024>>>(s_pm, s_lv, eps, g_mean, b_mean, g_logvar, b_logvar,
                           g_x, b_x, out_z, s_zx, out_zx);

    // 10) theta
    theta_kernel<<<NB, 256>>>(s_zx, s_zc, s_theta, out_theta);

    // 11) logits = mu_z @ emb^T — tf32 single pass
    logits_tf32<<<dim3((VV + 63) / 64, (KK + 63) / 64), 256>>>(s_muz, emb, s_logits);

    // 12) beta — exp-once, unnormalized + 1/sum
    beta_kernel<<<KK, 1024>>>(s_logits, bbias, g_dec, b_dec, s_beta);

    // 13) beta^T fp16 (applies 1/sum)
    transpose_beta<<<dim3(BTROWS / 32, KR / 32), 256>>>(s_beta);

    // 14) recon = theta @ beta — fp16 NT
    recon_f16<<<dim3(BTROWS / 128, NB / 128), 256, G1_SMEM>>>(out_recon);

    (void)in_sizes; (void)n_in; (void)out_size;
}

// round 16
// speedup vs baseline: 1.6908x; 1.0761x over previous
#include <cuda_runtime.h>
#include <cuda_bf16.h>
#include <cuda_fp16.h>
#include <math.h>
#include <float.h>
#include <stdint.h>

// ---------------- problem dims ----------------
#define NB   2048
#define VV   50000
#define E1   1024
#define E2   512
#define CC   2
#define KK   200
#define EMB  300

#define KP   50048
#define KPW  (KP/2)
#define G1NT (KP / 32)
#define SK   8                   // split-K factor for gemm1

#define KR   224
#define KRW  (KR/2)
#define RNT  (KR / 32)
#define BTROWS 50048

// ---------------- float scratch ----------------------------------------------
#define OFF_EN1    0LL
#define OFF_EN2    (OFF_EN1 + (long long)NB*E1)
#define OFF_PM     (OFF_EN2 + (long long)NB*E2)
#define OFF_LV     (OFF_PM + (long long)NB*CC)
#define OFF_Z      (OFF_LV + (long long)NB*CC)
#define OFF_ZX     (OFF_Z + (long long)NB*CC)
#define OFF_ZC     (OFF_ZX + (long long)NB*CC)
#define OFF_THETA  (OFF_ZC + (long long)KK*CC)
#define OFF_MU1    (OFF_THETA + (long long)NB*KK)
#define OFF_MU2    (OFF_MU1 + (long long)KK*100)
#define OFF_MUZ    (OFF_MU2 + (long long)KK*100)
#define OFF_LOGITS (OFF_MUZ + (long long)KK*EMB)
#define OFF_BETA   (OFF_LOGITS + (long long)KK*VV)
#define OFF_SPM    (OFF_BETA + (long long)KK*VV)
#define OFF_SLV    (OFF_SPM + 4)
#define OFF_SZ     (OFF_SLV + 4)
#define OFF_ST     (OFF_SZ + 4)
#define SCRATCH_FLOATS (OFF_ST + 8)

__device__ float g_scratch[SCRATCH_FLOATS];

// split-K partial planes for gemm1
__device__ __align__(16) float g_part[(long long)SK * NB * E1];
// per-topic 1/sum for beta softmax
__device__ float g_binv[KK];

// ---------------- fp16 planes (words) ----------------------------------------
#define WA 51249152LL
#define WB 25624576LL
#define W_AH 0LL
#define W_BH (W_AH + WA)
#define W_TH (W_BH + WB)
#define TWH  ((long long)NB * KRW)
#define W_BT (W_TH + TWH)
#define BTWH ((long long)BTROWS * KRW)

__device__ __align__(16) uint32_t g_bf[WA + WB + TWH + BTWH];

__device__ __forceinline__ float softplusf(float x) {
    return fmaxf(x, 0.0f) + log1pf(expf(-fabsf(x)));
}

__device__ __forceinline__ uint32_t pk_h2(__half lo, __half hi) {
    return ((uint32_t)__half_as_ushort(hi) << 16) | __half_as_ushort(lo);
}

__device__ __forceinline__ uint32_t pk_bf16(float lo, float hi) {
    uint32_t r;
    asm("cvt.rn.bf16x2.f32 %0, %1, %2;" : "=r"(r) : "f"(hi), "f"(lo));
    return r;
}

__device__ __forceinline__ unsigned tf32_rna(float x) {
    unsigned r;
    asm("cvt.rna.tf32.f32 %0, %1;" : "=r"(r) : "f"(x));
    return r;
}

__device__ __forceinline__ void mma_f16(float* d,
                                        uint32_t a0, uint32_t a1, uint32_t a2, uint32_t a3,
                                        uint32_t b0, uint32_t b1)
{
    asm volatile(
        "mma.sync.aligned.m16n8k16.row.col.f32.f16.f16.f32 "
        "{%0,%1,%2,%3},{%4,%5,%6,%7},{%8,%9},{%0,%1,%2,%3};"
        : "+f"(d[0]), "+f"(d[1]), "+f"(d[2]), "+f"(d[3])
        : "r"(a0), "r"(a1), "r"(a2), "r"(a3), "r"(b0), "r"(b1));
}

__device__ __forceinline__ void mma_bf16(float* d,
                                         uint32_t a0, uint32_t a1, uint32_t a2, uint32_t a3,
                                         uint32_t b0, uint32_t b1)
{
    asm volatile(
        "mma.sync.aligned.m16n8k16.row.col.f32.bf16.bf16.f32 "
        "{%0,%1,%2,%3},{%4,%5,%6,%7},{%8,%9},{%0,%1,%2,%3};"
        : "+f"(d[0]), "+f"(d[1]), "+f"(d[2]), "+f"(d[3])
        : "r"(a0), "r"(a1), "r"(a2), "r"(a3), "r"(b0), "r"(b1));
}

__device__ __forceinline__ void mma_tf32(float* d,
                                         unsigned a0, unsigned a1, unsigned a2, unsigned a3,
                                         unsigned b0, unsigned b1)
{
    asm volatile(
        "mma.sync.aligned.m16n8k8.row.col.f32.tf32.tf32.f32 "
        "{%0,%1,%2,%3},{%4,%5,%6,%7},{%8,%9},{%0,%1,%2,%3};"
        : "+f"(d[0]), "+f"(d[1]), "+f"(d[2]), "+f"(d[3])
        : "r"(a0), "r"(a1), "r"(a2), "r"(a3), "r"(b0), "r"(b1));
}

__device__ __forceinline__ void ldsm_x4(uint32_t& r0, uint32_t& r1, uint32_t& r2,
                                        uint32_t& r3, uint32_t addr)
{
    asm volatile("ldmatrix.sync.aligned.m8n8.x4.shared.b16 {%0,%1,%2,%3}, [%4];"
                 : "=r"(r0), "=r"(r1), "=r"(r2), "=r"(r3) : "r"(addr));
}

// =============================================================================
// Pre-pass: A=input, B=en1_W -> fp16 planes, zero pad.
// =============================================================================
__global__ void __launch_bounds__(256)
split_fp16(const float* __restrict__ A, const float* __restrict__ B)
{
    const int b = blockIdx.x, tid = threadIdx.x;
    const float* src;
    uint32_t* h;
    if (b < NB) {
        src = A + (size_t)b * VV;
        h = g_bf + W_AH + (size_t)b * KPW;
    } else {
        int r = b - NB;
        src = B + (size_t)r * VV;
        h = g_bf + W_BH + (size_t)r * KPW;
    }
    for (int i = tid; i < VV / 4; i += 256) {
        float4 v = *reinterpret_cast<const float4*>(src + i * 4);
        h[2*i]     = pk_h2(__float2half_rn(v.x), __float2half_rn(v.y));
        h[2*i + 1] = pk_h2(__float2half_rn(v.z), __float2half_rn(v.w));
    }
    if (tid < KPW - VV/2) h[VV/2 + tid] = 0u;
}

// =============================================================================
// GEMM1 split-K: partial[ks] = input @ en1_W^T over k-range of split ks.
// =============================================================================
#define STG    20480
#define G1_SMEM (3 * STG)

__global__ void __launch_bounds__(256, 2)
gemm1_fp16_sk()
{
    extern __shared__ __align__(16) char sm[];
    const uint32_t sb32 = (uint32_t)__cvta_generic_to_shared(sm);
    const int tid = threadIdx.x;
    const int lane = tid & 31, warp = tid >> 5;
    const int gid = lane >> 2, tig = lane & 3;
    const int wm = warp >> 1, wn = warp & 1;
    const int m0 = blockIdx.y * 128, n0 = blockIdx.x * 128;
    const int ks = blockIdx.z;
    const int ts = (G1NT * ks) / SK;
    const int te = (G1NT * (ks + 1)) / SK;

    float acc[2][8][4];
#pragma unroll
    for (int i = 0; i < 2; i++)
#pragma unroll
        for (int j = 0; j < 8; j++)
#pragma unroll
            for (int l = 0; l < 4; l++) acc[i][j][l] = 0.0f;

    const uint32_t* gsrc[4];
    uint32_t sdst[4];
#pragma unroll
    for (int i = 0; i < 2; i++) {
        int idx = tid + i * 256;
        int r = idx >> 2, part = idx & 3;
        gsrc[i] = g_bf + W_AH + (size_t)(m0 + r) * KPW + part * 4;
        sdst[i] = sb32 + (uint32_t)(r * 80 + part * 16);
    }
#pragma unroll
    for (int i = 0; i < 2; i++) {
        int idx = tid + i * 256;
        int r = idx >> 2, part = idx & 3;
        gsrc[2 + i] = g_bf + W_BH + (size_t)(n0 + r) * KPW + part * 4;
        sdst[2 + i] = sb32 + (uint32_t)(10240 + r * 80 + part * 16);
    }

    auto issue = [&](int t) {
        const uint32_t boff = (uint32_t)(t % 3) * STG;
        const size_t k = (size_t)t * 16;
#pragma unroll
        for (int i = 0; i < 4; i++)
            asm volatile("cp.async.cg.shared.global [%0], [%1], 16;"
                         :: "r"(sdst[i] + boff), "l"(gsrc[i] + k) : "memory");
        asm volatile("cp.async.commit_group;" ::: "memory");
    };

    const int lr = (lane & 7) + ((lane >> 3) & 1) * 8;
    const int kb = ((lane >> 4) & 1) * 16;
    const uint32_t aoff = (uint32_t)((wm * 32 + lr) * 80 + kb);
    const uint32_t boff2 = (uint32_t)(10240 + (wn * 64 + lr) * 80 + kb);

    issue(ts);
    issue(ts + 1);

    for (int t = ts; t < te; t++) {
        if (t == te - 1) asm volatile("cp.async.wait_group 0;" ::: "memory");
        else             asm volatile("cp.async.wait_group 1;" ::: "memory");
        __syncthreads();
        if (t + 2 < te) issue(t + 2);

        const uint32_t st = sb32 + (uint32_t)(t % 3) * STG;
#pragma unroll
        for (int kkw = 0; kkw < 2; kkw++) {
            const uint32_t ka = st + kkw * 32;
            uint32_t ah[2][4], bq[4][4];
#pragma unroll
            for (int ms = 0; ms < 2; ms++)
                ldsm_x4(ah[ms][0], ah[ms][1], ah[ms][2], ah[ms][3],
                        ka + aoff + ms * 1280);
#pragma unroll
            for (int pr = 0; pr < 4; pr++)
                ldsm_x4(bq[pr][0], bq[pr][1], bq[pr][2], bq[pr][3],
                        ka + boff2 + pr * 1280);
#pragma unroll
            for (int ms = 0; ms < 2; ms++)
#pragma unroll
                for (int pr = 0; pr < 4; pr++)
#pragma unroll
                    for (int j = 0; j < 2; j++) {
                        int ns = pr * 2 + j;
                        mma_f16(acc[ms][ns], ah[ms][0], ah[ms][1], ah[ms][2], ah[ms][3],
                                bq[pr][j], bq[pr][j + 2]);
                    }
        }
    }

    float* P = g_part + (size_t)ks * NB * E1;
#pragma unroll
    for (int ms = 0; ms < 2; ms++) {
        const int r0 = m0 + wm * 32 + ms * 16 + gid;
#pragma unroll
        for (int ns = 0; ns < 8; ns++) {
            const int c0 = n0 + wn * 64 + ns * 8 + 2 * tig;
            P[(size_t)r0 * E1 + c0]           = acc[ms][ns][0];
            P[(size_t)r0 * E1 + c0 + 1]       = acc[ms][ns][1];
            P[(size_t)(r0 + 8) * E1 + c0]     = acc[ms][ns][2];
            P[(size_t)(r0 + 8) * E1 + c0 + 1] = acc[ms][ns][3];
        }
    }
}

// =============================================================================
// reduce partials + bias + softplus -> en1
// =============================================================================
__global__ void __launch_bounds__(256)
reduce_en1(const float* __restrict__ bias, float* __restrict__ C)
{
    const size_t i = (size_t)blockIdx.x * 256 + threadIdx.x;
    float4 s = reinterpret_cast<const float4*>(g_part)[i];
#pragma unroll
    for (int p = 1; p < SK; p++) {
        float4 v = reinterpret_cast<const float4*>(g_part + (size_t)p * NB * E1)[i];
        s.x += v.x; s.y += v.y; s.z += v.z; s.w += v.w;
    }
    const int c = (int)((i * 4) & (E1 - 1));
    s.x = softplusf(s.x + bias[c]);
    s.y = softplusf(s.y + bias[c + 1]);
    s.z = softplusf(s.z + bias[c + 2]);
    s.w = softplusf(s.w + bias[c + 3]);
    reinterpret_cast<float4*>(C)[i] = s;
}

// =============================================================================
// recon = theta @ beta via NT fp16 planes.
// =============================================================================
__global__ void __launch_bounds__(256, 2)
recon_f16(float* __restrict__ C)
{
    extern __shared__ __align__(16) char sm[];
    const uint32_t sb32 = (uint32_t)__cvta_generic_to_shared(sm);
    const int tid = threadIdx.x;
    const int lane = tid & 31, warp = tid >> 5;
    const int gid = lane >> 2, tig = lane & 3;
    const int wm = warp >> 1, wn = warp & 1;
    const int m0 = blockIdx.y * 128, n0 = blockIdx.x * 128;

    float acc[2][8][4];
#pragma unroll
    for (int i = 0; i < 2; i++)
#pragma unroll
        for (int j = 0; j < 8; j++)
#pragma unroll
            for (int l = 0; l < 4; l++) acc[i][j][l] = 0.0f;

    const uint32_t* gsrc[4];
    uint32_t sdst[4];
#pragma unroll
    for (int i = 0; i < 2; i++) {
        int idx = tid + i * 256;
        int r = idx >> 2, part = idx & 3;
        gsrc[i] = g_bf + W_TH + (size_t)(m0 + r) * KRW + part * 4;
        sdst[i] = sb32 + (uint32_t)(r * 80 + part * 16);
    }
#pragma unroll
    for (int i = 0; i < 2; i++) {
        int idx = tid + i * 256;
        int r = idx >> 2, part = idx & 3;
        gsrc[2 + i] = g_bf + W_BT + (size_t)(n0 + r) * KRW + part * 4;
        sdst[2 + i] = sb32 + (uint32_t)(10240 + r * 80 + part * 16);
    }

    auto issue = [&](int t) {
        const uint32_t boff = (uint32_t)(t % 3) * STG;
        const size_t k = (size_t)t * 16;
#pragma unroll
        for (int i = 0; i < 4; i++)
            asm volatile("cp.async.cg.shared.global [%0], [%1], 16;"
                         :: "r"(sdst[i] + boff), "l"(gsrc[i] + k) : "memory");
        asm volatile("cp.async.commit_group;" ::: "memory");
    };

    const int lr = (lane & 7) + ((lane >> 3) & 1) * 8;
    const int kb = ((lane >> 4) & 1) * 16;
    const uint32_t aoff = (uint32_t)((wm * 32 + lr) * 80 + kb);
    const uint32_t boff2 = (uint32_t)(10240 + (wn * 64 + lr) * 80 + kb);

    issue(0);
    issue(1);

    for (int t = 0; t < RNT; t++) {
        if (t == RNT - 1) asm volatile("cp.async.wait_group 0;" ::: "memory");
        else              asm volatile("cp.async.wait_group 1;" ::: "memory");
        __syncthreads();
        if (t + 2 < RNT) issue(t + 2);

        const uint32_t st = sb32 + (uint32_t)(t % 3) * STG;
#pragma unroll
        for (int kkw = 0; kkw < 2; kkw++) {
            const uint32_t ka = st + kkw * 32;
            uint32_t ah[2][4], bq[4][4];
#pragma unroll
            for (int ms = 0; ms < 2; ms++)
                ldsm_x4(ah[ms][0], ah[ms][1], ah[ms][2], ah[ms][3],
                        ka + aoff + ms * 1280);
#pragma unroll
            for (int pr = 0; pr < 4; pr++)
                ldsm_x4(bq[pr][0], bq[pr][1], bq[pr][2], bq[pr][3],
                        ka + boff2 + pr * 1280);
#pragma unroll
            for (int ms = 0; ms < 2; ms++)
#pragma unroll
                for (int pr = 0; pr < 4; pr++)
#pragma unroll
                    for (int j = 0; j < 2; j++) {
                        int ns = pr * 2 + j;
                        mma_f16(acc[ms][ns], ah[ms][0], ah[ms][1], ah[ms][2], ah[ms][3],
                                bq[pr][j], bq[pr][j + 2]);
                    }
        }
    }

#pragma unroll
    for (int ms = 0; ms < 2; ms++) {
        const int r0 = m0 + wm * 32 + ms * 16 + gid;
#pragma unroll
        for (int ns = 0; ns < 8; ns++) {
            const int c0 = n0 + wn * 64 + ns * 8 + 2 * tig;
            if (c0 < VV) {
                C[(size_t)r0 * VV + c0]       = acc[ms][ns][0];
                C[(size_t)(r0 + 8) * VV + c0] = acc[ms][ns][2];
            }
            if (c0 + 1 < VV) {
                C[(size_t)r0 * VV + c0 + 1]       = acc[ms][ns][1];
                C[(size_t)(r0 + 8) * VV + c0 + 1] = acc[ms][ns][3];
            }
        }
    }
}

// =============================================================================
// beta^T fp16 with softmax normalization applied during conversion.
// =============================================================================
__global__ void __launch_bounds__(256)
transpose_beta(const float* __restrict__ beta)
{
    __shared__ float s[32][33];
    __shared__ float sinv[32];
    const int tid = threadIdx.x;
    const int tx = tid & 31, ty = tid >> 5;
    const int v0 = blockIdx.x * 32, k0 = blockIdx.y * 32;

    if (tid < 32) {
        int gk = k0 + tid;
        sinv[tid] = (gk < KK) ? g_binv[gk] : 0.f;
    }
#pragma unroll
    for (int i = 0; i < 4; i++) {
        int k = ty + i * 8;
        int gk = k0 + k, gv = v0 + tx;
        float val = 0.f;
        if (gk < KK && gv < VV) val = beta[(size_t)gk * VV + gv];
        s[k][tx] = val;
    }
    __syncthreads();

#pragma unroll
    for (int i = 0; i < 2; i++) {
        int w = tid + i * 256;
        int v = w >> 4, kw = w & 15;
        uint32_t word = pk_h2(__float2half_rn(s[2 * kw][v] * sinv[2 * kw]),
                              __float2half_rn(s[2 * kw + 1][v] * sinv[2 * kw + 1]));
        g_bf[W_BT + (size_t)(v0 + v) * KRW + (k0 >> 1) + kw] = word;
    }
}

// =============================================================================
// logits = mu_z[200,300] @ emb[50000,300]^T — single-pass tf32.
// =============================================================================
__global__ void __launch_bounds__(256)
logits_tf32(const float* __restrict__ A, const float* __restrict__ B,
            float* __restrict__ C)
{
    __shared__ float As[64][20];
    __shared__ float Bs[64][20];
    const int tid = threadIdx.x;
    const int lane = tid & 31, warp = tid >> 5;
    const int gid = lane >> 2, tig = lane & 3;
    const int wm = warp >> 1, wn = warp & 1;
    const int m0 = blockIdx.y * 64, n0 = blockIdx.x * 64;

    float acc[4][4];
#pragma unroll
    for (int j = 0; j < 4; j++)
#pragma unroll
        for (int l = 0; l < 4; l++) acc[j][l] = 0.0f;

    const int row = tid >> 2, q = (tid & 3) * 4;

    for (int k0 = 0; k0 < EMB; k0 += 16) {
        const int gk = k0 + q;
        {
            int gm = m0 + row;
            float4 v = make_float4(0.f, 0.f, 0.f, 0.f);
            if (gm < KK) {
                const float* p = A + (size_t)gm * EMB;
                if (gk + 3 < EMB) v = *reinterpret_cast<const float4*>(p + gk);
                else {
                    if (gk + 0 < EMB) v.x = p[gk + 0];
                    if (gk + 1 < EMB) v.y = p[gk + 1];
                    if (gk + 2 < EMB) v.z = p[gk + 2];
                    if (gk + 3 < EMB) v.w = p[gk + 3];
                }
            }
            As[row][q + 0] = __uint_as_float(tf32_rna(v.x));
            As[row][q + 1] = __uint_as_float(tf32_rna(v.y));
            As[row][q + 2] = __uint_as_float(tf32_rna(v.z));
            As[row][q + 3] = __uint_as_float(tf32_rna(v.w));
        }
        {
            int gn = n0 + row;
            float4 v = make_float4(0.f, 0.f, 0.f, 0.f);
            if (gn < VV) {
                const float* p = B + (size_t)gn * EMB;
                if (gk + 3 < EMB) v = *reinterpret_cast<const float4*>(p + gk);
                else {
                    if (gk + 0 < EMB) v.x = p[gk + 0];
                    if (gk + 1 < EMB) v.y = p[gk + 1];
                    if (gk + 2 < EMB) v.z = p[gk + 2];
                    if (gk + 3 < EMB) v.w = p[gk + 3];
                }
            }
            Bs[row][q + 0] = __uint_as_float(tf32_rna(v.x));
            Bs[row][q + 1] = __uint_as_float(tf32_rna(v.y));
            Bs[row][q + 2] = __uint_as_float(tf32_rna(v.z));
            Bs[row][q + 3] = __uint_as_float(tf32_rna(v.w));
        }
        __syncthreads();

#pragma unroll
        for (int kk = 0; kk < 16; kk += 8) {
            unsigned a[4], b[4][2];
            int r = wm * 16 + gid;
            a[0] = __float_as_uint(As[r][kk + tig]);
            a[1] = __float_as_uint(As[r + 8][kk + tig]);
            a[2] = __float_as_uint(As[r][kk + tig + 4]);
            a[3] = __float_as_uint(As[r + 8][kk + tig + 4]);
#pragma unroll
            for (int ns = 0; ns < 4; ns++) {
                int n = wn * 32 + ns * 8 + gid;
                b[ns][0] = __float_as_uint(Bs[n][kk + tig]);
                b[ns][1] = __float_as_uint(Bs[n][kk + tig + 4]);
            }
#pragma unroll
            for (int ns = 0; ns < 4; ns++)
                mma_tf32(acc[ns], a[0], a[1], a[2], a[3], b[ns][0], b[ns][1]);
        }
        __syncthreads();
    }

    const int r0 = m0 + wm * 16 + gid;
#pragma unroll
    for (int ns = 0; ns < 4; ns++) {
        const int c0 = n0 + wn * 32 + ns * 8 + 2 * tig;
        if (r0 < KK) {
            if (c0 < VV)     C[(size_t)r0 * VV + c0]     = acc[ns][0];
            if (c0 + 1 < VV) C[(size_t)r0 * VV + c0 + 1] = acc[ns][1];
        }
        if (r0 + 8 < KK) {
            if (c0 < VV)     C[(size_t)(r0 + 8) * VV + c0]     = acc[ns][2];
            if (c0 + 1 < VV) C[(size_t)(r0 + 8) * VV + c0 + 1] = acc[ns][3];
        }
    }
}

// ============================ bf16x3 NT GEMM (en2) ===========================
#define NTB_SMEM (2 * 10240 * 4)

template<bool SP, bool HB, bool CHKMN>
__global__ void __launch_bounds__(512, 1)
gemm_nt_bf16x3(const float* __restrict__ A, const float* __restrict__ B,
               const float* __restrict__ bias, float* __restrict__ C,
               int M, int N, int K)
{
    extern __shared__ __align__(16) uint32_t sw[];
    const int tid = threadIdx.x;
    const int lane = tid & 31, warp = tid >> 5;
    const int gid = lane >> 2, tig = lane & 3;
    const int wm = warp >> 2, wn = warp & 3;
    const int m0 = blockIdx.y * 128, n0 = blockIdx.x * 128;
    const int nt = (K + 31) / 32;

    float acc[2][4][4];
#pragma unroll
    for (int i = 0; i < 2; i++)
#pragma unroll
        for (int j = 0; j < 4; j++)
#pragma unroll
            for (int l = 0; l < 4; l++) acc[i][j][l] = 0.0f;

    const int srow = tid >> 3;
    const int sq   = tid & 7;
    float4 stA[2], stB[2];

    auto load_tile = [&](int t) {
        const int gk = t * 32 + sq * 4;
#pragma unroll
        for (int l = 0; l < 2; l++) {
            int r = srow + l * 64;
            {
                int gm = m0 + r;
                float4 v = make_float4(0.f, 0.f, 0.f, 0.f);
                if (((!CHKMN) || gm < M)) {
                    if (gk + 3 < K) v = *reinterpret_cast<const float4*>(A + (size_t)gm * K + gk);
                    else if (gk < K) {
                        const float* p = A + (size_t)gm * K;
                        v.x = p[gk];
                        if (gk + 1 < K) v.y = p[gk + 1];
                        if (gk + 2 < K) v.z = p[gk + 2];
                    }
                }
                stA[l] = v;
            }
            {
                int gn = n0 + r;
                float4 v = make_float4(0.f, 0.f, 0.f, 0.f);
                if (((!CHKMN) || gn < N)) {
                    if (gk + 3 < K) v = *reinterpret_cast<const float4*>(B + (size_t)gn * K + gk);
                    else if (gk < K) {
                        const float* p = B + (size_t)gn * K;
                        v.x = p[gk];
                        if (gk + 1 < K) v.y = p[gk + 1];
                        if (gk + 2 < K) v.z = p[gk + 2];
                    }
                }
                stB[l] = v;
            }
        }
    };

    auto store_tile = [&](uint32_t* buf) {
#pragma unroll
        for (int l = 0; l < 2; l++) {
            int r = srow + l * 64;
            uint32_t w = (uint32_t)(r * 20 + sq * 2);
            {
                float4 v = stA[l];
                __nv_bfloat16 hx = __float2bfloat16_rn(v.x), hy = __float2bfloat16_rn(v.y);
                __nv_bfloat16 hz = __float2bfloat16_rn(v.z), hw = __float2bfloat16_rn(v.w);
                buf[w]     = ((uint32_t)__bfloat16_as_ushort(hy) << 16) | __bfloat16_as_ushort(hx);
                buf[w + 1] = ((uint32_t)__bfloat16_as_ushort(hw) << 16) | __bfloat16_as_ushort(hz);
                buf[w + 2560]     = pk_bf16(v.x - __bfloat162float(hx), v.y - __bfloat162float(hy));
                buf[w + 2560 + 1] = pk_bf16(v.z - __bfloat162float(hz), v.w - __bfloat162float(hw));
            }
            {
                float4 v = stB[l];
                __nv_bfloat16 hx = __float2bfloat16_rn(v.x), hy = __float2bfloat16_rn(v.y);
                __nv_bfloat16 hz = __float2bfloat16_rn(v.z), hw = __float2bfloat16_rn(v.w);
                buf[w + 5120]     = ((uint32_t)__bfloat16_as_ushort(hy) << 16) | __bfloat16_as_ushort(hx);
                buf[w + 5120 + 1] = ((uint32_t)__bfloat16_as_ushort(hw) << 16) | __bfloat16_as_ushort(hz);
                buf[w + 7680]     = pk_bf16(v.x - __bfloat162float(hx), v.y - __bfloat162float(hy));
                buf[w + 7680 + 1] = pk_bf16(v.z - __bfloat162float(hz), v.w - __bfloat162float(hw));
            }
        }
    };

    load_tile(0);
    store_tile(sw);
    __syncthreads();

    for (int t = 0; t < nt; t++) {
        const int b = t & 1;
        uint32_t* bb = sw + b * 10240;
        if (t + 1 < nt) load_tile(t + 1);

#pragma unroll
        for (int kkw = 0; kkw < 16; kkw += 8) {
            uint32_t ah[2][4], al[2][4], bh[4][2], bl[4][2];
#pragma unroll
            for (int ms = 0; ms < 2; ms++) {
                int base = (wm * 32 + ms * 16 + gid) * 20 + kkw + tig;
                ah[ms][0] = bb[base];       ah[ms][1] = bb[base + 160];
                ah[ms][2] = bb[base + 4];   ah[ms][3] = bb[base + 164];
                al[ms][0] = bb[base + 2560];       al[ms][1] = bb[base + 2560 + 160];
                al[ms][2] = bb[base + 2560 + 4];   al[ms][3] = bb[base + 2560 + 164];
            }
#pragma unroll
            for (int ns = 0; ns < 4; ns++) {
                int base = 5120 + (wn * 32 + ns * 8 + gid) * 20 + kkw + tig;
                bh[ns][0] = bb[base];       bh[ns][1] = bb[base + 4];
                bl[ns][0] = bb[base + 2560]; bl[ns][1] = bb[base + 2560 + 4];
            }
#pragma unroll
            for (int ms = 0; ms < 2; ms++)
#pragma unroll
                for (int ns = 0; ns < 4; ns++) {
                    mma_bf16(acc[ms][ns], ah[ms][0], ah[ms][1], ah[ms][2], ah[ms][3],
                             bh[ns][0], bh[ns][1]);
                    mma_bf16(acc[ms][ns], ah[ms][0], ah[ms][1], ah[ms][2], ah[ms][3],
                             bl[ns][0], bl[ns][1]);
                    mma_bf16(acc[ms][ns], al[ms][0], al[ms][1], al[ms][2], al[ms][3],
                             bh[ns][0], bh[ns][1]);
                }
        }

        if (t + 1 < nt) store_tile(sw + (b ^ 1) * 10240);
        __syncthreads();
    }

#pragma unroll
    for (int ms = 0; ms < 2; ms++) {
        int r0 = m0 + wm * 32 + ms * 16 + gid;
#pragma unroll
        for (int ns = 0; ns < 4; ns++) {
            int c0 = n0 + wn * 32 + ns * 8 + 2 * tig;
            float bv0 = 0.f, bv1 = 0.f;
            if (HB) { bv0 = bias[c0]; bv1 = bias[c0 + 1]; }
            float v00 = acc[ms][ns][0] + bv0;
            float v01 = acc[ms][ns][1] + bv1;
            float v10 = acc[ms][ns][2] + bv0;
            float v11 = acc[ms][ns][3] + bv1;
            if (SP) { v00 = softplusf(v00); v01 = softplusf(v01);
                      v10 = softplusf(v10); v11 = softplusf(v11); }
            if (!CHKMN) {
                C[(size_t)r0 * N + c0]           = v00;
                C[(size_t)r0 * N + c0 + 1]       = v01;
                C[(size_t)(r0 + 8) * N + c0]     = v10;
                C[(size_t)(r0 + 8) * N + c0 + 1] = v11;
            } else {
                if (r0 < M) {
                    if (c0 < N)     C[(size_t)r0 * N + c0]     = v00;
                    if (c0 + 1 < N) C[(size_t)r0 * N + c0 + 1] = v01;
                }
                if (r0 + 8 < M) {
                    if (c0 < N)     C[(size_t)(r0 + 8) * N + c0]     = v10;
                    if (c0 + 1 < N) C[(size_t)(r0 + 8) * N + c0 + 1] = v11;
                }
            }
        }
    }
}

// ---------------- mean / logvar heads ---------------------------------------
__global__ void meanlogvar_kernel(const float* __restrict__ en2,
                                  const float* __restrict__ mW, const float* __restrict__ mb,
                                  const float* __restrict__ lW, const float* __restrict__ lb,
                                  float* __restrict__ pm, float* __restrict__ lv)
{
    int t = blockIdx.x * blockDim.x + threadIdx.x;
    if (t >= NB * 4) return;
    int n = t >> 2, j = t & 3;
    const float* w = (j < 2) ? (mW + j * E2) : (lW + (j - 2) * E2);
    const float* x = en2 + (size_t)n * E2;
    float s = 0.f;
    for (int i = 0; i < E2; i += 4) {
        float4 xa = *reinterpret_cast<const float4*>(x + i);
        float4 wa = *reinterpret_cast<const float4*>(w + i);
        s += xa.x * wa.x + xa.y * wa.y + xa.z * wa.z + xa.w * wa.w;
    }
    if (j < 2) pm[n * 2 + j] = s + mb[j];
    else       lv[n * 2 + (j - 2)] = s + lb[j - 2];
}

// =============================================================================
// zc fused: column stats of topics (200x2) + BN apply.
// =============================================================================
__global__ void __launch_bounds__(256)
zc_fused(const float* __restrict__ topics,
         const float* __restrict__ g, const float* __restrict__ b,
         float* __restrict__ o1, float* __restrict__ o2)
{
    __shared__ float4 red[256];
    __shared__ float st[4];
    const int tid = threadIdx.x;
    float x0 = 0.f, x1 = 0.f;
    const bool act = tid < KK;
    if (act) { x0 = topics[tid * 2]; x1 = topics[tid * 2 + 1]; }
    red[tid] = make_float4(x0, x0 * x0, x1, x1 * x1);
    __syncthreads();
    for (int s = 128; s > 0; s >>= 1) {
        if (tid < s) {
            float4 a = red[tid], c = red[tid + s];
            red[tid] = make_float4(a.x + c.x, a.y + c.y, a.z + c.z, a.w + c.w);
        }
        __syncthreads();
    }
    if (tid == 0) {
        float4 r = red[0];
        float m0 = r.x / KK, m1 = r.z / KK;
        st[0] = m0; st[1] = m1;
        st[2] = r.y / KK - m0 * m0;
        st[3] = r.w / KK - m1 * m1;
    }
    __syncthreads();
    if (act) {
        float y0 = g[0] * (x0 - st[0]) * rsqrtf(st[2] + 1e-5f) + b[0];
        float y1 = g[1] * (x1 - st[1]) * rsqrtf(st[3] + 1e-5f) + b[1];
        o1[tid * 2] = y0;     o1[tid * 2 + 1] = y1;
        o2[tid * 2] = y0;     o2[tid * 2 + 1] = y1;
    }
}

// =============================================================================
// Fused mid-section: pm/lv stats -> z -> z stats -> zx.
// =============================================================================
__global__ void __launch_bounds__(1024)
mid_fused(const float* __restrict__ pm, const float* __restrict__ lv,
          const float* __restrict__ epsin,
          const float* __restrict__ gm, const float* __restrict__ bm,
          const float* __restrict__ gl, const float* __restrict__ bl,
          const float* __restrict__ gx, const float* __restrict__ bxx,
          float* __restrict__ out_z, float* __restrict__ s_zx,
          float* __restrict__ out_zx)
{
    __shared__ float4 red[1024];
    __shared__ float st[12];
    const int tid = threadIdx.x;

    auto reduce4 = [&](float s0, float q0, float s1, float q1, int base) {
        red[tid] = make_float4(s0, q0, s1, q1);
        __syncthreads();
        for (int s = 512; s > 0; s >>= 1) {
            if (tid < s) {
                float4 a = red[tid], b2 = red[tid + s];
                red[tid] = make_float4(a.x + b2.x, a.y + b2.y, a.z + b2.z, a.w + b2.w);
            }
            __syncthreads();
        }
        if (tid == 0) {
            float4 r = red[0];
            float m0 = r.x / NB, m1 = r.z / NB;
            st[base + 0] = m0;
            st[base + 1] = m1;
            st[base + 2] = r.y / NB - m0 * m0;
            st[base + 3] = r.w / NB - m1 * m1;
        }
        __syncthreads();
    };

    {
        float s0 = 0, q0 = 0, s1 = 0, q1 = 0;
#pragma unroll
        for (int i = 0; i < 2; i++) {
            int r = tid + i * 1024;
            float x0 = pm[r * 2], x1 = pm[r * 2 + 1];
            s0 += x0; q0 += x0 * x0; s1 += x1; q1 += x1 * x1;
        }
        reduce4(s0, q0, s1, q1, 0);
    }
    {
        float s0 = 0, q0 = 0, s1 = 0, q1 = 0;
#pragma unroll
        for (int i = 0; i < 2; i++) {
            int r = tid + i * 1024;
            float x0 = lv[r * 2], x1 = lv[r * 2 + 1];
            s0 += x0; q0 += x0 * x0; s1 += x1; q1 += x1 * x1;
        }
        reduce4(s0, q0, s1, q1, 4);
    }
    float zr[2][2];
    {
        const float pmi0 = rsqrtf(st[2] + 1e-5f), pmi1 = rsqrtf(st[3] + 1e-5f);
        const float lvi0 = rsqrtf(st[6] + 1e-5f), lvi1 = rsqrtf(st[7] + 1e-5f);
        const float gm0 = gm[0], gm1 = gm[1], bm0 = bm[0], bm1 = bm[1];
        const float gl0 = gl[0], gl1 = gl[1], bl0 = bl[0], bl1 = bl[1];
        float s0 = 0, q0 = 0, s1 = 0, q1 = 0;
#pragma unroll
        for (int i = 0; i < 2; i++) {
            int r = tid + i * 1024;
            float p0 = gm0 * (pm[r * 2] - st[0]) * pmi0 + bm0;
            float p1 = gm1 * (pm[r * 2 + 1] - st[1]) * pmi1 + bm1;
            float l0 = gl0 * (lv[r * 2] - st[4]) * lvi0 + bl0;
            float l1 = gl1 * (lv[r * 2 + 1] - st[5]) * lvi1 + bl1;
            float z0 = p0 + sqrtf(expf(l0)) * epsin[r * 2];
            float z1 = p1 + sqrtf(expf(l1)) * epsin[r * 2 + 1];
            out_z[r * 2] = z0;
            out_z[r * 2 + 1] = z1;
            zr[i][0] = z0; zr[i][1] = z1;
            s0 += z0; q0 += z0 * z0; s1 += z1; q1 += z1 * z1;
        }
        reduce4(s0, q0, s1, q1, 8);
    }
    {
        const float zi0 = rsqrtf(st[10] + 1e-5f), zi1 = rsqrtf(st[11] + 1e-5f);
        const float gx0 = gx[0], gx1 = gx[1], bx0 = bxx[0], bx1 = bxx[1];
#pragma unroll
        for (int i = 0; i < 2; i++) {
            int r = tid + i * 1024;
            float y0 = gx0 * (zr[i][0] - st[8]) * zi0 + bx0;
            float y1 = gx1 * (zr[i][1] - st[9]) * zi1 + bx1;
            s_zx[r * 2] = y0;    s_zx[r * 2 + 1] = y1;
            out_zx[r * 2] = y0;  out_zx[r * 2 + 1] = y1;
        }
    }
}

// ---------------- theta (fp32 outputs + fp16 plane) --------------------------
__global__ void theta_kernel(const float* __restrict__ zx, const float* __restrict__ zc,
                             float* __restrict__ gtheta, float* __restrict__ otheta)
{
    __shared__ float sz[KK * 2];
    __shared__ float red[256];
    __shared__ float sth[KR];
    int n = blockIdx.x, tid = threadIdx.x;
    for (int i = tid; i < KK * 2; i += 256) sz[i] = zc[i];
    __syncthreads();
    float x0 = zx[n * 2], x1 = zx[n * 2 + 1];
    float l = -FLT_MAX;
    if (tid < KK) {
        float dx = x0 - sz[tid * 2];
        float dy = x1 - sz[tid * 2 + 1];
        l = -0.5f * (dx * dx + dy * dy);
    }
    red[tid] = l;
    __syncthreads();
    for (int st = 128; st > 0; st >>= 1) {
        if (tid < st) red[tid] = fmaxf(red[tid], red[tid + st]);
        __syncthreads();
    }
    float mx = red[0];
    __syncthreads();
    float e = (tid < KK) ? expf(l - mx) : 0.f;
    red[tid] = e;
    __syncthreads();
    for (int st = 128; st > 0; st >>= 1) {
        if (tid < st) red[tid] += red[tid + st];
        __syncthreads();
    }
    float inv = 1.f / red[0];
    float th = e * inv;
    if (tid < KK) {
        gtheta[(size_t)n * KK + tid] = th;
        otheta[(size_t)n * KK + tid] = th;
    }
    if (tid < KR) sth[tid] = (tid < KK) ? th : 0.f;
    __syncthreads();
    if (tid < KRW) {
        g_bf[W_TH + (size_t)n * KRW + tid] =
            pk_h2(__float2half_rn(sth[2 * tid]), __float2half_rn(sth[2 * tid + 1]));
    }
}

// ---------------- decoder MLP ------------------------------------------------
__global__ void mu1_kernel(const float* __restrict__ zc, const float* __restrict__ W,
                           const float* __restrict__ b, float* __restrict__ out)
{
    int t = blockIdx.x * 256 + threadIdx.x;
    if (t >= KK * 100) return;
    int k = t / 100, j = t % 100;
    float v = zc[k * 2] * W[j * 2] + zc[k * 2 + 1] * W[j * 2 + 1] + b[j];
    out[t] = softplusf(v);
}

__global__ void mu2_kernel(const float* __restrict__ mu1, const float* __restrict__ W,
                           const float* __restrict__ b, float* __restrict__ out)
{
    __shared__ float row[100];
    int k = blockIdx.x, tid = threadIdx.x;
    if (tid < 100) row[tid] = mu1[k * 100 + tid];
    __syncthreads();
    if (tid < 100) {
        const float* w = W + tid * 100;
        float s = b[tid];
        for (int i = 0; i < 100; i++) s += row[i] * w[i];
        out[k * 100 + tid] = softplusf(s);
    }
}

__global__ void muz_kernel(const float* __restrict__ mu2, const float* __restrict__ W,
                           const float* __restrict__ b, float* __restrict__ out)
{
    __shared__ float row[100];
    int k = blockIdx.x, tid = threadIdx.x;
    if (tid < 100) row[tid] = mu2[k * 100 + tid];
    __syncthreads();
    for (int j = tid; j < EMB; j += 128) {
        const float* w = W + j * 100;
        float s = b[j];
        for (int i = 0; i < 100; i++) s += row[i] * w[i];
        out[k * EMB + j] = s;
    }
}

// =============================================================================
// beta: BN_topic + softmax numerator only (exp-once, __expf).
// =============================================================================
__global__ void __launch_bounds__(1024)
beta_kernel(const float* __restrict__ logits, const float* __restrict__ bbias,
            const float* __restrict__ gdec, const float* __restrict__ bdec,
            float* __restrict__ beta)
{
    __shared__ float rs[1024], rq[1024], rmx[1024], rmn[1024], rmb[1024];
    const int k = blockIdx.x, tid = threadIdx.x;
    const float* row = logits + (size_t)k * VV;
    const float* bb  = bbias + (size_t)k * VV;
    float* brow = beta + (size_t)k * VV;

    float s = 0.f, q = 0.f, mxx = -FLT_MAX, mnx = FLT_MAX, mxb = -FLT_MAX;
    for (int v = tid; v < VV; v += 1024) {
        float x = row[v];
        s += x; q += x * x;
        mxx = fmaxf(mxx, x);
        mnx = fminf(mnx, x);
        mxb = fmaxf(mxb, bb[v]);
    }
    rs[tid] = s; rq[tid] = q; rmx[tid] = mxx; rmn[tid] = mnx; rmb[tid] = mxb;
    __syncthreads();
    for (int st = 512; st > 0; st >>= 1) {
        if (tid < st) {
            rs[tid] += rs[tid + st];
            rq[tid] += rq[tid + st];
            rmx[tid] = fmaxf(rmx[tid], rmx[tid + st]);
            rmn[tid] = fminf(rmn[tid], rmn[tid + st]);
            rmb[tid] = fmaxf(rmb[tid], rmb[tid + st]);
        }
        __syncthreads();
    }
    const float mean = rs[0] / VV;
    const float var  = rq[0] / VV - mean * mean;
    const float scale = gdec[k] * rsqrtf(var + 1e-5f);
    const float shift = bdec[k] - mean * scale;
    const float mx = scale * (scale > 0.f ? rmx[0] : rmn[0]) + shift + rmb[0];
    __syncthreads();

    float se = 0.f;
    for (int v = tid; v < VV; v += 1024) {
        float e = __expf(row[v] * scale + shift + bb[v] - mx);
        brow[v] = e;
        se += e;
    }
    rs[tid] = se;
    __syncthreads();
    for (int st = 512; st > 0; st >>= 1) {
        if (tid < st) rs[tid] += rs[tid + st];
        __syncthreads();
    }
    if (tid == 0) g_binv[k] = 1.f / rs[0];
}

// ---------------- launch -----------------------------------------------------
extern "C" void kernel_launch(void* const* d_in, const int* in_sizes, int n_in,
                              void* d_out, int out_size)
{
    const float* input_   = (const float*)d_in[0];
    const float* eps      = (const float*)d_in[2];
    const float* en1_W    = (const float*)d_in[3];
    const float* en1_b    = (const float*)d_in[4];
    const float* en2_W    = (const float*)d_in[5];
    const float* en2_b    = (const float*)d_in[6];
    const float* mean_W   = (const float*)d_in[7];
    const float* mean_b   = (const float*)d_in[8];
    const float* logvar_W = (const float*)d_in[9];
    const float* logvar_b = (const float*)d_in[10];
    const float* mu1_W    = (const float*)d_in[11];
    const float* mu1_b    = (const float*)d_in[12];
    const float* mu2_W    = (const float*)d_in[13];
    const float* mu2_b    = (const float*)d_in[14];
    const float* mu_W     = (const float*)d_in[15];
    const float* mu_b     = (const float*)d_in[16];
    const float* topics   = (const float*)d_in[17];
    const float* bbias    = (const float*)d_in[18];
    const float* emb      = (const float*)d_in[19];
    const float* g_mean   = (const float*)d_in[20];
    const float* b_mean   = (const float*)d_in[21];
    const float* g_logvar = (const float*)d_in[22];
    const float* b_logvar = (const float*)d_in[23];
    const float* g_x      = (const float*)d_in[24];
    const float* b_x      = (const float*)d_in[25];
    const float* g_phi    = (const float*)d_in[26];
    const float* b_phi    = (const float*)d_in[27];
    const float* g_dec    = (const float*)d_in[28];
    const float* b_dec    = (const float*)d_in[29];

    float* out = (float*)d_out;
    float* out_z     = out;
    float* out_recon = out + (long long)NB * CC;
    float* out_zx    = out_recon + (long long)NB * VV;
    float* out_zc    = out_zx + (long long)NB * CC;
    float* out_theta = out_zc + (long long)KK * CC;

    void* sp = nullptr;
    cudaGetSymbolAddress(&sp, g_scratch);
    float* S = (float*)sp;
    float* s_en1    = S + OFF_EN1;
    float* s_en2    = S + OFF_EN2;
    float* s_pm     = S + OFF_PM;
    float* s_lv     = S + OFF_LV;
    float* s_zx     = S + OFF_ZX;
    float* s_zc     = S + OFF_ZC;
    float* s_theta  = S + OFF_THETA;
    float* s_mu1    = S + OFF_MU1;
    float* s_mu2    = S + OFF_MU2;
    float* s_muz    = S + OFF_MUZ;
    float* s_logits = S + OFF_LOGITS;
    float* s_beta   = S + OFF_BETA;

    // lazily created host objects (no device allocation)
    static cudaStream_t s_dec = nullptr;
    static cudaEvent_t ev_fork = nullptr, ev_zc = nullptr, ev_join = nullptr;
    if (s_dec == nullptr) {
        cudaStreamCreateWithFlags(&s_dec, cudaStreamNonBlocking);
        cudaEventCreateWithFlags(&ev_fork, cudaEventDisableTiming);
        cudaEventCreateWithFlags(&ev_zc, cudaEventDisableTiming);
        cudaEventCreateWithFlags(&ev_join, cudaEventDisableTiming);
        cudaFuncSetAttribute(gemm1_fp16_sk, cudaFuncAttributeMaxDynamicSharedMemorySize, G1_SMEM);
        cudaFuncSetAttribute(recon_f16, cudaFuncAttributeMaxDynamicSharedMemorySize, G1_SMEM);
        cudaFuncSetAttribute(gemm_nt_bf16x3<true, true, false>,
                             cudaFuncAttributeMaxDynamicSharedMemorySize, NTB_SMEM);
    }

    // ---- fork decoder chain onto s_dec ----
    cudaEventRecord(ev_fork, 0);
    cudaStreamWaitEvent(s_dec, ev_fork, 0);

    // decoder chain (lightweight; only logits_tf32 touches tensor pipes ~60us)
    zc_fused<<<1, 256, 0, s_dec>>>(topics, g_phi, b_phi, s_zc, out_zc);
    cudaEventRecord(ev_zc, s_dec);
    mu1_kernel<<<(KK * 100 + 255) / 256, 256, 0, s_dec>>>(s_zc, mu1_W, mu1_b, s_mu1);
    mu2_kernel<<<KK, 128, 0, s_dec>>>(s_mu1, mu2_W, mu2_b, s_mu2);
    muz_kernel<<<KK, 128, 0, s_dec>>>(s_mu2, mu_W, mu_b, s_muz);
    logits_tf32<<<dim3((VV + 63) / 64, (KK + 63) / 64), 256, 0, s_dec>>>(s_muz, emb, s_logits);
    beta_kernel<<<KK, 1024, 0, s_dec>>>(s_logits, bbias, g_dec, b_dec, s_beta);
    transpose_beta<<<dim3(BTROWS / 32, KR / 32), 256, 0, s_dec>>>(s_beta);
    cudaEventRecord(ev_join, s_dec);

    // encoder chain on stream 0
    split_fp16<<<NB + E1, 256>>>(input_, en1_W);
    gemm1_fp16_sk<<<dim3(E1 / 128, NB / 128, SK), 256, G1_SMEM>>>();
    reduce_en1<<<(NB * E1 / 4) / 256, 256>>>(en1_b, s_en1);
    gemm_nt_bf16x3<true, true, false><<<dim3(E2 / 128, NB / 128), 512, NTB_SMEM>>>(
        s_en1, en2_W, en2_b, s_en2, NB, E2, E1);
    meanlogvar_kernel<<<(NB * 4 + 255) / 256, 256>>>(
        s_en2, mean_W, mean_b, logvar_W, logvar_b, s_pm, s_lv);
    mid_fused<<<1, 1024>>>(s_pm, s_lv, eps, g_mean, b_mean, g_logvar, b_logvar,
                           g_x, b_x, out_z, s_zx, out_zx);

    // theta needs zc from decoder chain
    cudaStreamWaitEvent(0, ev_zc, 0);
    theta_kernel<<<NB, 256>>>(s_zx, s_zc, s_theta, out_theta);

    // join: recon needs theta (stream 0) + beta^T (s_dec)
    cudaStreamWaitEvent(0, ev_join, 0);
    recon_f16<<<dim3(BTROWS / 128, NB / 128), 256, G1_SMEM>>>(out_recon);

    (void)in_sizes; (void)n_in; (void)out_size;
}

// round 17
// speedup vs baseline: 1.6945x; 1.0022x over previous
#include <cuda_runtime.h>
#include <cuda_bf16.h>
#include <cuda_fp16.h>
#include <math.h>
#include <float.h>
#include <stdint.h>

// ---------------- problem dims ----------------
#define NB   2048
#define VV   50000
#define E1   1024
#define E2   512
#define CC   2
#define KK   200
#define EMB  300

#define KP   50048
#define KPW  (KP/2)
#define G1NT (KP / 32)
#define SK   8                   // split-K factor for gemm1

#define KR   224
#define KRW  (KR/2)
#define RNT  (KR / 32)
#define BTROWS 50048

// ---------------- float scratch ----------------------------------------------
#define OFF_EN1    0LL
#define OFF_EN2    (OFF_EN1 + (long long)NB*E1)
#define OFF_PM     (OFF_EN2 + (long long)NB*E2)
#define OFF_LV     (OFF_PM + (long long)NB*CC)
#define OFF_Z      (OFF_LV + (long long)NB*CC)
#define OFF_ZX     (OFF_Z + (long long)NB*CC)
#define OFF_ZC     (OFF_ZX + (long long)NB*CC)
#define OFF_THETA  (OFF_ZC + (long long)KK*CC)
#define OFF_MU1    (OFF_THETA + (long long)NB*KK)
#define OFF_MU2    (OFF_MU1 + (long long)KK*100)
#define OFF_MUZ    (OFF_MU2 + (long long)KK*100)
#define OFF_LOGITS (OFF_MUZ + (long long)KK*EMB)
#define OFF_BETA   (OFF_LOGITS + (long long)KK*VV)
#define OFF_SPM    (OFF_BETA + (long long)KK*VV)
#define OFF_SLV    (OFF_SPM + 4)
#define OFF_SZ     (OFF_SLV + 4)
#define OFF_ST     (OFF_SZ + 4)
#define SCRATCH_FLOATS (OFF_ST + 8)

__device__ float g_scratch[SCRATCH_FLOATS];

// split-K partial planes for gemm1
__device__ __align__(16) float g_part[(long long)SK * NB * E1];
// per-topic 1/sum for beta softmax
__device__ float g_binv[KK];

// ---------------- fp16 planes (words) ----------------------------------------
#define WA 51249152LL
#define WB 25624576LL
#define W_AH 0LL
#define W_BH (W_AH + WA)
#define W_TH (W_BH + WB)
#define TWH  ((long long)NB * KRW)
#define W_BT (W_TH + TWH)
#define BTWH ((long long)BTROWS * KRW)

__device__ __align__(16) uint32_t g_bf[WA + WB + TWH + BTWH];

__device__ __forceinline__ float softplusf(float x) {
    return fmaxf(x, 0.0f) + log1pf(expf(-fabsf(x)));
}

__device__ __forceinline__ uint32_t pk_h2(__half lo, __half hi) {
    return ((uint32_t)__half_as_ushort(hi) << 16) | __half_as_ushort(lo);
}

__device__ __forceinline__ uint32_t pk_bf16(float lo, float hi) {
    uint32_t r;
    asm("cvt.rn.bf16x2.f32 %0, %1, %2;" : "=r"(r) : "f"(hi), "f"(lo));
    return r;
}

__device__ __forceinline__ unsigned tf32_rna(float x) {
    unsigned r;
    asm("cvt.rna.tf32.f32 %0, %1;" : "=r"(r) : "f"(x));
    return r;
}

__device__ __forceinline__ void mma_f16(float* d,
                                        uint32_t a0, uint32_t a1, uint32_t a2, uint32_t a3,
                                        uint32_t b0, uint32_t b1)
{
    asm volatile(
        "mma.sync.aligned.m16n8k16.row.col.f32.f16.f16.f32 "
        "{%0,%1,%2,%3},{%4,%5,%6,%7},{%8,%9},{%0,%1,%2,%3};"
        : "+f"(d[0]), "+f"(d[1]), "+f"(d[2]), "+f"(d[3])
        : "r"(a0), "r"(a1), "r"(a2), "r"(a3), "r"(b0), "r"(b1));
}

__device__ __forceinline__ void mma_bf16(float* d,
                                         uint32_t a0, uint32_t a1, uint32_t a2, uint32_t a3,
                                         uint32_t b0, uint32_t b1)
{
    asm volatile(
        "mma.sync.aligned.m16n8k16.row.col.f32.bf16.bf16.f32 "
        "{%0,%1,%2,%3},{%4,%5,%6,%7},{%8,%9},{%0,%1,%2,%3};"
        : "+f"(d[0]), "+f"(d[1]), "+f"(d[2]), "+f"(d[3])
        : "r"(a0), "r"(a1), "r"(a2), "r"(a3), "r"(b0), "r"(b1));
}

__device__ __forceinline__ void mma_tf32(float* d,
                                         unsigned a0, unsigned a1, unsigned a2, unsigned a3,
                                         unsigned b0, unsigned b1)
{
    asm volatile(
        "mma.sync.aligned.m16n8k8.row.col.f32.tf32.tf32.f32 "
        "{%0,%1,%2,%3},{%4,%5,%6,%7},{%8,%9},{%0,%1,%2,%3};"
        : "+f"(d[0]), "+f"(d[1]), "+f"(d[2]), "+f"(d[3])
        : "r"(a0), "r"(a1), "r"(a2), "r"(a3), "r"(b0), "r"(b1));
}

__device__ __forceinline__ void ldsm_x4(uint32_t& r0, uint32_t& r1, uint32_t& r2,
                                        uint32_t& r3, uint32_t addr)
{
    asm volatile("ldmatrix.sync.aligned.m8n8.x4.shared.b16 {%0,%1,%2,%3}, [%4];"
                 : "=r"(r0), "=r"(r1), "=r"(r2), "=r"(r3) : "r"(addr));
}

// =============================================================================
// Pre-pass: A=input, B=en1_W -> fp16 planes, zero pad.
// =============================================================================
__global__ void __launch_bounds__(256)
split_fp16(const float* __restrict__ A, const float* __restrict__ B)
{
    const int b = blockIdx.x, tid = threadIdx.x;
    const float* src;
    uint32_t* h;
    if (b < NB) {
        src = A + (size_t)b * VV;
        h = g_bf + W_AH + (size_t)b * KPW;
    } else {
        int r = b - NB;
        src = B + (size_t)r * VV;
        h = g_bf + W_BH + (size_t)r * KPW;
    }
    for (int i = tid; i < VV / 4; i += 256) {
        float4 v = *reinterpret_cast<const float4*>(src + i * 4);
        h[2*i]     = pk_h2(__float2half_rn(v.x), __float2half_rn(v.y));
        h[2*i + 1] = pk_h2(__float2half_rn(v.z), __float2half_rn(v.w));
    }
    if (tid < KPW - VV/2) h[VV/2 + tid] = 0u;
}

// =============================================================================
// GEMM1 split-K: partial[ks] = input @ en1_W^T over k-range of split ks.
// =============================================================================
#define STG    20480
#define G1_SMEM (3 * STG)

__global__ void __launch_bounds__(256, 2)
gemm1_fp16_sk()
{
    extern __shared__ __align__(16) char sm[];
    const uint32_t sb32 = (uint32_t)__cvta_generic_to_shared(sm);
    const int tid = threadIdx.x;
    const int lane = tid & 31, warp = tid >> 5;
    const int gid = lane >> 2, tig = lane & 3;
    const int wm = warp >> 1, wn = warp & 1;
    const int m0 = blockIdx.y * 128, n0 = blockIdx.x * 128;
    const int ks = blockIdx.z;
    const int ts = (G1NT * ks) / SK;
    const int te = (G1NT * (ks + 1)) / SK;

    float acc[2][8][4];
#pragma unroll
    for (int i = 0; i < 2; i++)
#pragma unroll
        for (int j = 0; j < 8; j++)
#pragma unroll
            for (int l = 0; l < 4; l++) acc[i][j][l] = 0.0f;

    const uint32_t* gsrc[4];
    uint32_t sdst[4];
#pragma unroll
    for (int i = 0; i < 2; i++) {
        int idx = tid + i * 256;
        int r = idx >> 2, part = idx & 3;
        gsrc[i] = g_bf + W_AH + (size_t)(m0 + r) * KPW + part * 4;
        sdst[i] = sb32 + (uint32_t)(r * 80 + part * 16);
    }
#pragma unroll
    for (int i = 0; i < 2; i++) {
        int idx = tid + i * 256;
        int r = idx >> 2, part = idx & 3;
        gsrc[2 + i] = g_bf + W_BH + (size_t)(n0 + r) * KPW + part * 4;
        sdst[2 + i] = sb32 + (uint32_t)(10240 + r * 80 + part * 16);
    }

    auto issue = [&](int t) {
        const uint32_t boff = (uint32_t)(t % 3) * STG;
        const size_t k = (size_t)t * 16;
#pragma unroll
        for (int i = 0; i < 4; i++)
            asm volatile("cp.async.cg.shared.global [%0], [%1], 16;"
                         :: "r"(sdst[i] + boff), "l"(gsrc[i] + k) : "memory");
        asm volatile("cp.async.commit_group;" ::: "memory");
    };

    const int lr = (lane & 7) + ((lane >> 3) & 1) * 8;
    const int kb = ((lane >> 4) & 1) * 16;
    const uint32_t aoff = (uint32_t)((wm * 32 + lr) * 80 + kb);
    const uint32_t boff2 = (uint32_t)(10240 + (wn * 64 + lr) * 80 + kb);

    issue(ts);
    issue(ts + 1);

    for (int t = ts; t < te; t++) {
        if (t == te - 1) asm volatile("cp.async.wait_group 0;" ::: "memory");
        else             asm volatile("cp.async.wait_group 1;" ::: "memory");
        __syncthreads();
        if (t + 2 < te) issue(t + 2);

        const uint32_t st = sb32 + (uint32_t)(t % 3) * STG;
#pragma unroll
        for (int kkw = 0; kkw < 2; kkw++) {
            const uint32_t ka = st + kkw * 32;
            uint32_t ah[2][4], bq[4][4];
#pragma unroll
            for (int ms = 0; ms < 2; ms++)
                ldsm_x4(ah[ms][0], ah[ms][1], ah[ms][2], ah[ms][3],
                        ka + aoff + ms * 1280);
#pragma unroll
            for (int pr = 0; pr < 4; pr++)
                ldsm_x4(bq[pr][0], bq[pr][1], bq[pr][2], bq[pr][3],
                        ka + boff2 + pr * 1280);
#pragma unroll
            for (int ms = 0; ms < 2; ms++)
#pragma unroll
                for (int pr = 0; pr < 4; pr++)
#pragma unroll
                    for (int j = 0; j < 2; j++) {
                        int ns = pr * 2 + j;
                        mma_f16(acc[ms][ns], ah[ms][0], ah[ms][1], ah[ms][2], ah[ms][3],
                                bq[pr][j], bq[pr][j + 2]);
                    }
        }
    }

    float* P = g_part + (size_t)ks * NB * E1;
#pragma unroll
    for (int ms = 0; ms < 2; ms++) {
        const int r0 = m0 + wm * 32 + ms * 16 + gid;
#pragma unroll
        for (int ns = 0; ns < 8; ns++) {
            const int c0 = n0 + wn * 64 + ns * 8 + 2 * tig;
            P[(size_t)r0 * E1 + c0]           = acc[ms][ns][0];
            P[(size_t)r0 * E1 + c0 + 1]       = acc[ms][ns][1];
            P[(size_t)(r0 + 8) * E1 + c0]     = acc[ms][ns][2];
            P[(size_t)(r0 + 8) * E1 + c0 + 1] = acc[ms][ns][3];
        }
    }
}

// =============================================================================
// reduce partials + bias + softplus -> en1
// =============================================================================
__global__ void __launch_bounds__(256)
reduce_en1(const float* __restrict__ bias, float* __restrict__ C)
{
    const size_t i = (size_t)blockIdx.x * 256 + threadIdx.x;
    float4 s = reinterpret_cast<const float4*>(g_part)[i];
#pragma unroll
    for (int p = 1; p < SK; p++) {
        float4 v = reinterpret_cast<const float4*>(g_part + (size_t)p * NB * E1)[i];
        s.x += v.x; s.y += v.y; s.z += v.z; s.w += v.w;
    }
    const int c = (int)((i * 4) & (E1 - 1));
    s.x = softplusf(s.x + bias[c]);
    s.y = softplusf(s.y + bias[c + 1]);
    s.z = softplusf(s.z + bias[c + 2]);
    s.w = softplusf(s.w + bias[c + 3]);
    reinterpret_cast<float4*>(C)[i] = s;
}

// =============================================================================
// recon = theta @ beta via NT fp16 planes.
// =============================================================================
__global__ void __launch_bounds__(256, 2)
recon_f16(float* __restrict__ C)
{
    extern __shared__ __align__(16) char sm[];
    const uint32_t sb32 = (uint32_t)__cvta_generic_to_shared(sm);
    const int tid = threadIdx.x;
    const int lane = tid & 31, warp = tid >> 5;
    const int gid = lane >> 2, tig = lane & 3;
    const int wm = warp >> 1, wn = warp & 1;
    const int m0 = blockIdx.y * 128, n0 = blockIdx.x * 128;

    float acc[2][8][4];
#pragma unroll
    for (int i = 0; i < 2; i++)
#pragma unroll
        for (int j = 0; j < 8; j++)
#pragma unroll
            for (int l = 0; l < 4; l++) acc[i][j][l] = 0.0f;

    const uint32_t* gsrc[4];
    uint32_t sdst[4];
#pragma unroll
    for (int i = 0; i < 2; i++) {
        int idx = tid + i * 256;
        int r = idx >> 2, part = idx & 3;
        gsrc[i] = g_bf + W_TH + (size_t)(m0 + r) * KRW + part * 4;
        sdst[i] = sb32 + (uint32_t)(r * 80 + part * 16);
    }
#pragma unroll
    for (int i = 0; i < 2; i++) {
        int idx = tid + i * 256;
        int r = idx >> 2, part = idx & 3;
        gsrc[2 + i] = g_bf + W_BT + (size_t)(n0 + r) * KRW + part * 4;
        sdst[2 + i] = sb32 + (uint32_t)(10240 + r * 80 + part * 16);
    }

    auto issue = [&](int t) {
        const uint32_t boff = (uint32_t)(t % 3) * STG;
        const size_t k = (size_t)t * 16;
#pragma unroll
        for (int i = 0; i < 4; i++)
            asm volatile("cp.async.cg.shared.global [%0], [%1], 16;"
                         :: "r"(sdst[i] + boff), "l"(gsrc[i] + k) : "memory");
        asm volatile("cp.async.commit_group;" ::: "memory");
    };

    const int lr = (lane & 7) + ((lane >> 3) & 1) * 8;
    const int kb = ((lane >> 4) & 1) * 16;
    const uint32_t aoff = (uint32_t)((wm * 32 + lr) * 80 + kb);
    const uint32_t boff2 = (uint32_t)(10240 + (wn * 64 + lr) * 80 + kb);

    issue(0);
    issue(1);

    for (int t = 0; t < RNT; t++) {
        if (t == RNT - 1) asm volatile("cp.async.wait_group 0;" ::: "memory");
        else              asm volatile("cp.async.wait_group 1;" ::: "memory");
        __syncthreads();
        if (t + 2 < RNT) issue(t + 2);

        const uint32_t st = sb32 + (uint32_t)(t % 3) * STG;
#pragma unroll
        for (int kkw = 0; kkw < 2; kkw++) {
            const uint32_t ka = st + kkw * 32;
            uint32_t ah[2][4], bq[4][4];
#pragma unroll
            for (int ms = 0; ms < 2; ms++)
                ldsm_x4(ah[ms][0], ah[ms][1], ah[ms][2], ah[ms][3],
                        ka + aoff + ms * 1280);
#pragma unroll
            for (int pr = 0; pr < 4; pr++)
                ldsm_x4(bq[pr][0], bq[pr][1], bq[pr][2], bq[pr][3],
                        ka + boff2 + pr * 1280);
#pragma unroll
            for (int ms = 0; ms < 2; ms++)
#pragma unroll
                for (int pr = 0; pr < 4; pr++)
#pragma unroll
                    for (int j = 0; j < 2; j++) {
                        int ns = pr * 2 + j;
                        mma_f16(acc[ms][ns], ah[ms][0], ah[ms][1], ah[ms][2], ah[ms][3],
                                bq[pr][j], bq[pr][j + 2]);
                    }
        }
    }

#pragma unroll
    for (int ms = 0; ms < 2; ms++) {
        const int r0 = m0 + wm * 32 + ms * 16 + gid;
#pragma unroll
        for (int ns = 0; ns < 8; ns++) {
            const int c0 = n0 + wn * 64 + ns * 8 + 2 * tig;
            if (c0 < VV) {
                C[(size_t)r0 * VV + c0]       = acc[ms][ns][0];
                C[(size_t)(r0 + 8) * VV + c0] = acc[ms][ns][2];
            }
            if (c0 + 1 < VV) {
                C[(size_t)r0 * VV + c0 + 1]       = acc[ms][ns][1];
                C[(size_t)(r0 + 8) * VV + c0 + 1] = acc[ms][ns][3];
            }
        }
    }
}

// =============================================================================
// beta^T fp16 with softmax normalization applied during conversion.
// =============================================================================
__global__ void __launch_bounds__(256)
transpose_beta(const float* __restrict__ beta)
{
    __shared__ float s[32][33];
    __shared__ float sinv[32];
    const int tid = threadIdx.x;
    const int tx = tid & 31, ty = tid >> 5;
    const int v0 = blockIdx.x * 32, k0 = blockIdx.y * 32;

    if (tid < 32) {
        int gk = k0 + tid;
        sinv[tid] = (gk < KK) ? g_binv[gk] : 0.f;
    }
#pragma unroll
    for (int i = 0; i < 4; i++) {
        int k = ty + i * 8;
        int gk = k0 + k, gv = v0 + tx;
        float val = 0.f;
        if (gk < KK && gv < VV) val = beta[(size_t)gk * VV + gv];
        s[k][tx] = val;
    }
    __syncthreads();

#pragma unroll
    for (int i = 0; i < 2; i++) {
        int w = tid + i * 256;
        int v = w >> 4, kw = w & 15;
        uint32_t word = pk_h2(__float2half_rn(s[2 * kw][v] * sinv[2 * kw]),
                              __float2half_rn(s[2 * kw + 1][v] * sinv[2 * kw + 1]));
        g_bf[W_BT + (size_t)(v0 + v) * KRW + (k0 >> 1) + kw] = word;
    }
}

// =============================================================================
// logits = mu_z[200,300] @ emb[50000,300]^T — single-pass tf32.
// =============================================================================
__global__ void __launch_bounds__(256)
logits_tf32(const float* __restrict__ A, const float* __restrict__ B,
            float* __restrict__ C)
{
    __shared__ float As[64][20];
    __shared__ float Bs[64][20];
    const int tid = threadIdx.x;
    const int lane = tid & 31, warp = tid >> 5;
    const int gid = lane >> 2, tig = lane & 3;
    const int wm = warp >> 1, wn = warp & 1;
    const int m0 = blockIdx.y * 64, n0 = blockIdx.x * 64;

    float acc[4][4];
#pragma unroll
    for (int j = 0; j < 4; j++)
#pragma unroll
        for (int l = 0; l < 4; l++) acc[j][l] = 0.0f;

    const int row = tid >> 2, q = (tid & 3) * 4;

    for (int k0 = 0; k0 < EMB; k0 += 16) {
        const int gk = k0 + q;
        {
            int gm = m0 + row;
            float4 v = make_float4(0.f, 0.f, 0.f, 0.f);
            if (gm < KK) {
                const float* p = A + (size_t)gm * EMB;
                if (gk + 3 < EMB) v = *reinterpret_cast<const float4*>(p + gk);
                else {
                    if (gk + 0 < EMB) v.x = p[gk + 0];
                    if (gk + 1 < EMB) v.y = p[gk + 1];
                    if (gk + 2 < EMB) v.z = p[gk + 2];
                    if (gk + 3 < EMB) v.w = p[gk + 3];
                }
            }
            As[row][q + 0] = __uint_as_float(tf32_rna(v.x));
            As[row][q + 1] = __uint_as_float(tf32_rna(v.y));
            As[row][q + 2] = __uint_as_float(tf32_rna(v.z));
            As[row][q + 3] = __uint_as_float(tf32_rna(v.w));
        }
        {
            int gn = n0 + row;
            float4 v = make_float4(0.f, 0.f, 0.f, 0.f);
            if (gn < VV) {
                const float* p = B + (size_t)gn * EMB;
                if (gk + 3 < EMB) v = *reinterpret_cast<const float4*>(p + gk);
                else {
                    if (gk + 0 < EMB) v.x = p[gk + 0];
                    if (gk + 1 < EMB) v.y = p[gk + 1];
                    if (gk + 2 < EMB) v.z = p[gk + 2];
                    if (gk + 3 < EMB) v.w = p[gk + 3];
                }
            }
            Bs[row][q + 0] = __uint_as_float(tf32_rna(v.x));
            Bs[row][q + 1] = __uint_as_float(tf32_rna(v.y));
            Bs[row][q + 2] = __uint_as_float(tf32_rna(v.z));
            Bs[row][q + 3] = __uint_as_float(tf32_rna(v.w));
        }
        __syncthreads();

#pragma unroll
        for (int kk = 0; kk < 16; kk += 8) {
            unsigned a[4], b[4][2];
            int r = wm * 16 + gid;
            a[0] = __float_as_uint(As[r][kk + tig]);
            a[1] = __float_as_uint(As[r + 8][kk + tig]);
            a[2] = __float_as_uint(As[r][kk + tig + 4]);
            a[3] = __float_as_uint(As[r + 8][kk + tig + 4]);
#pragma unroll
            for (int ns = 0; ns < 4; ns++) {
                int n = wn * 32 + ns * 8 + gid;
                b[ns][0] = __float_as_uint(Bs[n][kk + tig]);
                b[ns][1] = __float_as_uint(Bs[n][kk + tig + 4]);
            }
#pragma unroll
            for (int ns = 0; ns < 4; ns++)
                mma_tf32(acc[ns], a[0], a[1], a[2], a[3], b[ns][0], b[ns][1]);
        }
        __syncthreads();
    }

    const int r0 = m0 + wm * 16 + gid;
#pragma unroll
    for (int ns = 0; ns < 4; ns++) {
        const int c0 = n0 + wn * 32 + ns * 8 + 2 * tig;
        if (r0 < KK) {
            if (c0 < VV)     C[(size_t)r0 * VV + c0]     = acc[ns][0];
            if (c0 + 1 < VV) C[(size_t)r0 * VV + c0 + 1] = acc[ns][1];
        }
        if (r0 + 8 < KK) {
            if (c0 < VV)     C[(size_t)(r0 + 8) * VV + c0]     = acc[ns][2];
            if (c0 + 1 < VV) C[(size_t)(r0 + 8) * VV + c0 + 1] = acc[ns][3];
        }
    }
}

// ============================ bf16x3 NT GEMM (en2) ===========================
#define NTB_SMEM (2 * 10240 * 4)

template<bool SP, bool HB, bool CHKMN>
__global__ void __launch_bounds__(512, 1)
gemm_nt_bf16x3(const float* __restrict__ A, const float* __restrict__ B,
               const float* __restrict__ bias, float* __restrict__ C,
               int M, int N, int K)
{
    extern __shared__ __align__(16) uint32_t sw[];
    const int tid = threadIdx.x;
    const int lane = tid & 31, warp = tid >> 5;
    const int gid = lane >> 2, tig = lane & 3;
    const int wm = warp >> 2, wn = warp & 3;
    const int m0 = blockIdx.y * 128, n0 = blockIdx.x * 128;
    const int nt = (K + 31) / 32;

    float acc[2][4][4];
#pragma unroll
    for (int i = 0; i < 2; i++)
#pragma unroll
        for (int j = 0; j < 4; j++)
#pragma unroll
            for (int l = 0; l < 4; l++) acc[i][j][l] = 0.0f;

    const int srow = tid >> 3;
    const int sq   = tid & 7;
    float4 stA[2], stB[2];

    auto load_tile = [&](int t) {
        const int gk = t * 32 + sq * 4;
#pragma unroll
        for (int l = 0; l < 2; l++) {
            int r = srow + l * 64;
            {
                int gm = m0 + r;
                float4 v = make_float4(0.f, 0.f, 0.f, 0.f);
                if (((!CHKMN) || gm < M)) {
                    if (gk + 3 < K) v = *reinterpret_cast<const float4*>(A + (size_t)gm * K + gk);
                    else if (gk < K) {
                        const float* p = A + (size_t)gm * K;
                        v.x = p[gk];
                        if (gk + 1 < K) v.y = p[gk + 1];
                        if (gk + 2 < K) v.z = p[gk + 2];
                    }
                }
                stA[l] = v;
            }
            {
                int gn = n0 + r;
                float4 v = make_float4(0.f, 0.f, 0.f, 0.f);
                if (((!CHKMN) || gn < N)) {
                    if (gk + 3 < K) v = *reinterpret_cast<const float4*>(B + (size_t)gn * K + gk);
                    else if (gk < K) {
                        const float* p = B + (size_t)gn * K;
                        v.x = p[gk];
                        if (gk + 1 < K) v.y = p[gk + 1];
                        if (gk + 2 < K) v.z = p[gk + 2];
                    }
                }
                stB[l] = v;
            }
        }
    };

    auto store_tile = [&](uint32_t* buf) {
#pragma unroll
        for (int l = 0; l < 2; l++) {
            int r = srow + l * 64;
            uint32_t w = (uint32_t)(r * 20 + sq * 2);
            {
                float4 v = stA[l];
                __nv_bfloat16 hx = __float2bfloat16_rn(v.x), hy = __float2bfloat16_rn(v.y);
                __nv_bfloat16 hz = __float2bfloat16_rn(v.z), hw = __float2bfloat16_rn(v.w);
                buf[w]     = ((uint32_t)__bfloat16_as_ushort(hy) << 16) | __bfloat16_as_ushort(hx);
                buf[w + 1] = ((uint32_t)__bfloat16_as_ushort(hw) << 16) | __bfloat16_as_ushort(hz);
                buf[w + 2560]     = pk_bf16(v.x - __bfloat162float(hx), v.y - __bfloat162float(hy));
                buf[w + 2560 + 1] = pk_bf16(v.z - __bfloat162float(hz), v.w - __bfloat162float(hw));
            }
            {
                float4 v = stB[l];
                __nv_bfloat16 hx = __float2bfloat16_rn(v.x), hy = __float2bfloat16_rn(v.y);
                __nv_bfloat16 hz = __float2bfloat16_rn(v.z), hw = __float2bfloat16_rn(v.w);
                buf[w + 5120]     = ((uint32_t)__bfloat16_as_ushort(hy) << 16) | __bfloat16_as_ushort(hx);
                buf[w + 5120 + 1] = ((uint32_t)__bfloat16_as_ushort(hw) << 16) | __bfloat16_as_ushort(hz);
                buf[w + 7680]     = pk_bf16(v.x - __bfloat162float(hx), v.y - __bfloat162float(hy));
                buf[w + 7680 + 1] = pk_bf16(v.z - __bfloat162float(hz), v.w - __bfloat162float(hw));
            }
        }
    };

    load_tile(0);
    store_tile(sw);
    __syncthreads();

    for (int t = 0; t < nt; t++) {
        const int b = t & 1;
        uint32_t* bb = sw + b * 10240;
        if (t + 1 < nt) load_tile(t + 1);

#pragma unroll
        for (int kkw = 0; kkw < 16; kkw += 8) {
            uint32_t ah[2][4], al[2][4], bh[4][2], bl[4][2];
#pragma unroll
            for (int ms = 0; ms < 2; ms++) {
                int base = (wm * 32 + ms * 16 + gid) * 20 + kkw + tig;
                ah[ms][0] = bb[base];       ah[ms][1] = bb[base + 160];
                ah[ms][2] = bb[base + 4];   ah[ms][3] = bb[base + 164];
                al[ms][0] = bb[base + 2560];       al[ms][1] = bb[base + 2560 + 160];
                al[ms][2] = bb[base + 2560 + 4];   al[ms][3] = bb[base + 2560 + 164];
            }
#pragma unroll
            for (int ns = 0; ns < 4; ns++) {
                int base = 5120 + (wn * 32 + ns * 8 + gid) * 20 + kkw + tig;
                bh[ns][0] = bb[base];       bh[ns][1] = bb[base + 4];
                bl[ns][0] = bb[base + 2560]; bl[ns][1] = bb[base + 2560 + 4];
            }
#pragma unroll
            for (int ms = 0; ms < 2; ms++)
#pragma unroll
                for (int ns = 0; ns < 4; ns++) {
                    mma_bf16(acc[ms][ns], ah[ms][0], ah[ms][1], ah[ms][2], ah[ms][3],
                             bh[ns][0], bh[ns][1]);
                    mma_bf16(acc[ms][ns], ah[ms][0], ah[ms][1], ah[ms][2], ah[ms][3],
                             bl[ns][0], bl[ns][1]);
                    mma_bf16(acc[ms][ns], al[ms][0], al[ms][1], al[ms][2], al[ms][3],
                             bh[ns][0], bh[ns][1]);
                }
        }

        if (t + 1 < nt) store_tile(sw + (b ^ 1) * 10240);
        __syncthreads();
    }

#pragma unroll
    for (int ms = 0; ms < 2; ms++) {
        int r0 = m0 + wm * 32 + ms * 16 + gid;
#pragma unroll
        for (int ns = 0; ns < 4; ns++) {
            int c0 = n0 + wn * 32 + ns * 8 + 2 * tig;
            float bv0 = 0.f, bv1 = 0.f;
            if (HB) { bv0 = bias[c0]; bv1 = bias[c0 + 1]; }
            float v00 = acc[ms][ns][0] + bv0;
            float v01 = acc[ms][ns][1] + bv1;
            float v10 = acc[ms][ns][2] + bv0;
            float v11 = acc[ms][ns][3] + bv1;
            if (SP) { v00 = softplusf(v00); v01 = softplusf(v01);
                      v10 = softplusf(v10); v11 = softplusf(v11); }
            if (!CHKMN) {
                C[(size_t)r0 * N + c0]           = v00;
                C[(size_t)r0 * N + c0 + 1]       = v01;
                C[(size_t)(r0 + 8) * N + c0]     = v10;
                C[(size_t)(r0 + 8) * N + c0 + 1] = v11;
            } else {
                if (r0 < M) {
                    if (c0 < N)     C[(size_t)r0 * N + c0]     = v00;
                    if (c0 + 1 < N) C[(size_t)r0 * N + c0 + 1] = v01;
                }
                if (r0 + 8 < M) {
                    if (c0 < N)     C[(size_t)(r0 + 8) * N + c0]     = v10;
                    if (c0 + 1 < N) C[(size_t)(r0 + 8) * N + c0 + 1] = v11;
                }
            }
        }
    }
}

// ---------------- mean / logvar heads ---------------------------------------
__global__ void meanlogvar_kernel(const float* __restrict__ en2,
                                  const float* __restrict__ mW, const float* __restrict__ mb,
                                  const float* __restrict__ lW, const float* __restrict__ lb,
                                  float* __restrict__ pm, float* __restrict__ lv)
{
    int t = blockIdx.x * blockDim.x + threadIdx.x;
    if (t >= NB * 4) return;
    int n = t >> 2, j = t & 3;
    const float* w = (j < 2) ? (mW + j * E2) : (lW + (j - 2) * E2);
    const float* x = en2 + (size_t)n * E2;
    float s = 0.f;
    for (int i = 0; i < E2; i += 4) {
        float4 xa = *reinterpret_cast<const float4*>(x + i);
        float4 wa = *reinterpret_cast<const float4*>(w + i);
        s += xa.x * wa.x + xa.y * wa.y + xa.z * wa.z + xa.w * wa.w;
    }
    if (j < 2) pm[n * 2 + j] = s + mb[j];
    else       lv[n * 2 + (j - 2)] = s + lb[j - 2];
}

// =============================================================================
// zc fused: column stats of topics (200x2) + BN apply.
// =============================================================================
__global__ void __launch_bounds__(256)
zc_fused(const float* __restrict__ topics,
         const float* __restrict__ g, const float* __restrict__ b,
         float* __restrict__ o1, float* __restrict__ o2)
{
    __shared__ float4 red[256];
    __shared__ float st[4];
    const int tid = threadIdx.x;
    float x0 = 0.f, x1 = 0.f;
    const bool act = tid < KK;
    if (act) { x0 = topics[tid * 2]; x1 = topics[tid * 2 + 1]; }
    red[tid] = make_float4(x0, x0 * x0, x1, x1 * x1);
    __syncthreads();
    for (int s = 128; s > 0; s >>= 1) {
        if (tid < s) {
            float4 a = red[tid], c = red[tid + s];
            red[tid] = make_float4(a.x + c.x, a.y + c.y, a.z + c.z, a.w + c.w);
        }
        __syncthreads();
    }
    if (tid == 0) {
        float4 r = red[0];
        float m0 = r.x / KK, m1 = r.z / KK;
        st[0] = m0; st[1] = m1;
        st[2] = r.y / KK - m0 * m0;
        st[3] = r.w / KK - m1 * m1;
    }
    __syncthreads();
    if (act) {
        float y0 = g[0] * (x0 - st[0]) * rsqrtf(st[2] + 1e-5f) + b[0];
        float y1 = g[1] * (x1 - st[1]) * rsqrtf(st[3] + 1e-5f) + b[1];
        o1[tid * 2] = y0;     o1[tid * 2 + 1] = y1;
        o2[tid * 2] = y0;     o2[tid * 2 + 1] = y1;
    }
}

// =============================================================================
// Fused mid-section: pm/lv stats -> z -> z stats -> zx.
// =============================================================================
__global__ void __launch_bounds__(1024)
mid_fused(const float* __restrict__ pm, const float* __restrict__ lv,
          const float* __restrict__ epsin,
          const float* __restrict__ gm, const float* __restrict__ bm,
          const float* __restrict__ gl, const float* __restrict__ bl,
          const float* __restrict__ gx, const float* __restrict__ bxx,
          float* __restrict__ out_z, float* __restrict__ s_zx,
          float* __restrict__ out_zx)
{
    __shared__ float4 red[1024];
    __shared__ float st[12];
    const int tid = threadIdx.x;

    auto reduce4 = [&](float s0, float q0, float s1, float q1, int base) {
        red[tid] = make_float4(s0, q0, s1, q1);
        __syncthreads();
        for (int s = 512; s > 0; s >>= 1) {
            if (tid < s) {
                float4 a = red[tid], b2 = red[tid + s];
                red[tid] = make_float4(a.x + b2.x, a.y + b2.y, a.z + b2.z, a.w + b2.w);
            }
            __syncthreads();
        }
        if (tid == 0) {
            float4 r = red[0];
            float m0 = r.x / NB, m1 = r.z / NB;
            st[base + 0] = m0;
            st[base + 1] = m1;
            st[base + 2] = r.y / NB - m0 * m0;
            st[base + 3] = r.w / NB - m1 * m1;
        }
        __syncthreads();
    };

    {
        float s0 = 0, q0 = 0, s1 = 0, q1 = 0;
#pragma unroll
        for (int i = 0; i < 2; i++) {
            int r = tid + i * 1024;
            float x0 = pm[r * 2], x1 = pm[r * 2 + 1];
            s0 += x0; q0 += x0 * x0; s1 += x1; q1 += x1 * x1;
        }
        reduce4(s0, q0, s1, q1, 0);
    }
    {
        float s0 = 0, q0 = 0, s1 = 0, q1 = 0;
#pragma unroll
        for (int i = 0; i < 2; i++) {
            int r = tid + i * 1024;
            float x0 = lv[r * 2], x1 = lv[r * 2 + 1];
            s0 += x0; q0 += x0 * x0; s1 += x1; q1 += x1 * x1;
        }
        reduce4(s0, q0, s1, q1, 4);
    }
    float zr[2][2];
    {
        const float pmi0 = rsqrtf(st[2] + 1e-5f), pmi1 = rsqrtf(st[3] + 1e-5f);
        const float lvi0 = rsqrtf(st[6] + 1e-5f), lvi1 = rsqrtf(st[7] + 1e-5f);
        const float gm0 = gm[0], gm1 = gm[1], bm0 = bm[0], bm1 = bm[1];
        const float gl0 = gl[0], gl1 = gl[1], bl0 = bl[0], bl1 = bl[1];
        float s0 = 0, q0 = 0, s1 = 0, q1 = 0;
#pragma unroll
        for (int i = 0; i < 2; i++) {
            int r = tid + i * 1024;
            float p0 = gm0 * (pm[r * 2] - st[0]) * pmi0 + bm0;
            float p1 = gm1 * (pm[r * 2 + 1] - st[1]) * pmi1 + bm1;
            float l0 = gl0 * (lv[r * 2] - st[4]) * lvi0 + bl0;
            float l1 = gl1 * (lv[r * 2 + 1] - st[5]) * lvi1 + bl1;
            float z0 = p0 + sqrtf(expf(l0)) * epsin[r * 2];
            float z1 = p1 + sqrtf(expf(l1)) * epsin[r * 2 + 1];
            out_z[r * 2] = z0;
            out_z[r * 2 + 1] = z1;
            zr[i][0] = z0; zr[i][1] = z1;
            s0 += z0; q0 += z0 * z0; s1 += z1; q1 += z1 * z1;
        }
        reduce4(s0, q0, s1, q1, 8);
    }
    {
        const float zi0 = rsqrtf(st[10] + 1e-5f), zi1 = rsqrtf(st[11] + 1e-5f);
        const float gx0 = gx[0], gx1 = gx[1], bx0 = bxx[0], bx1 = bxx[1];
#pragma unroll
        for (int i = 0; i < 2; i++) {
            int r = tid + i * 1024;
            float y0 = gx0 * (zr[i][0] - st[8]) * zi0 + bx0;
            float y1 = gx1 * (zr[i][1] - st[9]) * zi1 + bx1;
            s_zx[r * 2] = y0;    s_zx[r * 2 + 1] = y1;
            out_zx[r * 2] = y0;  out_zx[r * 2 + 1] = y1;
        }
    }
}

// ---------------- theta (fp32 outputs + fp16 plane) --------------------------
__global__ void theta_kernel(const float* __restrict__ zx, const float* __restrict__ zc,
                             float* __restrict__ gtheta, float* __restrict__ otheta)
{
    __shared__ float sz[KK * 2];
    __shared__ float red[256];
    __shared__ float sth[KR];
    int n = blockIdx.x, tid = threadIdx.x;
    for (int i = tid; i < KK * 2; i += 256) sz[i] = zc[i];
    __syncthreads();
    float x0 = zx[n * 2], x1 = zx[n * 2 + 1];
    float l = -FLT_MAX;
    if (tid < KK) {
        float dx = x0 - sz[tid * 2];
        float dy = x1 - sz[tid * 2 + 1];
        l = -0.5f * (dx * dx + dy * dy);
    }
    red[tid] = l;
    __syncthreads();
    for (int st = 128; st > 0; st >>= 1) {
        if (tid < st) red[tid] = fmaxf(red[tid], red[tid + st]);
        __syncthreads();
    }
    float mx = red[0];
    __syncthreads();
    float e = (tid < KK) ? expf(l - mx) : 0.f;
    red[tid] = e;
    __syncthreads();
    for (int st = 128; st > 0; st >>= 1) {
        if (tid < st) red[tid] += red[tid + st];
        __syncthreads();
    }
    float inv = 1.f / red[0];
    float th = e * inv;
    if (tid < KK) {
        gtheta[(size_t)n * KK + tid] = th;
        otheta[(size_t)n * KK + tid] = th;
    }
    if (tid < KR) sth[tid] = (tid < KK) ? th : 0.f;
    __syncthreads();
    if (tid < KRW) {
        g_bf[W_TH + (size_t)n * KRW + tid] =
            pk_h2(__float2half_rn(sth[2 * tid]), __float2half_rn(sth[2 * tid + 1]));
    }
}

// ---------------- decoder MLP ------------------------------------------------
__global__ void mu1_kernel(const float* __restrict__ zc, const float* __restrict__ W,
                           const float* __restrict__ b, float* __restrict__ out)
{
    int t = blockIdx.x * 256 + threadIdx.x;
    if (t >= KK * 100) return;
    int k = t / 100, j = t % 100;
    float v = zc[k * 2] * W[j * 2] + zc[k * 2 + 1] * W[j * 2 + 1] + b[j];
    out[t] = softplusf(v);
}

__global__ void mu2_kernel(const float* __restrict__ mu1, const float* __restrict__ W,
                           const float* __restrict__ b, float* __restrict__ out)
{
    __shared__ float row[100];
    int k = blockIdx.x, tid = threadIdx.x;
    if (tid < 100) row[tid] = mu1[k * 100 + tid];
    __syncthreads();
    if (tid < 100) {
        const float* w = W + tid * 100;
        float s = b[tid];
        for (int i = 0; i < 100; i++) s += row[i] * w[i];
        out[k * 100 + tid] = softplusf(s);
    }
}

__global__ void muz_kernel(const float* __restrict__ mu2, const float* __restrict__ W,
                           const float* __restrict__ b, float* __restrict__ out)
{
    __shared__ float row[100];
    int k = blockIdx.x, tid = threadIdx.x;
    if (tid < 100) row[tid] = mu2[k * 100 + tid];
    __syncthreads();
    for (int j = tid; j < EMB; j += 128) {
        const float* w = W + j * 100;
        float s = b[j];
        for (int i = 0; i < 100; i++) s += row[i] * w[i];
        out[k * EMB + j] = s;
    }
}

// =============================================================================
// beta: BN_topic + softmax numerator only (exp-once, __expf).
// =============================================================================
__global__ void __launch_bounds__(1024)
beta_kernel(const float* __restrict__ logits, const float* __restrict__ bbias,
            const float* __restrict__ gdec, const float* __restrict__ bdec,
            float* __restrict__ beta)
{
    __shared__ float rs[1024], rq[1024], rmx[1024], rmn[1024], rmb[1024];
    const int k = blockIdx.x, tid = threadIdx.x;
    const float* row = logits + (size_t)k * VV;
    const float* bb  = bbias + (size_t)k * VV;
    float* brow = beta + (size_t)k * VV;

    float s = 0.f, q = 0.f, mxx = -FLT_MAX, mnx = FLT_MAX, mxb = -FLT_MAX;
    for (int v = tid; v < VV; v += 1024) {
        float x = row[v];
        s += x; q += x * x;
        mxx = fmaxf(mxx, x);
        mnx = fminf(mnx, x);
        mxb = fmaxf(mxb, bb[v]);
    }
    rs[tid] = s; rq[tid] = q; rmx[tid] = mxx; rmn[tid] = mnx; rmb[tid] = mxb;
    __syncthreads();
    for (int st = 512; st > 0; st >>= 1) {
        if (tid < st) {
            rs[tid] += rs[tid + st];
            rq[tid] += rq[tid + st];
            rmx[tid] = fmaxf(rmx[tid], rmx[tid + st]);
            rmn[tid] = fminf(rmn[tid], rmn[tid + st]);
            rmb[tid] = fmaxf(rmb[tid], rmb[tid + st]);
        }
        __syncthreads();
    }
    const float mean = rs[0] / VV;
    const float var  = rq[0] / VV - mean * mean;
    const float scale = gdec[k] * rsqrtf(var + 1e-5f);
    const float shift = bdec[k] - mean * scale;
    const float mx = scale * (scale > 0.f ? rmx[0] : rmn[0]) + shift + rmb[0];
    __syncthreads();

    float se = 0.f;
    for (int v = tid; v < VV; v += 1024) {
        float e = __expf(row[v] * scale + shift + bb[v] - mx);
        brow[v] = e;
        se += e;
    }
    rs[tid] = se;
    __syncthreads();
    for (int st = 512; st > 0; st >>= 1) {
        if (tid < st) rs[tid] += rs[tid + st];
        __syncthreads();
    }
    if (tid == 0) g_binv[k] = 1.f / rs[0];
}

// ---------------- launch -----------------------------------------------------
extern "C" void kernel_launch(void* const* d_in, const int* in_sizes, int n_in,
                              void* d_out, int out_size)
{
    const float* input_   = (const float*)d_in[0];
    const float* eps      = (const float*)d_in[2];
    const float* en1_W    = (const float*)d_in[3];
    const float* en1_b    = (const float*)d_in[4];
    const float* en2_W    = (const float*)d_in[5];
    const float* en2_b    = (const float*)d_in[6];
    const float* mean_W   = (const float*)d_in[7];
    const float* mean_b   = (const float*)d_in[8];
    const float* logvar_W = (const float*)d_in[9];
    const float* logvar_b = (const float*)d_in[10];
    const float* mu1_W    = (const float*)d_in[11];
    const float* mu1_b    = (const float*)d_in[12];
    const float* mu2_W    = (const float*)d_in[13];
    const float* mu2_b    = (const float*)d_in[14];
    const float* mu_W     = (const float*)d_in[15];
    const float* mu_b     = (const float*)d_in[16];
    const float* topics   = (const float*)d_in[17];
    const float* bbias    = (const float*)d_in[18];
    const float* emb      = (const float*)d_in[19];
    const float* g_mean   = (const float*)d_in[20];
    const float* b_mean   = (const float*)d_in[21];
    const float* g_logvar = (const float*)d_in[22];
    const float* b_logvar = (const float*)d_in[23];
    const float* g_x      = (const float*)d_in[24];
    const float* b_x      = (const float*)d_in[25];
    const float* g_phi    = (const float*)d_in[26];
    const float* b_phi    = (const float*)d_in[27];
    const float* g_dec    = (const float*)d_in[28];
    const float* b_dec    = (const float*)d_in[29];

    float* out = (float*)d_out;
    float* out_z     = out;
    float* out_recon = out + (long long)NB * CC;
    float* out_zx    = out_recon + (long long)NB * VV;
    float* out_zc    = out_zx + (long long)NB * CC;
    float* out_theta = out_zc + (long long)KK * CC;

    void* sp = nullptr;
    cudaGetSymbolAddress(&sp, g_scratch);
    float* S = (float*)sp;
    float* s_en1    = S + OFF_EN1;
    float* s_en2    = S + OFF_EN2;
    float* s_pm     = S + OFF_PM;
    float* s_lv     = S + OFF_LV;
    float* s_zx     = S + OFF_ZX;
    float* s_zc     = S + OFF_ZC;
    float* s_theta  = S + OFF_THETA;
    float* s_mu1    = S + OFF_MU1;
    float* s_mu2    = S + OFF_MU2;
    float* s_muz    = S + OFF_MUZ;
    float* s_logits = S + OFF_LOGITS;
    float* s_beta   = S + OFF_BETA;

    // lazily created host objects (no device allocation)
    static cudaStream_t s_dec = nullptr;
    static cudaEvent_t ev_fork = nullptr, ev_zc = nullptr, ev_join = nullptr;
    if (s_dec == nullptr) {
        cudaStreamCreateWithFlags(&s_dec, cudaStreamNonBlocking);
        cudaEventCreateWithFlags(&ev_fork, cudaEventDisableTiming);
        cudaEventCreateWithFlags(&ev_zc, cudaEventDisableTiming);
        cudaEventCreateWithFlags(&ev_join, cudaEventDisableTiming);
        cudaFuncSetAttribute(gemm1_fp16_sk, cudaFuncAttributeMaxDynamicSharedMemorySize, G1_SMEM);
        cudaFuncSetAttribute(recon_f16, cudaFuncAttributeMaxDynamicSharedMemorySize, G1_SMEM);
        cudaFuncSetAttribute(gemm_nt_bf16x3<true, true, false>,
                             cudaFuncAttributeMaxDynamicSharedMemorySize, NTB_SMEM);
    }

    // ---- fork decoder chain onto s_dec ----
    cudaEventRecord(ev_fork, 0);
    cudaStreamWaitEvent(s_dec, ev_fork, 0);

    // decoder chain (lightweight; only logits_tf32 touches tensor pipes ~60us)
    zc_fused<<<1, 256, 0, s_dec>>>(topics, g_phi, b_phi, s_zc, out_zc);
    cudaEventRecord(ev_zc, s_dec);
    mu1_kernel<<<(KK * 100 + 255) / 256, 256, 0, s_dec>>>(s_zc, mu1_W, mu1_b, s_mu1);
    mu2_kernel<<<KK, 128, 0, s_dec>>>(s_mu1, mu2_W, mu2_b, s_mu2);
    muz_kernel<<<KK, 128, 0, s_dec>>>(s_mu2, mu_W, mu_b, s_muz);
    logits_tf32<<<dim3((VV + 63) / 64, (KK + 63) / 64), 256, 0, s_dec>>>(s_muz, emb, s_logits);
    beta_kernel<<<KK, 1024, 0, s_dec>>>(s_logits, bbias, g_dec, b_dec, s_beta);
    transpose_beta<<<dim3(BTROWS / 32, KR / 32), 256, 0, s_dec>>>(s_beta);
    cudaEventRecord(ev_join, s_dec);

    // encoder chain on stream 0
    split_fp16<<<NB + E1, 256>>>(input_, en1_W);
    gemm1_fp16_sk<<<dim3(E1 / 128, NB / 128, SK), 256, G1_SMEM>>>();
    reduce_en1<<<(NB * E1 / 4) / 256, 256>>>(en1_b, s_en1);
    gemm_nt_bf16x3<true, true, false><<<dim3(E2 / 128, NB / 128), 512, NTB_SMEM>>>(
        s_en1, en2_W, en2_b, s_en2, NB, E2, E1);
    meanlogvar_kernel<<<(NB * 4 + 255) / 256, 256>>>(
        s_en2, mean_W, mean_b, logvar_W, logvar_b, s_pm, s_lv);
    mid_fused<<<1, 1024>>>(s_pm, s_lv, eps, g_mean, b_mean, g_logvar, b_logvar,
                           g_x, b_x, out_z, s_zx, out_zx);

    // theta needs zc from decoder chain
    cudaStreamWaitEvent(0, ev_zc, 0);
    theta_kernel<<<NB, 256>>>(s_zx, s_zc, s_theta, out_theta);

    // join: recon needs theta (stream 0) + beta^T (s_dec)
    cudaStreamWaitEvent(0, ev_join, 0);
    recon_f16<<<dim3(BTROWS / 128, NB / 128), 256, G1_SMEM>>>(out_recon);

    (void)in_sizes; (void)n_in; (void)out_size;
}